// round 6
// baseline (speedup 1.0000x reference)
#include <cuda_runtime.h>
#include <cuda_bf16.h>
#include <cstdint>
#include <cstddef>

// Problem constants
#define BB 4
#define SS 4096
#define HH 768
#define RR 242
#define HK 256
#define CP 256
#define RWIN 16
#define NFREQ 384

// ---------------- device scratch ---------------------------------------------------------
__device__ float g_z [(size_t)BB * SS * CP];
__device__ float g_z2[(size_t)BB * SS * CP];
__device__ float g_T1t[RR * RR];
__device__ float g_WcT[HH * CP];            // cols 242..255 stay zero (zero-init)
__device__ float g_e[RWIN + 1];
// pair-interleaved bf16 hi/lo weights, stored as u32 (one k-pair per word)
__device__ __align__(16) uint32_t g_vlh[CP * HH / 2];
__device__ __align__(16) uint32_t g_vll[CP * HH / 2];
__device__ __align__(16) uint32_t g_wch[HH * CP / 2];
__device__ __align__(16) uint32_t g_wcl[HH * CP / 2];

// ---------------- band weight precompute -------------------------------------------------
__global__ void prep_kernel() {
    int w    = threadIdx.x >> 5;
    int lane = threadIdx.x & 31;
    if (w > RWIN) return;
    float d = (float)w;
    float s = 0.f;
    for (int j = lane; j < NFREQ; j += 32) {
        float f = expf(-(float)j * (9.210340371976184f / (float)NFREQ));
        s += cosf(d * f);
    }
    #pragma unroll
    for (int o = 16; o > 0; o >>= 1) s += __shfl_down_sync(0xffffffffu, s, o);
    if (lane == 0) g_e[w] = expf(s - (float)NFREQ);
}

// ---------------- bf16 helpers -----------------------------------------------------------
__device__ __forceinline__ uint32_t pack_bf16x2(float e0, float e1) {
    uint32_t r;
    asm("cvt.rn.bf16x2.f32 %0, %1, %2;" : "=r"(r) : "f"(e1), "f"(e0));
    return r;
}
__device__ __forceinline__ void cvt_pair(float e0, float e1, uint32_t& hi, uint32_t& lo) {
    hi = pack_bf16x2(e0, e1);
    float h0 = __uint_as_float(hi << 16);
    float h1 = __uint_as_float(hi & 0xffff0000u);
    lo = pack_bf16x2(e0 - h0, e1 - h1);
}
__device__ __forceinline__ void mma_bf16(float* d, const uint32_t* a, uint32_t b0, uint32_t b1) {
    asm volatile(
        "mma.sync.aligned.m16n8k16.row.col.f32.bf16.bf16.f32 "
        "{%0,%1,%2,%3}, {%4,%5,%6,%7}, {%8,%9}, {%0,%1,%2,%3};"
        : "+f"(d[0]), "+f"(d[1]), "+f"(d[2]), "+f"(d[3])
        : "r"(a[0]), "r"(a[1]), "r"(a[2]), "r"(a[3]), "r"(b0), "r"(b1));
}
__device__ __forceinline__ uint32_t smem_u32(const void* p) {
    uint32_t a;
    asm("{ .reg .u64 t; cvta.to.shared.u64 t, %1; cvt.u32.u64 %0, t; }" : "=r"(a) : "l"(p));
    return a;
}
__device__ __forceinline__ void cp16(uint32_t dst, const void* src) {
    asm volatile("cp.async.cg.shared.global [%0], [%1], 16;" :: "r"(dst), "l"(src));
}
__device__ __forceinline__ void cp_commit() {
    asm volatile("cp.async.commit_group;" ::: "memory");
}
template<int N> __device__ __forceinline__ void cp_wait() {
    asm volatile("cp.async.wait_group %0;" :: "n"(N) : "memory");
}

// ---------------- weight pre-conversion: fp32 -> bf16 hi/lo, k-pair interleaved ----------
// slot j within an 8-slot (16-k) group holds pair p = (j>>1) + (j&1)*4, i.e. k = 2p, 2p+1.
// So a uint2 at slots {2c, 2c+1} yields pairs (c, c+4) = the mma b-frag / a-frag k pattern.
__global__ void conv_pairs(const float* __restrict__ src, int rows_src, int cols,
                           uint32_t* __restrict__ hi, uint32_t* __restrict__ lo,
                           int rows_dst) {
    int idx = blockIdx.x * 256 + threadIdx.x;
    int cols2 = cols >> 1;
    if (idx >= rows_dst * cols2) return;
    int row = idx / cols2;
    int s   = idx - row * cols2;
    int grp = s >> 3, j = s & 7;
    int k = (grp << 4) + (((j >> 1) + ((j & 1) << 2)) << 1);
    float e0 = 0.f, e1 = 0.f;
    if (row < rows_src) {
        e0 = src[(size_t)row * cols + k];
        e1 = src[(size_t)row * cols + k + 1];
    }
    uint32_t h, l;
    cvt_pair(e0, e1, h, l);
    hi[idx] = h;
    lo[idx] = l;
}

// ---------------- fast small NN gemm: 64x64 tiles, 4x4 per thread ------------------------
__global__ void __launch_bounds__(256)
gemm_nn_64(const float* __restrict__ A, int lda,
           const float* __restrict__ B, int ldb,
           float* __restrict__ C, int ldc,
           int M, int N, int K) {
    __shared__ float As[16][64];
    __shared__ float Bs[16][68];
    const int tid = threadIdx.x;
    const int m0 = blockIdx.y * 64, n0 = blockIdx.x * 64;
    const int tx = tid & 15, ty = tid >> 4;
    float acc[4][4] = {};
    for (int k0 = 0; k0 < K; k0 += 16) {
        #pragma unroll
        for (int i = 0; i < 4; i++) {
            int idx = tid + i * 256;
            int r = idx >> 4, kk = idx & 15;
            float v = 0.f;
            if (m0 + r < M && k0 + kk < K) v = A[(size_t)(m0 + r) * lda + k0 + kk];
            As[kk][r] = v;
        }
        #pragma unroll
        for (int i = 0; i < 4; i++) {
            int idx = tid + i * 256;
            int r = idx >> 6, c = idx & 63;
            float v = 0.f;
            if (k0 + r < K && n0 + c < N) v = B[(size_t)(k0 + r) * ldb + n0 + c];
            Bs[r][c] = v;
        }
        __syncthreads();
        #pragma unroll
        for (int k = 0; k < 16; k++) {
            float a[4], b[4];
            #pragma unroll
            for (int i = 0; i < 4; i++) { a[i] = As[k][ty * 4 + i]; b[i] = Bs[k][tx * 4 + i]; }
            #pragma unroll
            for (int i = 0; i < 4; i++)
                #pragma unroll
                for (int j = 0; j < 4; j++) acc[i][j] += a[i] * b[j];
        }
        __syncthreads();
    }
    #pragma unroll
    for (int i = 0; i < 4; i++) {
        int m = m0 + ty * 4 + i;
        if (m >= M) break;
        #pragma unroll
        for (int j = 0; j < 4; j++) {
            int n = n0 + tx * 4 + j;
            if (n < N) C[(size_t)m * ldc + n] = acc[i][j];
        }
    }
}

// ---------------- pipelined tensor-core GEMM: C = A_f32 @ B_bf16split^T ------------------
// BM=BN=128, BK=32; 256 threads = 8 warps (4M x 2N), warp tile 32x64.
// A converted hi/lo in registers; B pre-split + pair-interleaved in gmem (u32 words).
#define A_PITCH 40                      // floats per A smem row (conflict-free float2 frags)
#define B_PITCH 24                      // u32 per B smem row (conflict-free uint2 frags)
#define A_U32 (128 * A_PITCH)           // 5120 u32
#define B_U32 (128 * B_PITCH)           // 3072 u32
#define STAGE_U32 (A_U32 + 2 * B_U32)   // 11264 u32 = 45056 B
#define SM_BYTES (2 * STAGE_U32 * 4)    // 90112 B

__global__ void __launch_bounds__(256, 2)
mma_gemm_abt(const float* __restrict__ A, int lda,
             const uint32_t* __restrict__ Bh,
             const uint32_t* __restrict__ Bl, int ldbu,   // u32 words per B row
             float* __restrict__ C, int ldc, int K) {
    extern __shared__ uint32_t sm4[];
    const uint32_t sb = smem_u32(sm4);
    const int tid  = threadIdx.x;
    const int wid  = tid >> 5;
    const int lane = tid & 31;
    const int m0 = blockIdx.y * 128;
    const int n0 = blockIdx.x * 128;
    const int mbw = (wid & 3) * 32;
    const int nbw = (wid >> 2) * 64;
    const int lr = lane >> 2;
    const int lc = lane & 3;

    const int ar = tid >> 3, ac = tid & 7;   // A fill: rows ar+32i, 16B chunk ac
    const int br = tid >> 2, bc = tid & 3;   // B fill: rows br+64i, 16B chunk bc

    const float*    aSrc  = A  + (size_t)(m0 + ar) * lda + ac * 4;
    const uint32_t* bhSrc = Bh + (size_t)(n0 + br) * ldbu + bc * 4;
    const uint32_t* blSrc = Bl + (size_t)(n0 + br) * ldbu + bc * 4;
    const uint32_t aDst  = sb + (ar * A_PITCH + ac * 4) * 4;
    const uint32_t bhDst = sb + (A_U32 + br * B_PITCH + bc * 4) * 4;
    const uint32_t blDst = sb + (A_U32 + B_U32 + br * B_PITCH + bc * 4) * 4;

    float acc[2][8][4] = {};
    const int nchunks = K >> 5;

    #define ISSUE(ch) do {                                                          \
        const uint32_t so_ = ((ch) & 1) * (STAGE_U32 * 4);                          \
        const int kf_ = (ch) << 5;   /* floats */                                   \
        const int ku_ = (ch) << 4;   /* u32 words */                                \
        _Pragma("unroll")                                                           \
        for (int i_ = 0; i_ < 4; i_++)                                              \
            cp16(aDst + so_ + i_ * 32 * A_PITCH * 4,                                \
                 aSrc + kf_ + (size_t)i_ * 32 * lda);                               \
        _Pragma("unroll")                                                           \
        for (int i_ = 0; i_ < 2; i_++) {                                            \
            cp16(bhDst + so_ + i_ * 64 * B_PITCH * 4,                               \
                 bhSrc + ku_ + (size_t)i_ * 64 * ldbu);                             \
            cp16(blDst + so_ + i_ * 64 * B_PITCH * 4,                               \
                 blSrc + ku_ + (size_t)i_ * 64 * ldbu);                             \
        }                                                                           \
        cp_commit();                                                                \
    } while (0)

    ISSUE(0);
    for (int ch = 0; ch < nchunks; ch++) {
        if (ch + 1 < nchunks) { ISSUE(ch + 1); cp_wait<1>(); }
        else                  { cp_wait<0>(); }
        __syncthreads();

        const uint32_t stg = (ch & 1) * STAGE_U32;
        const float* As = (const float*)(sm4 + stg);
        const uint32_t* BHs = sm4 + stg + A_U32;
        const uint32_t* BLs = sm4 + stg + A_U32 + B_U32;

        #pragma unroll
        for (int ks = 0; ks < 2; ks++) {
            uint32_t ah[2][4], al[2][4];
            #pragma unroll
            for (int t = 0; t < 2; t++) {
                const float* ap = As + (mbw + t * 16 + lr) * A_PITCH + ks * 16 + 2 * lc;
                float2 f0 = *(const float2*)(ap);
                float2 f1 = *(const float2*)(ap + 8 * A_PITCH);
                float2 f2 = *(const float2*)(ap + 8);
                float2 f3 = *(const float2*)(ap + 8 * A_PITCH + 8);
                cvt_pair(f0.x, f0.y, ah[t][0], al[t][0]);
                cvt_pair(f1.x, f1.y, ah[t][1], al[t][1]);
                cvt_pair(f2.x, f2.y, ah[t][2], al[t][2]);
                cvt_pair(f3.x, f3.y, ah[t][3], al[t][3]);
            }
            #pragma unroll
            for (int u = 0; u < 8; u++) {
                int rb = (nbw + u * 8 + lr) * B_PITCH + ks * 8 + 2 * lc;
                uint2 bh = *(const uint2*)(BHs + rb);
                uint2 bl = *(const uint2*)(BLs + rb);
                #pragma unroll
                for (int t = 0; t < 2; t++) {
                    mma_bf16(acc[t][u], ah[t], bh.x, bh.y);   // hi*hi
                    mma_bf16(acc[t][u], ah[t], bl.x, bl.y);   // hi*lo
                    mma_bf16(acc[t][u], al[t], bh.x, bh.y);   // lo*hi
                }
            }
        }
        __syncthreads();
    }

    // ---- epilogue ----
    #pragma unroll
    for (int t = 0; t < 2; t++) {
        int row = m0 + mbw + t * 16 + lr;
        #pragma unroll
        for (int u = 0; u < 8; u++) {
            int col = n0 + nbw + u * 8 + lc * 2;
            *(float2*)(C + (size_t)row * ldc + col) = make_float2(acc[t][u][0], acc[t][u][1]);
            *(float2*)(C + (size_t)(row + 8) * ldc + col) = make_float2(acc[t][u][2], acc[t][u][3]);
        }
    }
}

// ---------------- banded softmax mix, smem-tiled ------------------------------------------
__global__ void __launch_bounds__(256)
mix_kernel(const float* __restrict__ z, float* __restrict__ z2) {
    __shared__ float zs[96][64];
    __shared__ float ws[2 * RWIN + 1];
    const int s0 = blockIdx.x * 64;
    const int c0 = blockIdx.y * 64;
    const int b  = blockIdx.z;
    const int tid = threadIdx.x;

    if (tid < 2 * RWIN + 1) ws[tid] = g_e[tid < RWIN ? RWIN - tid : tid - RWIN];

    #pragma unroll
    for (int i = 0; i < 24; i++) {
        int idx = tid + i * 256;
        int r = idx >> 6, c = idx & 63;
        int gs = s0 - 16 + r;
        float v = 0.f;
        if ((unsigned)gs < (unsigned)SS)
            v = z[((size_t)b * SS + gs) * CP + c0 + c];
        zs[r][c] = v;
    }
    __syncthreads();

    const int c = tid & 63;
    #pragma unroll 4
    for (int is = 0; is < 16; is++) {
        int sl = (tid >> 6) + is * 4;
        int s = s0 + sl;
        float Z = 0.f, acc2 = 0.f;
        #pragma unroll
        for (int d = -RWIN; d <= RWIN; ++d) {
            int t = s - d;
            if ((unsigned)t < (unsigned)SS) {
                float w = ws[d + RWIN];
                Z += w;
                acc2 += w * zs[sl + 16 - d][c];
            }
        }
        z2[((size_t)b * SS + s) * CP + c0 + c] = acc2 * (1.f / Z);
    }
}

// ---------------- launch ------------------------------------------------------------------
extern "C" void kernel_launch(void* const* d_in, const int* in_sizes, int n_in,
                              void* d_out, int out_size) {
    const float* x      = (const float*)d_in[0];
    const float* v_low  = (const float*)d_in[5];   // [242, 768]
    const float* v_high = (const float*)d_in[6];   // [256, 242]
    const float* o_low  = (const float*)d_in[7];   // [242, 256]
    const float* o_high = (const float*)d_in[8];   // [768, 242]
    float* out = (float*)d_out;                    // [4, 4096, 768]

    float* z   = nullptr; cudaGetSymbolAddress((void**)&z,   g_z);
    float* z2  = nullptr; cudaGetSymbolAddress((void**)&z2,  g_z2);
    float* T1t = nullptr; cudaGetSymbolAddress((void**)&T1t, g_T1t);
    float* WcT = nullptr; cudaGetSymbolAddress((void**)&WcT, g_WcT);
    uint32_t* vlh = nullptr; cudaGetSymbolAddress((void**)&vlh, g_vlh);
    uint32_t* vll = nullptr; cudaGetSymbolAddress((void**)&vll, g_vll);
    uint32_t* wch = nullptr; cudaGetSymbolAddress((void**)&wch, g_wch);
    uint32_t* wcl = nullptr; cudaGetSymbolAddress((void**)&wcl, g_wcl);

    cudaFuncSetAttribute(mma_gemm_abt, cudaFuncAttributeMaxDynamicSharedMemorySize, SM_BYTES);

    // 1. band weights
    prep_kernel<<<1, (RWIN + 1) * 32>>>();

    // 2. v_low -> bf16 hi/lo pair-interleaved, zero-padded to 256 rows
    conv_pairs<<<(CP * HH / 2 + 255) / 256, 256>>>(v_low, RR, HH, vlh, vll, CP);

    // 3. T1t[242,242] = o_low[242,256] @ v_high[256,242]
    gemm_nn_64<<<dim3(4, 4), 256>>>(o_low, HK, v_high, RR, T1t, RR, RR, RR, HK);

    // 4. WcT[768,242] = o_high[768,242] @ T1t[242,242]   (ldc=256)
    gemm_nn_64<<<dim3(4, 12), 256>>>(o_high, RR, T1t, RR, WcT, CP, HH, RR, RR);

    // 5. WcT -> bf16 hi/lo pair-interleaved
    conv_pairs<<<(HH * CP / 2 + 255) / 256, 256>>>(WcT, HH, CP, wch, wcl, HH);

    // 6. z = x @ v_low^T   [16384, 256]
    mma_gemm_abt<<<dim3(CP / 128, (BB * SS) / 128), 256, SM_BYTES>>>(
        x, HH, vlh, vll, HH / 2, z, CP, HH);

    // 7. banded softmax mix
    mix_kernel<<<dim3(SS / 64, CP / 64, BB), 256>>>(z, z2);

    // 8. out = z2 @ WcT^T  [16384, 768]
    mma_gemm_abt<<<dim3(HH / 128, (BB * SS) / 128), 256, SM_BYTES>>>(
        z2, CP, wch, wcl, CP / 2, out, HH, CP);

    (void)in_sizes; (void)n_in; (void)out_size;
}

// round 7
// speedup vs baseline: 1.1119x; 1.1119x over previous
#include <cuda_runtime.h>
#include <cuda_bf16.h>
#include <cstdint>
#include <cstddef>

// Problem constants
#define BB 4
#define SS 4096
#define HH 768
#define RR 242
#define HK 256
#define CP 256
#define RWIN 16
#define NFREQ 384

// ---------------- device scratch ---------------------------------------------------------
__device__ float g_z [(size_t)BB * SS * CP];
__device__ float g_T1t[RR * RR];
__device__ float g_WcT[HH * CP];            // cols 242..255 never written (stay zero)
__device__ float g_e[RWIN + 1];
// pair-interleaved bf16 hi/lo tensors, stored as u32 (one k-pair per word)
__device__ __align__(16) uint32_t g_vlh[CP * HH / 2];
__device__ __align__(16) uint32_t g_vll[CP * HH / 2];
__device__ __align__(16) uint32_t g_wch[HH * CP / 2];
__device__ __align__(16) uint32_t g_wcl[HH * CP / 2];
__device__ __align__(16) uint32_t g_z2h[(size_t)BB * SS * CP / 2];
__device__ __align__(16) uint32_t g_z2l[(size_t)BB * SS * CP / 2];

// ---------------- band weight precompute -------------------------------------------------
__global__ void prep_kernel() {
    int w    = threadIdx.x >> 5;
    int lane = threadIdx.x & 31;
    if (w > RWIN) return;
    float d = (float)w;
    float s = 0.f;
    for (int j = lane; j < NFREQ; j += 32) {
        float f = expf(-(float)j * (9.210340371976184f / (float)NFREQ));
        s += cosf(d * f);
    }
    #pragma unroll
    for (int o = 16; o > 0; o >>= 1) s += __shfl_down_sync(0xffffffffu, s, o);
    if (lane == 0) g_e[w] = expf(s - (float)NFREQ);
}

// ---------------- bf16 helpers -----------------------------------------------------------
__device__ __forceinline__ uint32_t pack_bf16x2(float e0, float e1) {
    uint32_t r;
    asm("cvt.rn.bf16x2.f32 %0, %1, %2;" : "=r"(r) : "f"(e1), "f"(e0));
    return r;
}
__device__ __forceinline__ void cvt_pair(float e0, float e1, uint32_t& hi, uint32_t& lo) {
    hi = pack_bf16x2(e0, e1);
    float h0 = __uint_as_float(hi << 16);
    float h1 = __uint_as_float(hi & 0xffff0000u);
    lo = pack_bf16x2(e0 - h0, e1 - h1);
}
__device__ __forceinline__ void mma_bf16(float* d, const uint32_t* a, uint32_t b0, uint32_t b1) {
    asm volatile(
        "mma.sync.aligned.m16n8k16.row.col.f32.bf16.bf16.f32 "
        "{%0,%1,%2,%3}, {%4,%5,%6,%7}, {%8,%9}, {%0,%1,%2,%3};"
        : "+f"(d[0]), "+f"(d[1]), "+f"(d[2]), "+f"(d[3])
        : "r"(a[0]), "r"(a[1]), "r"(a[2]), "r"(a[3]), "r"(b0), "r"(b1));
}
__device__ __forceinline__ uint32_t smem_u32(const void* p) {
    uint32_t a;
    asm("{ .reg .u64 t; cvta.to.shared.u64 t, %1; cvt.u32.u64 %0, t; }" : "=r"(a) : "l"(p));
    return a;
}
__device__ __forceinline__ void cp16(uint32_t dst, const void* src) {
    asm volatile("cp.async.cg.shared.global [%0], [%1], 16;" :: "r"(dst), "l"(src));
}
__device__ __forceinline__ void cp_commit() {
    asm volatile("cp.async.commit_group;" ::: "memory");
}
template<int N> __device__ __forceinline__ void cp_wait() {
    asm volatile("cp.async.wait_group %0;" :: "n"(N) : "memory");
}

// ---------------- weight pre-conversion: fp32 -> bf16 hi/lo, k-pair interleaved ----------
// slot j within an 8-slot (16-k) group holds pair p = (j>>1) + (j&1)*4.
__global__ void conv_pairs(const float* __restrict__ src, int rows_src, int cols,
                           uint32_t* __restrict__ hi, uint32_t* __restrict__ lo,
                           int rows_dst) {
    int idx = blockIdx.x * 256 + threadIdx.x;
    int cols2 = cols >> 1;
    if (idx >= rows_dst * cols2) return;
    int row = idx / cols2;
    int s   = idx - row * cols2;
    int grp = s >> 3, j = s & 7;
    int k = (grp << 4) + (((j >> 1) + ((j & 1) << 2)) << 1);
    float e0 = 0.f, e1 = 0.f;
    if (row < rows_src) {
        e0 = src[(size_t)row * cols + k];
        e1 = src[(size_t)row * cols + k + 1];
    }
    uint32_t h, l;
    cvt_pair(e0, e1, h, l);
    hi[idx] = h;
    lo[idx] = l;
}

// ---------------- split-K small NN gemm: C += A@B over a 64-k slice ----------------------
// 32x32 tile, K-slice 64 per block (blockIdx.z). C must be zeroed beforehand.
__global__ void __launch_bounds__(256)
sgemm_splitk(const float* __restrict__ A, int lda,
             const float* __restrict__ B, int ldb,
             float* __restrict__ C, int ldc,
             int M, int N, int K) {
    __shared__ float As[64][33];
    __shared__ float Bs[64][33];
    const int tid = threadIdx.x;
    const int m0 = blockIdx.y * 32, n0 = blockIdx.x * 32, k0 = blockIdx.z * 64;
    // load A slice 32x64
    #pragma unroll
    for (int i = 0; i < 8; i++) {
        int idx = tid + i * 256;
        int r = idx & 31, k = idx >> 5;
        float v = 0.f;
        if (m0 + r < M && k0 + k < K) v = A[(size_t)(m0 + r) * lda + k0 + k];
        As[k][r] = v;
    }
    // load B slice 64x32
    #pragma unroll
    for (int i = 0; i < 8; i++) {
        int idx = tid + i * 256;
        int r = idx >> 5, c = idx & 31;
        float v = 0.f;
        if (k0 + r < K && n0 + c < N) v = B[(size_t)(k0 + r) * ldb + n0 + c];
        Bs[r][c] = v;
    }
    __syncthreads();
    const int tx = tid & 15, ty = tid >> 4;
    float acc[2][2] = {};
    #pragma unroll 16
    for (int k = 0; k < 64; k++) {
        float a0 = As[k][ty * 2], a1 = As[k][ty * 2 + 1];
        float b0 = Bs[k][tx * 2], b1 = Bs[k][tx * 2 + 1];
        acc[0][0] += a0 * b0; acc[0][1] += a0 * b1;
        acc[1][0] += a1 * b0; acc[1][1] += a1 * b1;
    }
    #pragma unroll
    for (int i = 0; i < 2; i++) {
        int m = m0 + ty * 2 + i;
        if (m >= M) continue;
        #pragma unroll
        for (int j = 0; j < 2; j++) {
            int n = n0 + tx * 2 + j;
            if (n < N) atomicAdd(&C[(size_t)m * ldc + n], acc[i][j]);
        }
    }
}

// ---------------- gemm1: C = A_f32 @ B_bf16split^T (pipelined, in-reg A conversion) ------
#define A_PITCH 40
#define B_PITCH 24
#define A_U32 (128 * A_PITCH)
#define B_U32 (128 * B_PITCH)
#define STAGE_U32 (A_U32 + 2 * B_U32)
#define SM_BYTES (2 * STAGE_U32 * 4)

__global__ void __launch_bounds__(256, 2)
mma_gemm_abt(const float* __restrict__ A, int lda,
             const uint32_t* __restrict__ Bh,
             const uint32_t* __restrict__ Bl, int ldbu,
             float* __restrict__ C, int ldc, int K) {
    extern __shared__ uint32_t sm4[];
    const uint32_t sb = smem_u32(sm4);
    const int tid  = threadIdx.x;
    const int wid  = tid >> 5;
    const int lane = tid & 31;
    const int m0 = blockIdx.y * 128;
    const int n0 = blockIdx.x * 128;
    const int mbw = (wid & 3) * 32;
    const int nbw = (wid >> 2) * 64;
    const int lr = lane >> 2;
    const int lc = lane & 3;

    const int ar = tid >> 3, ac = tid & 7;
    const int br = tid >> 2, bc = tid & 3;

    const float*    aSrc  = A  + (size_t)(m0 + ar) * lda + ac * 4;
    const uint32_t* bhSrc = Bh + (size_t)(n0 + br) * ldbu + bc * 4;
    const uint32_t* blSrc = Bl + (size_t)(n0 + br) * ldbu + bc * 4;
    const uint32_t aDst  = sb + (ar * A_PITCH + ac * 4) * 4;
    const uint32_t bhDst = sb + (A_U32 + br * B_PITCH + bc * 4) * 4;
    const uint32_t blDst = sb + (A_U32 + B_U32 + br * B_PITCH + bc * 4) * 4;

    float acc[2][8][4] = {};
    const int nchunks = K >> 5;

    #define ISSUE(ch) do {                                                          \
        const uint32_t so_ = ((ch) & 1) * (STAGE_U32 * 4);                          \
        const int kf_ = (ch) << 5;                                                  \
        const int ku_ = (ch) << 4;                                                  \
        _Pragma("unroll")                                                           \
        for (int i_ = 0; i_ < 4; i_++)                                              \
            cp16(aDst + so_ + i_ * 32 * A_PITCH * 4,                                \
                 aSrc + kf_ + (size_t)i_ * 32 * lda);                               \
        _Pragma("unroll")                                                           \
        for (int i_ = 0; i_ < 2; i_++) {                                            \
            cp16(bhDst + so_ + i_ * 64 * B_PITCH * 4,                               \
                 bhSrc + ku_ + (size_t)i_ * 64 * ldbu);                             \
            cp16(blDst + so_ + i_ * 64 * B_PITCH * 4,                               \
                 blSrc + ku_ + (size_t)i_ * 64 * ldbu);                             \
        }                                                                           \
        cp_commit();                                                                \
    } while (0)

    ISSUE(0);
    for (int ch = 0; ch < nchunks; ch++) {
        if (ch + 1 < nchunks) { ISSUE(ch + 1); cp_wait<1>(); }
        else                  { cp_wait<0>(); }
        __syncthreads();

        const uint32_t stg = (ch & 1) * STAGE_U32;
        const float* As = (const float*)(sm4 + stg);
        const uint32_t* BHs = sm4 + stg + A_U32;
        const uint32_t* BLs = sm4 + stg + A_U32 + B_U32;

        #pragma unroll
        for (int ks = 0; ks < 2; ks++) {
            uint32_t ah[2][4], al[2][4];
            #pragma unroll
            for (int t = 0; t < 2; t++) {
                const float* ap = As + (mbw + t * 16 + lr) * A_PITCH + ks * 16 + 2 * lc;
                float2 f0 = *(const float2*)(ap);
                float2 f1 = *(const float2*)(ap + 8 * A_PITCH);
                float2 f2 = *(const float2*)(ap + 8);
                float2 f3 = *(const float2*)(ap + 8 * A_PITCH + 8);
                cvt_pair(f0.x, f0.y, ah[t][0], al[t][0]);
                cvt_pair(f1.x, f1.y, ah[t][1], al[t][1]);
                cvt_pair(f2.x, f2.y, ah[t][2], al[t][2]);
                cvt_pair(f3.x, f3.y, ah[t][3], al[t][3]);
            }
            #pragma unroll
            for (int u = 0; u < 8; u++) {
                int rb = (nbw + u * 8 + lr) * B_PITCH + ks * 8 + 2 * lc;
                uint2 bh = *(const uint2*)(BHs + rb);
                uint2 bl = *(const uint2*)(BLs + rb);
                #pragma unroll
                for (int t = 0; t < 2; t++) {
                    mma_bf16(acc[t][u], ah[t], bh.x, bh.y);
                    mma_bf16(acc[t][u], ah[t], bl.x, bl.y);
                    mma_bf16(acc[t][u], al[t], bh.x, bh.y);
                }
            }
        }
        __syncthreads();
    }

    #pragma unroll
    for (int t = 0; t < 2; t++) {
        int row = m0 + mbw + t * 16 + lr;
        #pragma unroll
        for (int u = 0; u < 8; u++) {
            int col = n0 + nbw + u * 8 + lc * 2;
            *(float2*)(C + (size_t)row * ldc + col) = make_float2(acc[t][u][0], acc[t][u][1]);
            *(float2*)(C + (size_t)(row + 8) * ldc + col) = make_float2(acc[t][u][2], acc[t][u][3]);
        }
    }
}

// ---------------- gemm2: C = A_bf16split @ B_bf16split^T (all pre-split, no cvt) ---------
#define P2 24
#define T2_U32 (128 * P2)                 // 3072 u32 per tile array
#define STAGE2_U32 (4 * T2_U32)           // AH, AL, BH, BL
#define SM2_BYTES (2 * STAGE2_U32 * 4)    // 98304 B

__global__ void __launch_bounds__(256, 2)
mma_gemm_bb(const uint32_t* __restrict__ Ah, const uint32_t* __restrict__ Al, int ldau,
            const uint32_t* __restrict__ Bh, const uint32_t* __restrict__ Bl, int ldbu,
            float* __restrict__ C, int ldc, int K) {
    extern __shared__ uint32_t sm4[];
    const uint32_t sb = smem_u32(sm4);
    const int tid  = threadIdx.x;
    const int wid  = tid >> 5;
    const int lane = tid & 31;
    const int m0 = blockIdx.y * 128;
    const int n0 = blockIdx.x * 128;
    const int mbw = (wid & 3) * 32;
    const int nbw = (wid >> 2) * 64;
    const int lr = lane >> 2;
    const int lc = lane & 3;

    const int fr = tid >> 2, fc = tid & 3;   // fill: rows fr+128i (i<2 via idx), chunk fc

    const uint32_t* s0p[4] = { Ah + (size_t)(m0 + fr) * ldau + fc * 4,
                               Al + (size_t)(m0 + fr) * ldau + fc * 4,
                               Bh + (size_t)(n0 + fr) * ldbu + fc * 4,
                               Bl + (size_t)(n0 + fr) * ldbu + fc * 4 };
    const int lds[4] = { ldau, ldau, ldbu, ldbu };
    const uint32_t dst0 = sb + (fr * P2 + fc * 4) * 4;

    float acc[2][8][4] = {};
    const int nchunks = K >> 5;

    #define ISSUE2(ch) do {                                                         \
        const uint32_t so_ = ((ch) & 1) * (STAGE2_U32 * 4);                         \
        const int ku_ = (ch) << 4;                                                  \
        _Pragma("unroll")                                                           \
        for (int a_ = 0; a_ < 4; a_++) {                                            \
            _Pragma("unroll")                                                       \
            for (int i_ = 0; i_ < 2; i_++)                                          \
                cp16(dst0 + so_ + (a_ * T2_U32 + i_ * 64 * P2) * 4,                 \
                     s0p[a_] + ku_ + (size_t)i_ * 64 * lds[a_]);                    \
        }                                                                           \
        cp_commit();                                                                \
    } while (0)

    ISSUE2(0);
    for (int ch = 0; ch < nchunks; ch++) {
        if (ch + 1 < nchunks) { ISSUE2(ch + 1); cp_wait<1>(); }
        else                  { cp_wait<0>(); }
        __syncthreads();

        const uint32_t stg = (ch & 1) * STAGE2_U32;
        const uint32_t* AHs = sm4 + stg;
        const uint32_t* ALs = sm4 + stg + T2_U32;
        const uint32_t* BHs = sm4 + stg + 2 * T2_U32;
        const uint32_t* BLs = sm4 + stg + 3 * T2_U32;

        #pragma unroll
        for (int ks = 0; ks < 2; ks++) {
            uint32_t ah[2][4], al[2][4];
            #pragma unroll
            for (int t = 0; t < 2; t++) {
                int ba = (mbw + t * 16 + lr) * P2 + ks * 8 + 2 * lc;
                uint2 h0 = *(const uint2*)(AHs + ba);
                uint2 h8 = *(const uint2*)(AHs + ba + 8 * P2);
                uint2 l0 = *(const uint2*)(ALs + ba);
                uint2 l8 = *(const uint2*)(ALs + ba + 8 * P2);
                ah[t][0] = h0.x; ah[t][1] = h8.x; ah[t][2] = h0.y; ah[t][3] = h8.y;
                al[t][0] = l0.x; al[t][1] = l8.x; al[t][2] = l0.y; al[t][3] = l8.y;
            }
            #pragma unroll
            for (int u = 0; u < 8; u++) {
                int rb = (nbw + u * 8 + lr) * P2 + ks * 8 + 2 * lc;
                uint2 bh = *(const uint2*)(BHs + rb);
                uint2 bl = *(const uint2*)(BLs + rb);
                #pragma unroll
                for (int t = 0; t < 2; t++) {
                    mma_bf16(acc[t][u], ah[t], bh.x, bh.y);
                    mma_bf16(acc[t][u], ah[t], bl.x, bl.y);
                    mma_bf16(acc[t][u], al[t], bh.x, bh.y);
                }
            }
        }
        __syncthreads();
    }

    #pragma unroll
    for (int t = 0; t < 2; t++) {
        int row = m0 + mbw + t * 16 + lr;
        #pragma unroll
        for (int u = 0; u < 8; u++) {
            int col = n0 + nbw + u * 8 + lc * 2;
            *(float2*)(C + (size_t)row * ldc + col) = make_float2(acc[t][u][0], acc[t][u][1]);
            *(float2*)(C + (size_t)(row + 8) * ldc + col) = make_float2(acc[t][u][2], acc[t][u][3]);
        }
    }
}

// ---------------- banded softmax mix -> pair-interleaved bf16 hi/lo ----------------------
__global__ void __launch_bounds__(256)
mix_kernel(const float* __restrict__ z,
           uint32_t* __restrict__ z2h, uint32_t* __restrict__ z2l) {
    __shared__ float zs[96][64];
    __shared__ float ws[2 * RWIN + 1];
    const int s0 = blockIdx.x * 64;
    const int c0 = blockIdx.y * 64;
    const int b  = blockIdx.z;
    const int tid = threadIdx.x;

    if (tid < 2 * RWIN + 1) ws[tid] = g_e[tid < RWIN ? RWIN - tid : tid - RWIN];

    #pragma unroll
    for (int i = 0; i < 24; i++) {
        int idx = tid + i * 256;
        int r = idx >> 6, c = idx & 63;
        int gs = s0 - 16 + r;
        float v = 0.f;
        if ((unsigned)gs < (unsigned)SS)
            v = z[((size_t)b * SS + gs) * CP + c0 + c];
        zs[r][c] = v;
    }
    __syncthreads();

    const int pr = tid & 31;          // channel pair within tile
    const int sw = tid >> 5;          // 0..7
    const int P = (c0 >> 1) + pr;     // global pair 0..127
    const int slot = (P & 0x78) + 2 * (P & 3) + ((P >> 2) & 1);

    #pragma unroll 2
    for (int it = 0; it < 8; it++) {
        int sl = sw + it * 8;
        int s = s0 + sl;
        float Z = 0.f, a0 = 0.f, a1 = 0.f;
        #pragma unroll
        for (int d = -RWIN; d <= RWIN; ++d) {
            int t = s - d;
            if ((unsigned)t < (unsigned)SS) {
                float w = ws[d + RWIN];
                Z += w;
                float2 v = *(const float2*)&zs[sl + 16 - d][2 * pr];
                a0 += w * v.x;
                a1 += w * v.y;
            }
        }
        float inv = 1.f / Z;
        uint32_t h, l;
        cvt_pair(a0 * inv, a1 * inv, h, l);
        size_t row = (size_t)b * SS + s;
        z2h[row * 128 + slot] = h;
        z2l[row * 128 + slot] = l;
    }
}

// ---------------- launch ------------------------------------------------------------------
extern "C" void kernel_launch(void* const* d_in, const int* in_sizes, int n_in,
                              void* d_out, int out_size) {
    const float* x      = (const float*)d_in[0];
    const float* v_low  = (const float*)d_in[5];   // [242, 768]
    const float* v_high = (const float*)d_in[6];   // [256, 242]
    const float* o_low  = (const float*)d_in[7];   // [242, 256]
    const float* o_high = (const float*)d_in[8];   // [768, 242]
    float* out = (float*)d_out;                    // [4, 4096, 768]

    float* z   = nullptr; cudaGetSymbolAddress((void**)&z,   g_z);
    float* T1t = nullptr; cudaGetSymbolAddress((void**)&T1t, g_T1t);
    float* WcT = nullptr; cudaGetSymbolAddress((void**)&WcT, g_WcT);
    uint32_t* vlh = nullptr; cudaGetSymbolAddress((void**)&vlh, g_vlh);
    uint32_t* vll = nullptr; cudaGetSymbolAddress((void**)&vll, g_vll);
    uint32_t* wch = nullptr; cudaGetSymbolAddress((void**)&wch, g_wch);
    uint32_t* wcl = nullptr; cudaGetSymbolAddress((void**)&wcl, g_wcl);
    uint32_t* z2h = nullptr; cudaGetSymbolAddress((void**)&z2h, g_z2h);
    uint32_t* z2l = nullptr; cudaGetSymbolAddress((void**)&z2l, g_z2l);

    cudaFuncSetAttribute(mma_gemm_abt, cudaFuncAttributeMaxDynamicSharedMemorySize, SM_BYTES);
    cudaFuncSetAttribute(mma_gemm_bb,  cudaFuncAttributeMaxDynamicSharedMemorySize, SM2_BYTES);

    // 0. zero split-K accumulators (graph-capturable memsets)
    cudaMemsetAsync(T1t, 0, (size_t)RR * RR * sizeof(float));
    cudaMemsetAsync(WcT, 0, (size_t)HH * CP * sizeof(float));

    // 1. band weights
    prep_kernel<<<1, (RWIN + 1) * 32>>>();

    // 2. v_low -> bf16 hi/lo pair-interleaved, zero-padded to 256 rows
    conv_pairs<<<(CP * HH / 2 + 255) / 256, 256>>>(v_low, RR, HH, vlh, vll, CP);

    // 3. T1t[242,242] += o_low[242,256] @ v_high[256,242]   (split-K)
    sgemm_splitk<<<dim3(8, 8, 4), 256>>>(o_low, HK, v_high, RR, T1t, RR, RR, RR, HK);

    // 4. WcT[768,242] += o_high[768,242] @ T1t[242,242]     (split-K, ldc=256)
    sgemm_splitk<<<dim3(8, 24, 4), 256>>>(o_high, RR, T1t, RR, WcT, CP, HH, RR, RR);

    // 5. WcT -> bf16 hi/lo pair-interleaved
    conv_pairs<<<(HH * CP / 2 + 255) / 256, 256>>>(WcT, HH, CP, wch, wcl, HH);

    // 6. z = x @ v_low^T   [16384, 256]
    mma_gemm_abt<<<dim3(CP / 128, (BB * SS) / 128), 256, SM_BYTES>>>(
        x, HH, vlh, vll, HH / 2, z, CP, HH);

    // 7. banded softmax mix -> pair-interleaved bf16 hi/lo z2
    mix_kernel<<<dim3(SS / 64, CP / 64, BB), 256>>>(z, z2h, z2l);

    // 8. out = z2 @ WcT^T  [16384, 768]  (all-bf16 GEMM)
    mma_gemm_bb<<<dim3(HH / 128, (BB * SS) / 128), 256, SM2_BYTES>>>(
        z2h, z2l, CP / 2, wch, wcl, CP / 2, out, HH, CP);

    (void)in_sizes; (void)n_in; (void)out_size;
}

// round 8
// speedup vs baseline: 1.1139x; 1.0017x over previous
#include <cuda_runtime.h>
#include <cuda_bf16.h>
#include <cstdint>
#include <cstddef>

// Problem constants
#define BB 4
#define SS 4096
#define HH 768
#define RR 242
#define HK 256
#define CP 256
#define RWIN 16
#define NFREQ 384

// ---------------- device scratch ---------------------------------------------------------
__device__ float g_z [(size_t)BB * SS * CP];
__device__ float g_T1t[RR * RR];
__device__ float g_WcT[HH * CP];            // cols 242..255 stay zero
__device__ float g_e[RWIN + 1];
__device__ __align__(16) uint32_t g_vlh[CP * HH / 2];
__device__ __align__(16) uint32_t g_vll[CP * HH / 2];
__device__ __align__(16) uint32_t g_wch[HH * CP / 2];
__device__ __align__(16) uint32_t g_wcl[HH * CP / 2];
__device__ __align__(16) uint32_t g_z2h[(size_t)BB * SS * CP / 2];
__device__ __align__(16) uint32_t g_z2l[(size_t)BB * SS * CP / 2];

// ---------------- bf16 helpers -----------------------------------------------------------
__device__ __forceinline__ uint32_t pack_bf16x2(float e0, float e1) {
    uint32_t r;
    asm("cvt.rn.bf16x2.f32 %0, %1, %2;" : "=r"(r) : "f"(e1), "f"(e0));
    return r;
}
__device__ __forceinline__ void cvt_pair(float e0, float e1, uint32_t& hi, uint32_t& lo) {
    hi = pack_bf16x2(e0, e1);
    float h0 = __uint_as_float(hi << 16);
    float h1 = __uint_as_float(hi & 0xffff0000u);
    lo = pack_bf16x2(e0 - h0, e1 - h1);
}
__device__ __forceinline__ void mma_bf16(float* d, const uint32_t* a, uint32_t b0, uint32_t b1) {
    asm volatile(
        "mma.sync.aligned.m16n8k16.row.col.f32.bf16.bf16.f32 "
        "{%0,%1,%2,%3}, {%4,%5,%6,%7}, {%8,%9}, {%0,%1,%2,%3};"
        : "+f"(d[0]), "+f"(d[1]), "+f"(d[2]), "+f"(d[3])
        : "r"(a[0]), "r"(a[1]), "r"(a[2]), "r"(a[3]), "r"(b0), "r"(b1));
}
__device__ __forceinline__ uint32_t smem_u32(const void* p) {
    uint32_t a;
    asm("{ .reg .u64 t; cvta.to.shared.u64 t, %1; cvt.u32.u64 %0, t; }" : "=r"(a) : "l"(p));
    return a;
}
__device__ __forceinline__ void cp16(uint32_t dst, const void* src) {
    asm volatile("cp.async.cg.shared.global [%0], [%1], 16;" :: "r"(dst), "l"(src));
}
__device__ __forceinline__ void cp_commit() {
    asm volatile("cp.async.commit_group;" ::: "memory");
}
template<int N> __device__ __forceinline__ void cp_wait() {
    asm volatile("cp.async.wait_group %0;" :: "n"(N) : "memory");
}

// ---------------- pair-interleave conversion (device helper) -----------------------------
// slot j within an 8-slot (16-k) group holds pair p = (j>>1) + (j&1)*4.
__device__ __forceinline__ void conv_pairs_idx(int idx, const float* __restrict__ src,
                                               int rows_src, int cols,
                                               uint32_t* __restrict__ hi,
                                               uint32_t* __restrict__ lo) {
    int cols2 = cols >> 1;
    int row = idx / cols2;
    int s   = idx - row * cols2;
    int grp = s >> 3, j = s & 7;
    int k = (grp << 4) + (((j >> 1) + ((j & 1) << 2)) << 1);
    float e0 = 0.f, e1 = 0.f;
    if (row < rows_src) {
        e0 = src[(size_t)row * cols + k];
        e1 = src[(size_t)row * cols + k + 1];
    }
    uint32_t h, l;
    cvt_pair(e0, e1, h, l);
    hi[idx] = h;
    lo[idx] = l;
}

// ---------------- split-K 64x64 small gemm body (dynamic smem, 68-float pitch) -----------
#define WSM_BYTES (2 * 128 * 68 * 4)
__device__ void splitk64_body(float* smem,
                              const float* __restrict__ A, int lda,
                              const float* __restrict__ B, int ldb,
                              float* __restrict__ C, int ldc,
                              int M, int N, int K,
                              int m_t, int n_t, int kz, int kslice) {
    float* As = smem;             // [128][68]  As[k][m]
    float* Bs = smem + 128 * 68;  // [128][68]  Bs[k][n]
    const int tid = threadIdx.x;
    const int m0 = m_t * 64, n0 = n_t * 64, k0 = kz * kslice;
    const int kl = min(kslice, K - k0);
    #pragma unroll
    for (int i = 0; i < 32; i++) {
        int idx = tid + i * 256;
        int m = idx >> 7, k = idx & 127;
        float v = 0.f;
        if (k < kl && m0 + m < M) v = A[(size_t)(m0 + m) * lda + k0 + k];
        As[k * 68 + m] = v;
    }
    #pragma unroll
    for (int i = 0; i < 32; i++) {
        int idx = tid + i * 256;
        int k = idx >> 6, n = idx & 63;
        float v = 0.f;
        if (k < kl && n0 + n < N) v = B[(size_t)(k0 + k) * ldb + n0 + n];
        Bs[k * 68 + n] = v;
    }
    __syncthreads();
    const int ty = tid >> 4, tx = tid & 15;
    float acc[4][4] = {};
    for (int k = 0; k < kl; k++) {
        float4 a = *(const float4*)&As[k * 68 + ty * 4];
        float4 b = *(const float4*)&Bs[k * 68 + tx * 4];
        acc[0][0] += a.x * b.x; acc[0][1] += a.x * b.y; acc[0][2] += a.x * b.z; acc[0][3] += a.x * b.w;
        acc[1][0] += a.y * b.x; acc[1][1] += a.y * b.y; acc[1][2] += a.y * b.z; acc[1][3] += a.y * b.w;
        acc[2][0] += a.z * b.x; acc[2][1] += a.z * b.y; acc[2][2] += a.z * b.z; acc[2][3] += a.z * b.w;
        acc[3][0] += a.w * b.x; acc[3][1] += a.w * b.y; acc[3][2] += a.w * b.z; acc[3][3] += a.w * b.w;
    }
    #pragma unroll
    for (int i = 0; i < 4; i++) {
        int m = m0 + ty * 4 + i;
        if (m >= M) continue;
        #pragma unroll
        for (int j = 0; j < 4; j++) {
            int n = n0 + tx * 4 + j;
            if (n < N) atomicAdd(&C[(size_t)m * ldc + n], acc[i][j]);
        }
    }
}

// ---------------- W1: conv(v_low) + band-weight prep + zero T1t --------------------------
// blocks [0,384): conv v_low;  [384,387): prep (w = (bid-384)*8 + warp);  rest: zero T1t
__global__ void __launch_bounds__(256)
wk1(const float* __restrict__ v_low, uint32_t* __restrict__ vlh, uint32_t* __restrict__ vll,
    float* __restrict__ T1t) {
    const int bid = blockIdx.x, tid = threadIdx.x;
    if (bid < 384) {
        conv_pairs_idx(bid * 256 + tid, v_low, RR, HH, vlh, vll);
    } else if (bid < 387) {
        int w = (bid - 384) * 8 + (tid >> 5);
        int lane = tid & 31;
        if (w > RWIN) return;
        float d = (float)w, s = 0.f;
        for (int j = lane; j < NFREQ; j += 32) {
            float f = expf(-(float)j * (9.210340371976184f / (float)NFREQ));
            s += cosf(d * f);
        }
        #pragma unroll
        for (int o = 16; o > 0; o >>= 1) s += __shfl_down_sync(0xffffffffu, s, o);
        if (lane == 0) g_e[w] = expf(s - (float)NFREQ);
    } else {
        int idx = (bid - 387) * 256 + tid;           // float4 units; T1t = 14641 float4
        if (idx < (RR * RR) / 4) ((float4*)T1t)[idx] = make_float4(0.f, 0.f, 0.f, 0.f);
    }
}

// ---------------- W2: splitk T1t (+ zero WcT) --------------------------------------------
__global__ void __launch_bounds__(256)
wk2(const float* __restrict__ o_low, const float* __restrict__ v_high,
    float* __restrict__ T1t, float* __restrict__ WcT) {
    extern __shared__ float wsm[];
    const int cb = blockIdx.x;
    if (cb < 32) {
        int n_t = cb & 3, m_t = (cb >> 2) & 3, kz = cb >> 4;
        splitk64_body(wsm, o_low, HK, v_high, RR, T1t, RR, RR, RR, HK, m_t, n_t, kz, 128);
    } else {
        int idx = (cb - 32) * 256 + threadIdx.x;     // float4 units; WcT = 49152 float4
        if (idx < (HH * CP) / 4) ((float4*)WcT)[idx] = make_float4(0.f, 0.f, 0.f, 0.f);
    }
}

// ---------------- W3: splitk WcT ----------------------------------------------------------
__global__ void __launch_bounds__(256)
wk3(const float* __restrict__ o_high, const float* __restrict__ T1t,
    float* __restrict__ WcT) {
    extern __shared__ float wsm[];
    const int cb = blockIdx.x;                       // 96 blocks: 4 n x 12 m x 2 k
    int n_t = cb & 3, m_t = (cb >> 2) % 12, kz = cb / 48;
    splitk64_body(wsm, o_high, RR, T1t, RR, WcT, CP, HH, RR, RR, m_t, n_t, kz, 121);
}

// ---------------- W4: conv(WcT) -----------------------------------------------------------
__global__ void __launch_bounds__(256)
wk4(const float* __restrict__ WcT, uint32_t* __restrict__ wch, uint32_t* __restrict__ wcl) {
    conv_pairs_idx(blockIdx.x * 256 + threadIdx.x, WcT, HH, CP, wch, wcl);
}

// ---------------- gemm1: C = A_f32 @ B_bf16split^T (single-sync pipeline) ----------------
#define A_PITCH 40
#define B_PITCH 24
#define A_U32 (128 * A_PITCH)
#define B_U32 (128 * B_PITCH)
#define STAGE_U32 (A_U32 + 2 * B_U32)
#define SM_BYTES (2 * STAGE_U32 * 4)

__global__ void __launch_bounds__(256, 2)
mma_gemm_abt(const float* __restrict__ A, int lda,
             const uint32_t* __restrict__ Bh,
             const uint32_t* __restrict__ Bl, int ldbu,
             float* __restrict__ C, int ldc, int K) {
    extern __shared__ uint32_t sm4[];
    const uint32_t sb = smem_u32(sm4);
    const int tid  = threadIdx.x;
    const int wid  = tid >> 5;
    const int lane = tid & 31;
    const int m0 = blockIdx.y * 128;
    const int n0 = blockIdx.x * 128;
    const int mbw = (wid & 3) * 32;
    const int nbw = (wid >> 2) * 64;
    const int lr = lane >> 2;
    const int lc = lane & 3;

    const int ar = tid >> 3, ac = tid & 7;
    const int br = tid >> 2, bc = tid & 3;

    const float*    aSrc  = A  + (size_t)(m0 + ar) * lda + ac * 4;
    const uint32_t* bhSrc = Bh + (size_t)(n0 + br) * ldbu + bc * 4;
    const uint32_t* blSrc = Bl + (size_t)(n0 + br) * ldbu + bc * 4;
    const uint32_t aDst  = sb + (ar * A_PITCH + ac * 4) * 4;
    const uint32_t bhDst = sb + (A_U32 + br * B_PITCH + bc * 4) * 4;
    const uint32_t blDst = sb + (A_U32 + B_U32 + br * B_PITCH + bc * 4) * 4;

    float acc[2][8][4] = {};
    const int nchunks = K >> 5;

    #define ISSUE(ch) do {                                                          \
        const uint32_t so_ = ((ch) & 1) * (STAGE_U32 * 4);                          \
        const int kf_ = (ch) << 5;                                                  \
        const int ku_ = (ch) << 4;                                                  \
        _Pragma("unroll")                                                           \
        for (int i_ = 0; i_ < 4; i_++)                                              \
            cp16(aDst + so_ + i_ * 32 * A_PITCH * 4,                                \
                 aSrc + kf_ + (size_t)i_ * 32 * lda);                               \
        _Pragma("unroll")                                                           \
        for (int i_ = 0; i_ < 2; i_++) {                                            \
            cp16(bhDst + so_ + i_ * 64 * B_PITCH * 4,                               \
                 bhSrc + ku_ + (size_t)i_ * 64 * ldbu);                             \
            cp16(blDst + so_ + i_ * 64 * B_PITCH * 4,                               \
                 blSrc + ku_ + (size_t)i_ * 64 * ldbu);                             \
        }                                                                           \
        cp_commit();                                                                \
    } while (0)

    ISSUE(0);
    for (int ch = 0; ch < nchunks; ch++) {
        cp_wait<0>();
        __syncthreads();
        if (ch + 1 < nchunks) ISSUE(ch + 1);

        const uint32_t stg = (ch & 1) * STAGE_U32;
        const float* As = (const float*)(sm4 + stg);
        const uint32_t* BHs = sm4 + stg + A_U32;
        const uint32_t* BLs = sm4 + stg + A_U32 + B_U32;

        #pragma unroll
        for (int ks = 0; ks < 2; ks++) {
            uint32_t ah[2][4], al[2][4];
            #pragma unroll
            for (int t = 0; t < 2; t++) {
                const float* ap = As + (mbw + t * 16 + lr) * A_PITCH + ks * 16 + 2 * lc;
                float2 f0 = *(const float2*)(ap);
                float2 f1 = *(const float2*)(ap + 8 * A_PITCH);
                float2 f2 = *(const float2*)(ap + 8);
                float2 f3 = *(const float2*)(ap + 8 * A_PITCH + 8);
                cvt_pair(f0.x, f0.y, ah[t][0], al[t][0]);
                cvt_pair(f1.x, f1.y, ah[t][1], al[t][1]);
                cvt_pair(f2.x, f2.y, ah[t][2], al[t][2]);
                cvt_pair(f3.x, f3.y, ah[t][3], al[t][3]);
            }
            #pragma unroll
            for (int u = 0; u < 8; u++) {
                int rb = (nbw + u * 8 + lr) * B_PITCH + ks * 8 + 2 * lc;
                uint2 bh = *(const uint2*)(BHs + rb);
                uint2 bl = *(const uint2*)(BLs + rb);
                #pragma unroll
                for (int t = 0; t < 2; t++) {
                    mma_bf16(acc[t][u], ah[t], bh.x, bh.y);
                    mma_bf16(acc[t][u], ah[t], bl.x, bl.y);
                    mma_bf16(acc[t][u], al[t], bh.x, bh.y);
                }
            }
        }
    }

    #pragma unroll
    for (int t = 0; t < 2; t++) {
        int row = m0 + mbw + t * 16 + lr;
        #pragma unroll
        for (int u = 0; u < 8; u++) {
            int col = n0 + nbw + u * 8 + lc * 2;
            *(float2*)(C + (size_t)row * ldc + col) = make_float2(acc[t][u][0], acc[t][u][1]);
            *(float2*)(C + (size_t)(row + 8) * ldc + col) = make_float2(acc[t][u][2], acc[t][u][3]);
        }
    }
}

// ---------------- gemm2: C = A_bf16split @ B_bf16split^T (single-sync pipeline) ----------
#define P2 24
#define T2_U32 (128 * P2)
#define STAGE2_U32 (4 * T2_U32)
#define SM2_BYTES (2 * STAGE2_U32 * 4)

__global__ void __launch_bounds__(256, 2)
mma_gemm_bb(const uint32_t* __restrict__ Ah, const uint32_t* __restrict__ Al, int ldau,
            const uint32_t* __restrict__ Bh, const uint32_t* __restrict__ Bl, int ldbu,
            float* __restrict__ C, int ldc, int K) {
    extern __shared__ uint32_t sm4[];
    const uint32_t sb = smem_u32(sm4);
    const int tid  = threadIdx.x;
    const int wid  = tid >> 5;
    const int lane = tid & 31;
    const int m0 = blockIdx.y * 128;
    const int n0 = blockIdx.x * 128;
    const int mbw = (wid & 3) * 32;
    const int nbw = (wid >> 2) * 64;
    const int lr = lane >> 2;
    const int lc = lane & 3;

    const int fr = tid >> 2, fc = tid & 3;

    const uint32_t* s0p[4] = { Ah + (size_t)(m0 + fr) * ldau + fc * 4,
                               Al + (size_t)(m0 + fr) * ldau + fc * 4,
                               Bh + (size_t)(n0 + fr) * ldbu + fc * 4,
                               Bl + (size_t)(n0 + fr) * ldbu + fc * 4 };
    const int lds[4] = { ldau, ldau, ldbu, ldbu };
    const uint32_t dst0 = sb + (fr * P2 + fc * 4) * 4;

    float acc[2][8][4] = {};
    const int nchunks = K >> 5;

    #define ISSUE2(ch) do {                                                         \
        const uint32_t so_ = ((ch) & 1) * (STAGE2_U32 * 4);                         \
        const int ku_ = (ch) << 4;                                                  \
        _Pragma("unroll")                                                           \
        for (int a_ = 0; a_ < 4; a_++) {                                            \
            _Pragma("unroll")                                                       \
            for (int i_ = 0; i_ < 2; i_++)                                          \
                cp16(dst0 + so_ + (a_ * T2_U32 + i_ * 64 * P2) * 4,                 \
                     s0p[a_] + ku_ + (size_t)i_ * 64 * lds[a_]);                    \
        }                                                                           \
        cp_commit();                                                                \
    } while (0)

    ISSUE2(0);
    for (int ch = 0; ch < nchunks; ch++) {
        cp_wait<0>();
        __syncthreads();
        if (ch + 1 < nchunks) ISSUE2(ch + 1);

        const uint32_t stg = (ch & 1) * STAGE2_U32;
        const uint32_t* AHs = sm4 + stg;
        const uint32_t* ALs = sm4 + stg + T2_U32;
        const uint32_t* BHs = sm4 + stg + 2 * T2_U32;
        const uint32_t* BLs = sm4 + stg + 3 * T2_U32;

        #pragma unroll
        for (int ks = 0; ks < 2; ks++) {
            uint32_t ah[2][4], al[2][4];
            #pragma unroll
            for (int t = 0; t < 2; t++) {
                int ba = (mbw + t * 16 + lr) * P2 + ks * 8 + 2 * lc;
                uint2 h0 = *(const uint2*)(AHs + ba);
                uint2 h8 = *(const uint2*)(AHs + ba + 8 * P2);
                uint2 l0 = *(const uint2*)(ALs + ba);
                uint2 l8 = *(const uint2*)(ALs + ba + 8 * P2);
                ah[t][0] = h0.x; ah[t][1] = h8.x; ah[t][2] = h0.y; ah[t][3] = h8.y;
                al[t][0] = l0.x; al[t][1] = l8.x; al[t][2] = l0.y; al[t][3] = l8.y;
            }
            #pragma unroll
            for (int u = 0; u < 8; u++) {
                int rb = (nbw + u * 8 + lr) * P2 + ks * 8 + 2 * lc;
                uint2 bh = *(const uint2*)(BHs + rb);
                uint2 bl = *(const uint2*)(BLs + rb);
                #pragma unroll
                for (int t = 0; t < 2; t++) {
                    mma_bf16(acc[t][u], ah[t], bh.x, bh.y);
                    mma_bf16(acc[t][u], ah[t], bl.x, bl.y);
                    mma_bf16(acc[t][u], al[t], bh.x, bh.y);
                }
            }
        }
    }

    #pragma unroll
    for (int t = 0; t < 2; t++) {
        int row = m0 + mbw + t * 16 + lr;
        #pragma unroll
        for (int u = 0; u < 8; u++) {
            int col = n0 + nbw + u * 8 + lc * 2;
            *(float2*)(C + (size_t)row * ldc + col) = make_float2(acc[t][u][0], acc[t][u][1]);
            *(float2*)(C + (size_t)(row + 8) * ldc + col) = make_float2(acc[t][u][2], acc[t][u][3]);
        }
    }
}

// ---------------- banded softmax mix -> pair-interleaved bf16 hi/lo ----------------------
__global__ void __launch_bounds__(256)
mix_kernel(const float* __restrict__ z,
           uint32_t* __restrict__ z2h, uint32_t* __restrict__ z2l) {
    __shared__ float zs[96][64];
    __shared__ float ws[2 * RWIN + 1];
    const int s0 = blockIdx.x * 64;
    const int c0 = blockIdx.y * 64;
    const int b  = blockIdx.z;
    const int tid = threadIdx.x;

    if (tid < 2 * RWIN + 1) ws[tid] = g_e[tid < RWIN ? RWIN - tid : tid - RWIN];

    #pragma unroll
    for (int i = 0; i < 24; i++) {
        int idx = tid + i * 256;
        int r = idx >> 6, c = idx & 63;
        int gs = s0 - 16 + r;
        float v = 0.f;
        if ((unsigned)gs < (unsigned)SS)
            v = z[((size_t)b * SS + gs) * CP + c0 + c];
        zs[r][c] = v;
    }
    __syncthreads();

    const int pr = tid & 31;
    const int sw = tid >> 5;
    const int P = (c0 >> 1) + pr;
    const int slot = (P & 0x78) + 2 * (P & 3) + ((P >> 2) & 1);

    #pragma unroll 2
    for (int it = 0; it < 8; it++) {
        int sl = sw + it * 8;
        int s = s0 + sl;
        float Z = 0.f, a0 = 0.f, a1 = 0.f;
        #pragma unroll
        for (int d = -RWIN; d <= RWIN; ++d) {
            int t = s - d;
            if ((unsigned)t < (unsigned)SS) {
                float w = ws[d + RWIN];
                Z += w;
                float2 v = *(const float2*)&zs[sl + 16 - d][2 * pr];
                a0 += w * v.x;
                a1 += w * v.y;
            }
        }
        float inv = 1.f / Z;
        uint32_t h, l;
        cvt_pair(a0 * inv, a1 * inv, h, l);
        size_t row = (size_t)b * SS + s;
        z2h[row * 128 + slot] = h;
        z2l[row * 128 + slot] = l;
    }
}

// ---------------- launch ------------------------------------------------------------------
extern "C" void kernel_launch(void* const* d_in, const int* in_sizes, int n_in,
                              void* d_out, int out_size) {
    const float* x      = (const float*)d_in[0];
    const float* v_low  = (const float*)d_in[5];   // [242, 768]
    const float* v_high = (const float*)d_in[6];   // [256, 242]
    const float* o_low  = (const float*)d_in[7];   // [242, 256]
    const float* o_high = (const float*)d_in[8];   // [768, 242]
    float* out = (float*)d_out;                    // [4, 4096, 768]

    float* z   = nullptr; cudaGetSymbolAddress((void**)&z,   g_z);
    float* T1t = nullptr; cudaGetSymbolAddress((void**)&T1t, g_T1t);
    float* WcT = nullptr; cudaGetSymbolAddress((void**)&WcT, g_WcT);
    uint32_t* vlh = nullptr; cudaGetSymbolAddress((void**)&vlh, g_vlh);
    uint32_t* vll = nullptr; cudaGetSymbolAddress((void**)&vll, g_vll);
    uint32_t* wch = nullptr; cudaGetSymbolAddress((void**)&wch, g_wch);
    uint32_t* wcl = nullptr; cudaGetSymbolAddress((void**)&wcl, g_wcl);
    uint32_t* z2h = nullptr; cudaGetSymbolAddress((void**)&z2h, g_z2h);
    uint32_t* z2l = nullptr; cudaGetSymbolAddress((void**)&z2l, g_z2l);

    cudaFuncSetAttribute(mma_gemm_abt, cudaFuncAttributeMaxDynamicSharedMemorySize, SM_BYTES);
    cudaFuncSetAttribute(mma_gemm_bb,  cudaFuncAttributeMaxDynamicSharedMemorySize, SM2_BYTES);
    cudaFuncSetAttribute(wk2, cudaFuncAttributeMaxDynamicSharedMemorySize, WSM_BYTES);
    cudaFuncSetAttribute(wk3, cudaFuncAttributeMaxDynamicSharedMemorySize, WSM_BYTES);

    // W1: conv(v_low) + prep + zero T1t       (384 + 3 + 58 blocks)
    wk1<<<445, 256>>>(v_low, vlh, vll, T1t);
    // W2: splitk T1t + zero WcT               (32 + 192 blocks)
    wk2<<<224, 256, WSM_BYTES>>>(o_low, v_high, T1t, WcT);
    // W3: splitk WcT                          (96 blocks)
    wk3<<<96, 256, WSM_BYTES>>>(o_high, T1t, WcT);
    // W4: conv(WcT)                           (384 blocks)
    wk4<<<384, 256>>>(WcT, wch, wcl);

    // gemm1: z = x @ v_low^T   [16384, 256]
    mma_gemm_abt<<<dim3(CP / 128, (BB * SS) / 128), 256, SM_BYTES>>>(
        x, HH, vlh, vll, HH / 2, z, CP, HH);

    // banded softmax mix -> pair-interleaved bf16 hi/lo z2
    mix_kernel<<<dim3(SS / 64, CP / 64, BB), 256>>>(z, z2h, z2l);

    // gemm2: out = z2 @ WcT^T  [16384, 768]
    mma_gemm_bb<<<dim3(HH / 128, (BB * SS) / 128), 256, SM2_BYTES>>>(
        z2h, z2l, CP / 2, wch, wcl, CP / 2, out, HH, CP);

    (void)in_sizes; (void)n_in; (void)out_size;
}

// round 9
// speedup vs baseline: 1.3827x; 1.2414x over previous
#include <cuda_runtime.h>
#include <cuda_fp16.h>
#include <cstdint>
#include <cstddef>

// Problem constants
#define BB 4
#define SS 4096
#define HH 768
#define RR 242
#define HK 256
#define CP 256
#define RWIN 16
#define NFREQ 384

// ---------------- device scratch ---------------------------------------------------------
__device__ float g_z [(size_t)BB * SS * CP];
__device__ float g_T1t[RR * RR];
__device__ float g_WcT[HH * CP];            // cols 242..255 stay zero
__device__ float g_e[RWIN + 1];
// pair-interleaved fp16x2 tensors, stored as u32 (one k-pair per word)
__device__ __align__(16) uint32_t g_vlh[CP * HH / 2];
__device__ __align__(16) uint32_t g_vll[CP * HH / 2];
__device__ __align__(16) uint32_t g_wch[HH * CP / 2];
__device__ __align__(16) uint32_t g_wcl[HH * CP / 2];
__device__ __align__(16) uint32_t g_z2f[(size_t)BB * SS * CP / 2];

// ---------------- fp16 helpers -----------------------------------------------------------
__device__ __forceinline__ uint32_t pack_f16x2(float e0, float e1) {
    uint32_t r;                      // low half = e0, high half = e1
    asm("cvt.rn.f16x2.f32 %0, %1, %2;" : "=r"(r) : "f"(e1), "f"(e0));
    return r;
}
__device__ __forceinline__ void cvt_pair_f16(float e0, float e1, uint32_t& hi, uint32_t& lo) {
    hi = pack_f16x2(e0, e1);
    __half2 h = *reinterpret_cast<__half2*>(&hi);
    float h0 = __half2float(__low2half(h));
    float h1 = __half2float(__high2half(h));
    lo = pack_f16x2(e0 - h0, e1 - h1);
}
__device__ __forceinline__ void mma_f16(float* d, const uint32_t* a, uint32_t b0, uint32_t b1) {
    asm volatile(
        "mma.sync.aligned.m16n8k16.row.col.f32.f16.f16.f32 "
        "{%0,%1,%2,%3}, {%4,%5,%6,%7}, {%8,%9}, {%0,%1,%2,%3};"
        : "+f"(d[0]), "+f"(d[1]), "+f"(d[2]), "+f"(d[3])
        : "r"(a[0]), "r"(a[1]), "r"(a[2]), "r"(a[3]), "r"(b0), "r"(b1));
}
__device__ __forceinline__ uint32_t smem_u32(const void* p) {
    uint32_t a;
    asm("{ .reg .u64 t; cvta.to.shared.u64 t, %1; cvt.u32.u64 %0, t; }" : "=r"(a) : "l"(p));
    return a;
}
__device__ __forceinline__ void cp16(uint32_t dst, const void* src) {
    asm volatile("cp.async.cg.shared.global [%0], [%1], 16;" :: "r"(dst), "l"(src));
}
__device__ __forceinline__ void cp_commit() {
    asm volatile("cp.async.commit_group;" ::: "memory");
}
template<int N> __device__ __forceinline__ void cp_wait() {
    asm volatile("cp.async.wait_group %0;" :: "n"(N) : "memory");
}

// ---------------- pair-interleave conversion (device helper) -----------------------------
// slot j within an 8-slot (16-k) group holds pair p = (j>>1) + (j&1)*4.
__device__ __forceinline__ void conv_pairs_idx(int idx, const float* __restrict__ src,
                                               int rows_src, int cols,
                                               uint32_t* __restrict__ hi,
                                               uint32_t* __restrict__ lo) {
    int cols2 = cols >> 1;
    int row = idx / cols2;
    int s   = idx - row * cols2;
    int grp = s >> 3, j = s & 7;
    int k = (grp << 4) + (((j >> 1) + ((j & 1) << 2)) << 1);
    float e0 = 0.f, e1 = 0.f;
    if (row < rows_src) {
        e0 = src[(size_t)row * cols + k];
        e1 = src[(size_t)row * cols + k + 1];
    }
    uint32_t h, l;
    cvt_pair_f16(e0, e1, h, l);
    hi[idx] = h;
    lo[idx] = l;
}

// ---------------- split-K 64x64 small gemm body ------------------------------------------
#define WSM_BYTES (2 * 128 * 68 * 4)
__device__ void splitk64_body(float* smem,
                              const float* __restrict__ A, int lda,
                              const float* __restrict__ B, int ldb,
                              float* __restrict__ C, int ldc,
                              int M, int N, int K,
                              int m_t, int n_t, int kz, int kslice) {
    float* As = smem;
    float* Bs = smem + 128 * 68;
    const int tid = threadIdx.x;
    const int m0 = m_t * 64, n0 = n_t * 64, k0 = kz * kslice;
    const int kl = min(kslice, K - k0);
    #pragma unroll
    for (int i = 0; i < 32; i++) {
        int idx = tid + i * 256;
        int m = idx >> 7, k = idx & 127;
        float v = 0.f;
        if (k < kl && m0 + m < M) v = A[(size_t)(m0 + m) * lda + k0 + k];
        As[k * 68 + m] = v;
    }
    #pragma unroll
    for (int i = 0; i < 32; i++) {
        int idx = tid + i * 256;
        int k = idx >> 6, n = idx & 63;
        float v = 0.f;
        if (k < kl && n0 + n < N) v = B[(size_t)(k0 + k) * ldb + n0 + n];
        Bs[k * 68 + n] = v;
    }
    __syncthreads();
    const int ty = tid >> 4, tx = tid & 15;
    float acc[4][4] = {};
    for (int k = 0; k < kl; k++) {
        float4 a = *(const float4*)&As[k * 68 + ty * 4];
        float4 b = *(const float4*)&Bs[k * 68 + tx * 4];
        acc[0][0] += a.x * b.x; acc[0][1] += a.x * b.y; acc[0][2] += a.x * b.z; acc[0][3] += a.x * b.w;
        acc[1][0] += a.y * b.x; acc[1][1] += a.y * b.y; acc[1][2] += a.y * b.z; acc[1][3] += a.y * b.w;
        acc[2][0] += a.z * b.x; acc[2][1] += a.z * b.y; acc[2][2] += a.z * b.z; acc[2][3] += a.z * b.w;
        acc[3][0] += a.w * b.x; acc[3][1] += a.w * b.y; acc[3][2] += a.w * b.z; acc[3][3] += a.w * b.w;
    }
    #pragma unroll
    for (int i = 0; i < 4; i++) {
        int m = m0 + ty * 4 + i;
        if (m >= M) continue;
        #pragma unroll
        for (int j = 0; j < 4; j++) {
            int n = n0 + tx * 4 + j;
            if (n < N) atomicAdd(&C[(size_t)m * ldc + n], acc[i][j]);
        }
    }
}

// ---------------- W1: conv(v_low) + band-weight prep + zero T1t --------------------------
__global__ void __launch_bounds__(256)
wk1(const float* __restrict__ v_low, uint32_t* __restrict__ vlh, uint32_t* __restrict__ vll,
    float* __restrict__ T1t) {
    const int bid = blockIdx.x, tid = threadIdx.x;
    if (bid < 384) {
        conv_pairs_idx(bid * 256 + tid, v_low, RR, HH, vlh, vll);
    } else if (bid < 387) {
        int w = (bid - 384) * 8 + (tid >> 5);
        int lane = tid & 31;
        if (w > RWIN) return;
        float d = (float)w, s = 0.f;
        for (int j = lane; j < NFREQ; j += 32) {
            float f = expf(-(float)j * (9.210340371976184f / (float)NFREQ));
            s += cosf(d * f);
        }
        #pragma unroll
        for (int o = 16; o > 0; o >>= 1) s += __shfl_down_sync(0xffffffffu, s, o);
        if (lane == 0) g_e[w] = expf(s - (float)NFREQ);
    } else {
        int idx = (bid - 387) * 256 + tid;
        if (idx < (RR * RR) / 4) ((float4*)T1t)[idx] = make_float4(0.f, 0.f, 0.f, 0.f);
    }
}

// ---------------- W2: splitk T1t (+ zero WcT) --------------------------------------------
__global__ void __launch_bounds__(256)
wk2(const float* __restrict__ o_low, const float* __restrict__ v_high,
    float* __restrict__ T1t, float* __restrict__ WcT) {
    extern __shared__ float wsm[];
    const int cb = blockIdx.x;
    if (cb < 32) {
        int n_t = cb & 3, m_t = (cb >> 2) & 3, kz = cb >> 4;
        splitk64_body(wsm, o_low, HK, v_high, RR, T1t, RR, RR, RR, HK, m_t, n_t, kz, 128);
    } else {
        int idx = (cb - 32) * 256 + threadIdx.x;
        if (idx < (HH * CP) / 4) ((float4*)WcT)[idx] = make_float4(0.f, 0.f, 0.f, 0.f);
    }
}

// ---------------- W3: splitk WcT ----------------------------------------------------------
__global__ void __launch_bounds__(256)
wk3(const float* __restrict__ o_high, const float* __restrict__ T1t,
    float* __restrict__ WcT) {
    extern __shared__ float wsm[];
    const int cb = blockIdx.x;
    int n_t = cb & 3, m_t = (cb >> 2) % 12, kz = cb / 48;
    splitk64_body(wsm, o_high, RR, T1t, RR, WcT, CP, HH, RR, RR, m_t, n_t, kz, 121);
}

// ---------------- W4: conv(WcT) -----------------------------------------------------------
__global__ void __launch_bounds__(256)
wk4(const float* __restrict__ WcT, uint32_t* __restrict__ wch, uint32_t* __restrict__ wcl) {
    conv_pairs_idx(blockIdx.x * 256 + threadIdx.x, WcT, HH, CP, wch, wcl);
}

// ---------------- gemm1: C = round_f16(A_f32) @ B_f16split^T -----------------------------
// 2-term: ah*bh + ah*bl. BM=BN=128, BK=32; 8 warps (4M x 2N), warp tile 32x64.
#define A_PITCH 40
#define B_PITCH 24
#define A_U32 (128 * A_PITCH)
#define B_U32 (128 * B_PITCH)
#define STAGE_U32 (A_U32 + 2 * B_U32)
#define SM_BYTES (2 * STAGE_U32 * 4)

__global__ void __launch_bounds__(256, 2)
mma_gemm_abt(const float* __restrict__ A, int lda,
             const uint32_t* __restrict__ Bh,
             const uint32_t* __restrict__ Bl, int ldbu,
             float* __restrict__ C, int ldc, int K) {
    extern __shared__ uint32_t sm4[];
    const uint32_t sb = smem_u32(sm4);
    const int tid  = threadIdx.x;
    const int wid  = tid >> 5;
    const int lane = tid & 31;
    const int m0 = blockIdx.y * 128;
    const int n0 = blockIdx.x * 128;
    const int mbw = (wid & 3) * 32;
    const int nbw = (wid >> 2) * 64;
    const int lr = lane >> 2;
    const int lc = lane & 3;

    const int ar = tid >> 3, ac = tid & 7;
    const int br = tid >> 2, bc = tid & 3;

    const float*    aSrc  = A  + (size_t)(m0 + ar) * lda + ac * 4;
    const uint32_t* bhSrc = Bh + (size_t)(n0 + br) * ldbu + bc * 4;
    const uint32_t* blSrc = Bl + (size_t)(n0 + br) * ldbu + bc * 4;
    const uint32_t aDst  = sb + (ar * A_PITCH + ac * 4) * 4;
    const uint32_t bhDst = sb + (A_U32 + br * B_PITCH + bc * 4) * 4;
    const uint32_t blDst = sb + (A_U32 + B_U32 + br * B_PITCH + bc * 4) * 4;

    float acc[2][8][4] = {};
    const int nchunks = K >> 5;

    #define ISSUE(ch) do {                                                          \
        const uint32_t so_ = ((ch) & 1) * (STAGE_U32 * 4);                          \
        const int kf_ = (ch) << 5;                                                  \
        const int ku_ = (ch) << 4;                                                  \
        _Pragma("unroll")                                                           \
        for (int i_ = 0; i_ < 4; i_++)                                              \
            cp16(aDst + so_ + i_ * 32 * A_PITCH * 4,                                \
                 aSrc + kf_ + (size_t)i_ * 32 * lda);                               \
        _Pragma("unroll")                                                           \
        for (int i_ = 0; i_ < 2; i_++) {                                            \
            cp16(bhDst + so_ + i_ * 64 * B_PITCH * 4,                               \
                 bhSrc + ku_ + (size_t)i_ * 64 * ldbu);                             \
            cp16(blDst + so_ + i_ * 64 * B_PITCH * 4,                               \
                 blSrc + ku_ + (size_t)i_ * 64 * ldbu);                             \
        }                                                                           \
        cp_commit();                                                                \
    } while (0)

    ISSUE(0);
    for (int ch = 0; ch < nchunks; ch++) {
        cp_wait<0>();
        __syncthreads();
        if (ch + 1 < nchunks) ISSUE(ch + 1);

        const uint32_t stg = (ch & 1) * STAGE_U32;
        const float* As = (const float*)(sm4 + stg);
        const uint32_t* BHs = sm4 + stg + A_U32;
        const uint32_t* BLs = sm4 + stg + A_U32 + B_U32;

        #pragma unroll
        for (int ks = 0; ks < 2; ks++) {
            uint32_t ah[2][4];
            #pragma unroll
            for (int t = 0; t < 2; t++) {
                const float* ap = As + (mbw + t * 16 + lr) * A_PITCH + ks * 16 + 2 * lc;
                float2 f0 = *(const float2*)(ap);
                float2 f1 = *(const float2*)(ap + 8 * A_PITCH);
                float2 f2 = *(const float2*)(ap + 8);
                float2 f3 = *(const float2*)(ap + 8 * A_PITCH + 8);
                ah[t][0] = pack_f16x2(f0.x, f0.y);
                ah[t][1] = pack_f16x2(f1.x, f1.y);
                ah[t][2] = pack_f16x2(f2.x, f2.y);
                ah[t][3] = pack_f16x2(f3.x, f3.y);
            }
            #pragma unroll
            for (int u = 0; u < 8; u++) {
                int rb = (nbw + u * 8 + lr) * B_PITCH + ks * 8 + 2 * lc;
                uint2 bh = *(const uint2*)(BHs + rb);
                uint2 bl = *(const uint2*)(BLs + rb);
                #pragma unroll
                for (int t = 0; t < 2; t++) {
                    mma_f16(acc[t][u], ah[t], bh.x, bh.y);
                    mma_f16(acc[t][u], ah[t], bl.x, bl.y);
                }
            }
        }
    }

    #pragma unroll
    for (int t = 0; t < 2; t++) {
        int row = m0 + mbw + t * 16 + lr;
        #pragma unroll
        for (int u = 0; u < 8; u++) {
            int col = n0 + nbw + u * 8 + lc * 2;
            *(float2*)(C + (size_t)row * ldc + col) = make_float2(acc[t][u][0], acc[t][u][1]);
            *(float2*)(C + (size_t)(row + 8) * ldc + col) = make_float2(acc[t][u][2], acc[t][u][3]);
        }
    }
}

// ---------------- gemm2: C = A_f16 @ B_f16split^T (all fp16, 2-term) ---------------------
#define P2 24
#define T2_U32 (128 * P2)
#define STAGE2_U32 (3 * T2_U32)           // AF, BH, BL
#define SM2_BYTES (2 * STAGE2_U32 * 4)    // 73728 B

__global__ void __launch_bounds__(256, 2)
mma_gemm_fb(const uint32_t* __restrict__ Af, int ldau,
            const uint32_t* __restrict__ Bh, const uint32_t* __restrict__ Bl, int ldbu,
            float* __restrict__ C, int ldc, int K) {
    extern __shared__ uint32_t sm4[];
    const uint32_t sb = smem_u32(sm4);
    const int tid  = threadIdx.x;
    const int wid  = tid >> 5;
    const int lane = tid & 31;
    const int m0 = blockIdx.y * 128;
    const int n0 = blockIdx.x * 128;
    const int mbw = (wid & 3) * 32;
    const int nbw = (wid >> 2) * 64;
    const int lr = lane >> 2;
    const int lc = lane & 3;

    const int fr = tid >> 2, fc = tid & 3;

    const uint32_t* s0p[3] = { Af + (size_t)(m0 + fr) * ldau + fc * 4,
                               Bh + (size_t)(n0 + fr) * ldbu + fc * 4,
                               Bl + (size_t)(n0 + fr) * ldbu + fc * 4 };
    const int lds[3] = { ldau, ldbu, ldbu };
    const uint32_t dst0 = sb + (fr * P2 + fc * 4) * 4;

    float acc[2][8][4] = {};
    const int nchunks = K >> 5;

    #define ISSUE2(ch) do {                                                         \
        const uint32_t so_ = ((ch) & 1) * (STAGE2_U32 * 4);                         \
        const int ku_ = (ch) << 4;                                                  \
        _Pragma("unroll")                                                           \
        for (int a_ = 0; a_ < 3; a_++) {                                            \
            _Pragma("unroll")                                                       \
            for (int i_ = 0; i_ < 2; i_++)                                          \
                cp16(dst0 + so_ + (a_ * T2_U32 + i_ * 64 * P2) * 4,                 \
                     s0p[a_] + ku_ + (size_t)i_ * 64 * lds[a_]);                    \
        }                                                                           \
        cp_commit();                                                                \
    } while (0)

    ISSUE2(0);
    for (int ch = 0; ch < nchunks; ch++) {
        cp_wait<0>();
        __syncthreads();
        if (ch + 1 < nchunks) ISSUE2(ch + 1);

        const uint32_t stg = (ch & 1) * STAGE2_U32;
        const uint32_t* AFs = sm4 + stg;
        const uint32_t* BHs = sm4 + stg + T2_U32;
        const uint32_t* BLs = sm4 + stg + 2 * T2_U32;

        #pragma unroll
        for (int ks = 0; ks < 2; ks++) {
            uint32_t ah[2][4];
            #pragma unroll
            for (int t = 0; t < 2; t++) {
                int ba = (mbw + t * 16 + lr) * P2 + ks * 8 + 2 * lc;
                uint2 h0 = *(const uint2*)(AFs + ba);
                uint2 h8 = *(const uint2*)(AFs + ba + 8 * P2);
                ah[t][0] = h0.x; ah[t][1] = h8.x; ah[t][2] = h0.y; ah[t][3] = h8.y;
            }
            #pragma unroll
            for (int u = 0; u < 8; u++) {
                int rb = (nbw + u * 8 + lr) * P2 + ks * 8 + 2 * lc;
                uint2 bh = *(const uint2*)(BHs + rb);
                uint2 bl = *(const uint2*)(BLs + rb);
                #pragma unroll
                for (int t = 0; t < 2; t++) {
                    mma_f16(acc[t][u], ah[t], bh.x, bh.y);
                    mma_f16(acc[t][u], ah[t], bl.x, bl.y);
                }
            }
        }
    }

    #pragma unroll
    for (int t = 0; t < 2; t++) {
        int row = m0 + mbw + t * 16 + lr;
        #pragma unroll
        for (int u = 0; u < 8; u++) {
            int col = n0 + nbw + u * 8 + lc * 2;
            *(float2*)(C + (size_t)row * ldc + col) = make_float2(acc[t][u][0], acc[t][u][1]);
            *(float2*)(C + (size_t)(row + 8) * ldc + col) = make_float2(acc[t][u][2], acc[t][u][3]);
        }
    }
}

// ---------------- banded softmax mix -> pair-interleaved fp16 ----------------------------
__global__ void __launch_bounds__(256)
mix_kernel(const float* __restrict__ z, uint32_t* __restrict__ z2f) {
    __shared__ float zs[96][64];
    __shared__ float ws[2 * RWIN + 1];
    const int s0 = blockIdx.x * 64;
    const int c0 = blockIdx.y * 64;
    const int b  = blockIdx.z;
    const int tid = threadIdx.x;

    if (tid < 2 * RWIN + 1) ws[tid] = g_e[tid < RWIN ? RWIN - tid : tid - RWIN];

    #pragma unroll
    for (int i = 0; i < 24; i++) {
        int idx = tid + i * 256;
        int r = idx >> 6, c = idx & 63;
        int gs = s0 - 16 + r;
        float v = 0.f;
        if ((unsigned)gs < (unsigned)SS)
            v = z[((size_t)b * SS + gs) * CP + c0 + c];
        zs[r][c] = v;
    }
    __syncthreads();

    const int pr = tid & 31;
    const int sw = tid >> 5;
    const int P = (c0 >> 1) + pr;
    const int slot = (P & 0x78) + 2 * (P & 3) + ((P >> 2) & 1);

    #pragma unroll 2
    for (int it = 0; it < 8; it++) {
        int sl = sw + it * 8;
        int s = s0 + sl;
        float Z = 0.f, a0 = 0.f, a1 = 0.f;
        #pragma unroll
        for (int d = -RWIN; d <= RWIN; ++d) {
            int t = s - d;
            if ((unsigned)t < (unsigned)SS) {
                float w = ws[d + RWIN];
                Z += w;
                float2 v = *(const float2*)&zs[sl + 16 - d][2 * pr];
                a0 += w * v.x;
                a1 += w * v.y;
            }
        }
        float inv = 1.f / Z;
        size_t row = (size_t)b * SS + s;
        z2f[row * 128 + slot] = pack_f16x2(a0 * inv, a1 * inv);
    }
}

// ---------------- launch ------------------------------------------------------------------
extern "C" void kernel_launch(void* const* d_in, const int* in_sizes, int n_in,
                              void* d_out, int out_size) {
    const float* x      = (const float*)d_in[0];
    const float* v_low  = (const float*)d_in[5];   // [242, 768]
    const float* v_high = (const float*)d_in[6];   // [256, 242]
    const float* o_low  = (const float*)d_in[7];   // [242, 256]
    const float* o_high = (const float*)d_in[8];   // [768, 242]
    float* out = (float*)d_out;                    // [4, 4096, 768]

    float* z   = nullptr; cudaGetSymbolAddress((void**)&z,   g_z);
    float* T1t = nullptr; cudaGetSymbolAddress((void**)&T1t, g_T1t);
    float* WcT = nullptr; cudaGetSymbolAddress((void**)&WcT, g_WcT);
    uint32_t* vlh = nullptr; cudaGetSymbolAddress((void**)&vlh, g_vlh);
    uint32_t* vll = nullptr; cudaGetSymbolAddress((void**)&vll, g_vll);
    uint32_t* wch = nullptr; cudaGetSymbolAddress((void**)&wch, g_wch);
    uint32_t* wcl = nullptr; cudaGetSymbolAddress((void**)&wcl, g_wcl);
    uint32_t* z2f = nullptr; cudaGetSymbolAddress((void**)&z2f, g_z2f);

    cudaFuncSetAttribute(mma_gemm_abt, cudaFuncAttributeMaxDynamicSharedMemorySize, SM_BYTES);
    cudaFuncSetAttribute(mma_gemm_fb,  cudaFuncAttributeMaxDynamicSharedMemorySize, SM2_BYTES);
    cudaFuncSetAttribute(wk2, cudaFuncAttributeMaxDynamicSharedMemorySize, WSM_BYTES);
    cudaFuncSetAttribute(wk3, cudaFuncAttributeMaxDynamicSharedMemorySize, WSM_BYTES);

    // weight chain
    wk1<<<445, 256>>>(v_low, vlh, vll, T1t);
    wk2<<<224, 256, WSM_BYTES>>>(o_low, v_high, T1t, WcT);
    wk3<<<96, 256, WSM_BYTES>>>(o_high, T1t, WcT);
    wk4<<<384, 256>>>(WcT, wch, wcl);

    // gemm1: z = x @ v_low^T   [16384, 256]
    mma_gemm_abt<<<dim3(CP / 128, (BB * SS) / 128), 256, SM_BYTES>>>(
        x, HH, vlh, vll, HH / 2, z, CP, HH);

    // banded softmax mix -> pair-interleaved fp16 z2
    mix_kernel<<<dim3(SS / 64, CP / 64, BB), 256>>>(z, z2f);

    // gemm2: out = z2 @ WcT^T  [16384, 768]
    mma_gemm_fb<<<dim3(HH / 128, (BB * SS) / 128), 256, SM2_BYTES>>>(
        z2f, CP / 2, wch, wcl, CP / 2, out, HH, CP);

    (void)in_sizes; (void)n_in; (void)out_size;
}

// round 10
// speedup vs baseline: 1.6309x; 1.1795x over previous
#include <cuda_runtime.h>
#include <cuda_fp16.h>
#include <cstdint>
#include <cstddef>

// Problem constants
#define BB 4
#define SS 4096
#define HH 768
#define RR 242
#define HK 256
#define CP 256
#define RWIN 16
#define NFREQ 384

// ---------------- device scratch ---------------------------------------------------------
__device__ float g_z [(size_t)BB * SS * CP];
__device__ float g_T1t[RR * RR];
__device__ float g_WcT[HH * CP];            // cols 242..255 never written -> stay zero
__device__ float g_e[RWIN + 1];
// pair-interleaved fp16x2 tensors, stored as u32 (one k-pair per word)
__device__ __align__(16) uint32_t g_vlh[CP * HH / 2];
__device__ __align__(16) uint32_t g_wch[HH * CP / 2];
__device__ __align__(16) uint32_t g_z2f[(size_t)BB * SS * CP / 2];

// ---------------- fp16 helpers -----------------------------------------------------------
__device__ __forceinline__ uint32_t pack_f16x2(float e0, float e1) {
    uint32_t r;                      // low half = e0, high half = e1
    asm("cvt.rn.f16x2.f32 %0, %1, %2;" : "=r"(r) : "f"(e1), "f"(e0));
    return r;
}
__device__ __forceinline__ void mma_f16(float* d, const uint32_t* a, uint32_t b0, uint32_t b1) {
    asm volatile(
        "mma.sync.aligned.m16n8k16.row.col.f32.f16.f16.f32 "
        "{%0,%1,%2,%3}, {%4,%5,%6,%7}, {%8,%9}, {%0,%1,%2,%3};"
        : "+f"(d[0]), "+f"(d[1]), "+f"(d[2]), "+f"(d[3])
        : "r"(a[0]), "r"(a[1]), "r"(a[2]), "r"(a[3]), "r"(b0), "r"(b1));
}
__device__ __forceinline__ uint32_t smem_u32(const void* p) {
    uint32_t a;
    asm("{ .reg .u64 t; cvta.to.shared.u64 t, %1; cvt.u32.u64 %0, t; }" : "=r"(a) : "l"(p));
    return a;
}
__device__ __forceinline__ void cp16(uint32_t dst, const void* src) {
    asm volatile("cp.async.cg.shared.global [%0], [%1], 16;" :: "r"(dst), "l"(src));
}
__device__ __forceinline__ void cp_commit() {
    asm volatile("cp.async.commit_group;" ::: "memory");
}
template<int N> __device__ __forceinline__ void cp_wait() {
    asm volatile("cp.async.wait_group %0;" :: "n"(N) : "memory");
}

// ---------------- pair-interleave conversion (hi only) -----------------------------------
// slot j within an 8-slot (16-k) group holds pair p = (j>>1) + (j&1)*4.
__device__ __forceinline__ void conv_hi_idx(int idx, const float* __restrict__ src,
                                            int rows_src, int cols,
                                            uint32_t* __restrict__ hi) {
    int cols2 = cols >> 1;
    int row = idx / cols2;
    int s   = idx - row * cols2;
    int grp = s >> 3, j = s & 7;
    int k = (grp << 4) + (((j >> 1) + ((j & 1) << 2)) << 1);
    float e0 = 0.f, e1 = 0.f;
    if (row < rows_src) {
        e0 = src[(size_t)row * cols + k];
        e1 = src[(size_t)row * cols + k + 1];
    }
    hi[idx] = pack_f16x2(e0, e1);
}

// ---------------- exclusive-tile 64x64 small gemm (internal K loop, plain stores) --------
#define WSM_BYTES (2 * 128 * 68 * 4)
__device__ void gemm64_body(float* smem,
                            const float* __restrict__ A, int lda,
                            const float* __restrict__ B, int ldb,
                            float* __restrict__ C, int ldc,
                            int M, int N, int K, int m_t, int n_t) {
    float* As = smem;             // [128][68]  As[k][m]
    float* Bs = smem + 128 * 68;  // [128][68]  Bs[k][n]
    const int tid = threadIdx.x;
    const int m0 = m_t * 64, n0 = n_t * 64;
    const int ty = tid >> 4, tx = tid & 15;
    float acc[4][4] = {};
    for (int k0 = 0; k0 < K; k0 += 128) {
        const int kl = min(128, K - k0);
        #pragma unroll
        for (int i = 0; i < 32; i++) {
            int idx = tid + i * 256;
            int m = idx >> 7, k = idx & 127;
            float v = 0.f;
            if (k < kl && m0 + m < M) v = A[(size_t)(m0 + m) * lda + k0 + k];
            As[k * 68 + m] = v;
        }
        #pragma unroll
        for (int i = 0; i < 32; i++) {
            int idx = tid + i * 256;
            int k = idx >> 6, n = idx & 63;
            float v = 0.f;
            if (k < kl && n0 + n < N) v = B[(size_t)(k0 + k) * ldb + n0 + n];
            Bs[k * 68 + n] = v;
        }
        __syncthreads();
        for (int k = 0; k < kl; k++) {
            float4 a = *(const float4*)&As[k * 68 + ty * 4];
            float4 b = *(const float4*)&Bs[k * 68 + tx * 4];
            acc[0][0] += a.x * b.x; acc[0][1] += a.x * b.y; acc[0][2] += a.x * b.z; acc[0][3] += a.x * b.w;
            acc[1][0] += a.y * b.x; acc[1][1] += a.y * b.y; acc[1][2] += a.y * b.z; acc[1][3] += a.y * b.w;
            acc[2][0] += a.z * b.x; acc[2][1] += a.z * b.y; acc[2][2] += a.z * b.z; acc[2][3] += a.z * b.w;
            acc[3][0] += a.w * b.x; acc[3][1] += a.w * b.y; acc[3][2] += a.w * b.z; acc[3][3] += a.w * b.w;
        }
        __syncthreads();
    }
    #pragma unroll
    for (int i = 0; i < 4; i++) {
        int m = m0 + ty * 4 + i;
        if (m >= M) continue;
        #pragma unroll
        for (int j = 0; j < 4; j++) {
            int n = n0 + tx * 4 + j;
            if (n < N) C[(size_t)m * ldc + n] = acc[i][j];
        }
    }
}

// ---------------- W1: conv(v_low) + band-weight prep + T1t gemm --------------------------
// blocks [0,384): conv v_low;  [384,387): prep;  [387,403): T1t 64x64 tiles (4m x 4n)
__global__ void __launch_bounds__(256)
wk1(const float* __restrict__ v_low, uint32_t* __restrict__ vlh,
    const float* __restrict__ o_low, const float* __restrict__ v_high,
    float* __restrict__ T1t) {
    extern __shared__ float wsm[];
    const int bid = blockIdx.x, tid = threadIdx.x;
    if (bid < 384) {
        conv_hi_idx(bid * 256 + tid, v_low, RR, HH, vlh);
    } else if (bid < 387) {
        int w = (bid - 384) * 8 + (tid >> 5);
        int lane = tid & 31;
        if (w > RWIN) return;
        float d = (float)w, s = 0.f;
        for (int j = lane; j < NFREQ; j += 32) {
            float f = expf(-(float)j * (9.210340371976184f / (float)NFREQ));
            s += cosf(d * f);
        }
        #pragma unroll
        for (int o = 16; o > 0; o >>= 1) s += __shfl_down_sync(0xffffffffu, s, o);
        if (lane == 0) g_e[w] = expf(s - (float)NFREQ);
    } else {
        int tb = bid - 387;                  // 0..15
        gemm64_body(wsm, o_low, HK, v_high, RR, T1t, RR, RR, RR, HK, tb >> 2, tb & 3);
    }
}

// ---------------- W2: WcT gemm ------------------------------------------------------------
__global__ void __launch_bounds__(256)
wk2(const float* __restrict__ o_high, const float* __restrict__ T1t,
    float* __restrict__ WcT) {
    extern __shared__ float wsm[];
    const int cb = blockIdx.x;               // 48 blocks: 12m x 4n
    gemm64_body(wsm, o_high, RR, T1t, RR, WcT, CP, HH, RR, RR, cb >> 2, cb & 3);
}

// ---------------- W3: conv(WcT) -----------------------------------------------------------
__global__ void __launch_bounds__(256)
wk3(const float* __restrict__ WcT, uint32_t* __restrict__ wch) {
    conv_hi_idx(blockIdx.x * 256 + threadIdx.x, WcT, HH, CP, wch);
}

// ---------------- gemm1: C = round_f16(A_f32) @ B_f16^T (single-term) --------------------
// BM=BN=128, BK=32; 8 warps (4M x 2N), warp tile 32x64.
#define A_PITCH 40
#define B_PITCH 24
#define A_U32 (128 * A_PITCH)
#define B_U32 (128 * B_PITCH)
#define STAGE_U32 (A_U32 + B_U32)
#define SM_BYTES (2 * STAGE_U32 * 4)          // 65536 B

__global__ void __launch_bounds__(256, 2)
mma_gemm_abt(const float* __restrict__ A, int lda,
             const uint32_t* __restrict__ Bh, int ldbu,
             float* __restrict__ C, int ldc, int K) {
    extern __shared__ uint32_t sm4[];
    const uint32_t sb = smem_u32(sm4);
    const int tid  = threadIdx.x;
    const int wid  = tid >> 5;
    const int lane = tid & 31;
    const int m0 = blockIdx.y * 128;
    const int n0 = blockIdx.x * 128;
    const int mbw = (wid & 3) * 32;
    const int nbw = (wid >> 2) * 64;
    const int lr = lane >> 2;
    const int lc = lane & 3;

    const int ar = tid >> 3, ac = tid & 7;
    const int br = tid >> 2, bc = tid & 3;

    const float*    aSrc  = A  + (size_t)(m0 + ar) * lda + ac * 4;
    const uint32_t* bhSrc = Bh + (size_t)(n0 + br) * ldbu + bc * 4;
    const uint32_t aDst  = sb + (ar * A_PITCH + ac * 4) * 4;
    const uint32_t bhDst = sb + (A_U32 + br * B_PITCH + bc * 4) * 4;

    float acc[2][8][4] = {};
    const int nchunks = K >> 5;

    #define ISSUE(ch) do {                                                          \
        const uint32_t so_ = ((ch) & 1) * (STAGE_U32 * 4);                          \
        const int kf_ = (ch) << 5;                                                  \
        const int ku_ = (ch) << 4;                                                  \
        _Pragma("unroll")                                                           \
        for (int i_ = 0; i_ < 4; i_++)                                              \
            cp16(aDst + so_ + i_ * 32 * A_PITCH * 4,                                \
                 aSrc + kf_ + (size_t)i_ * 32 * lda);                               \
        _Pragma("unroll")                                                           \
        for (int i_ = 0; i_ < 2; i_++)                                              \
            cp16(bhDst + so_ + i_ * 64 * B_PITCH * 4,                               \
                 bhSrc + ku_ + (size_t)i_ * 64 * ldbu);                             \
        cp_commit();                                                                \
    } while (0)

    ISSUE(0);
    for (int ch = 0; ch < nchunks; ch++) {
        cp_wait<0>();
        __syncthreads();
        if (ch + 1 < nchunks) ISSUE(ch + 1);

        const uint32_t stg = (ch & 1) * STAGE_U32;
        const float* As = (const float*)(sm4 + stg);
        const uint32_t* BHs = sm4 + stg + A_U32;

        #pragma unroll
        for (int ks = 0; ks < 2; ks++) {
            uint32_t ah[2][4];
            #pragma unroll
            for (int t = 0; t < 2; t++) {
                const float* ap = As + (mbw + t * 16 + lr) * A_PITCH + ks * 16 + 2 * lc;
                float2 f0 = *(const float2*)(ap);
                float2 f1 = *(const float2*)(ap + 8 * A_PITCH);
                float2 f2 = *(const float2*)(ap + 8);
                float2 f3 = *(const float2*)(ap + 8 * A_PITCH + 8);
                ah[t][0] = pack_f16x2(f0.x, f0.y);
                ah[t][1] = pack_f16x2(f1.x, f1.y);
                ah[t][2] = pack_f16x2(f2.x, f2.y);
                ah[t][3] = pack_f16x2(f3.x, f3.y);
            }
            #pragma unroll
            for (int u = 0; u < 8; u++) {
                int rb = (nbw + u * 8 + lr) * B_PITCH + ks * 8 + 2 * lc;
                uint2 bh = *(const uint2*)(BHs + rb);
                #pragma unroll
                for (int t = 0; t < 2; t++)
                    mma_f16(acc[t][u], ah[t], bh.x, bh.y);
            }
        }
    }

    #pragma unroll
    for (int t = 0; t < 2; t++) {
        int row = m0 + mbw + t * 16 + lr;
        #pragma unroll
        for (int u = 0; u < 8; u++) {
            int col = n0 + nbw + u * 8 + lc * 2;
            *(float2*)(C + (size_t)row * ldc + col) = make_float2(acc[t][u][0], acc[t][u][1]);
            *(float2*)(C + (size_t)(row + 8) * ldc + col) = make_float2(acc[t][u][2], acc[t][u][3]);
        }
    }
}

// ---------------- gemm2: C = A_f16 @ B_f16^T (single-term) -------------------------------
#define P2 24
#define T2_U32 (128 * P2)
#define STAGE2_U32 (2 * T2_U32)               // AF, BH
#define SM2_BYTES (2 * STAGE2_U32 * 4)        // 49152 B

__global__ void __launch_bounds__(256, 2)
mma_gemm_fb(const uint32_t* __restrict__ Af, int ldau,
            const uint32_t* __restrict__ Bh, int ldbu,
            float* __restrict__ C, int ldc, int K) {
    extern __shared__ uint32_t sm4[];
    const uint32_t sb = smem_u32(sm4);
    const int tid  = threadIdx.x;
    const int wid  = tid >> 5;
    const int lane = tid & 31;
    const int m0 = blockIdx.y * 128;
    const int n0 = blockIdx.x * 128;
    const int mbw = (wid & 3) * 32;
    const int nbw = (wid >> 2) * 64;
    const int lr = lane >> 2;
    const int lc = lane & 3;

    const int fr = tid >> 2, fc = tid & 3;

    const uint32_t* aSrc = Af + (size_t)(m0 + fr) * ldau + fc * 4;
    const uint32_t* bSrc = Bh + (size_t)(n0 + fr) * ldbu + fc * 4;
    const uint32_t aDst = sb + (fr * P2 + fc * 4) * 4;
    const uint32_t bDst = sb + (T2_U32 + fr * P2 + fc * 4) * 4;

    float acc[2][8][4] = {};
    const int nchunks = K >> 5;

    #define ISSUE2(ch) do {                                                         \
        const uint32_t so_ = ((ch) & 1) * (STAGE2_U32 * 4);                         \
        const int ku_ = (ch) << 4;                                                  \
        _Pragma("unroll")                                                           \
        for (int i_ = 0; i_ < 2; i_++) {                                            \
            cp16(aDst + so_ + i_ * 64 * P2 * 4,                                     \
                 aSrc + ku_ + (size_t)i_ * 64 * ldau);                              \
            cp16(bDst + so_ + i_ * 64 * P2 * 4,                                     \
                 bSrc + ku_ + (size_t)i_ * 64 * ldbu);                              \
        }                                                                           \
        cp_commit();                                                                \
    } while (0)

    ISSUE2(0);
    for (int ch = 0; ch < nchunks; ch++) {
        cp_wait<0>();
        __syncthreads();
        if (ch + 1 < nchunks) ISSUE2(ch + 1);

        const uint32_t stg = (ch & 1) * STAGE2_U32;
        const uint32_t* AFs = sm4 + stg;
        const uint32_t* BHs = sm4 + stg + T2_U32;

        #pragma unroll
        for (int ks = 0; ks < 2; ks++) {
            uint32_t ah[2][4];
            #pragma unroll
            for (int t = 0; t < 2; t++) {
                int ba = (mbw + t * 16 + lr) * P2 + ks * 8 + 2 * lc;
                uint2 h0 = *(const uint2*)(AFs + ba);
                uint2 h8 = *(const uint2*)(AFs + ba + 8 * P2);
                ah[t][0] = h0.x; ah[t][1] = h8.x; ah[t][2] = h0.y; ah[t][3] = h8.y;
            }
            #pragma unroll
            for (int u = 0; u < 8; u++) {
                int rb = (nbw + u * 8 + lr) * P2 + ks * 8 + 2 * lc;
                uint2 bh = *(const uint2*)(BHs + rb);
                #pragma unroll
                for (int t = 0; t < 2; t++)
                    mma_f16(acc[t][u], ah[t], bh.x, bh.y);
            }
        }
    }

    #pragma unroll
    for (int t = 0; t < 2; t++) {
        int row = m0 + mbw + t * 16 + lr;
        #pragma unroll
        for (int u = 0; u < 8; u++) {
            int col = n0 + nbw + u * 8 + lc * 2;
            *(float2*)(C + (size_t)row * ldc + col) = make_float2(acc[t][u][0], acc[t][u][1]);
            *(float2*)(C + (size_t)(row + 8) * ldc + col) = make_float2(acc[t][u][2], acc[t][u][3]);
        }
    }
}

// ---------------- banded softmax mix -> pair-interleaved fp16 ----------------------------
__global__ void __launch_bounds__(256)
mix_kernel(const float* __restrict__ z, uint32_t* __restrict__ z2f) {
    __shared__ float zs[96][64];
    __shared__ float ws[2 * RWIN + 1];
    const int s0 = blockIdx.x * 64;
    const int c0 = blockIdx.y * 64;
    const int b  = blockIdx.z;
    const int tid = threadIdx.x;

    if (tid < 2 * RWIN + 1) ws[tid] = g_e[tid < RWIN ? RWIN - tid : tid - RWIN];

    #pragma unroll
    for (int i = 0; i < 24; i++) {
        int idx = tid + i * 256;
        int r = idx >> 6, c = idx & 63;
        int gs = s0 - 16 + r;
        float v = 0.f;
        if ((unsigned)gs < (unsigned)SS)
            v = z[((size_t)b * SS + gs) * CP + c0 + c];
        zs[r][c] = v;
    }
    __syncthreads();

    const int pr = tid & 31;
    const int sw = tid >> 5;
    const int P = (c0 >> 1) + pr;
    const int slot = (P & 0x78) + 2 * (P & 3) + ((P >> 2) & 1);

    #pragma unroll 2
    for (int it = 0; it < 8; it++) {
        int sl = sw + it * 8;
        int s = s0 + sl;
        float Z = 0.f, a0 = 0.f, a1 = 0.f;
        #pragma unroll
        for (int d = -RWIN; d <= RWIN; ++d) {
            int t = s - d;
            if ((unsigned)t < (unsigned)SS) {
                float w = ws[d + RWIN];
                Z += w;
                float2 v = *(const float2*)&zs[sl + 16 - d][2 * pr];
                a0 += w * v.x;
                a1 += w * v.y;
            }
        }
        float inv = 1.f / Z;
        size_t row = (size_t)b * SS + s;
        z2f[row * 128 + slot] = pack_f16x2(a0 * inv, a1 * inv);
    }
}

// ---------------- launch ------------------------------------------------------------------
extern "C" void kernel_launch(void* const* d_in, const int* in_sizes, int n_in,
                              void* d_out, int out_size) {
    const float* x      = (const float*)d_in[0];
    const float* v_low  = (const float*)d_in[5];   // [242, 768]
    const float* v_high = (const float*)d_in[6];   // [256, 242]
    const float* o_low  = (const float*)d_in[7];   // [242, 256]
    const float* o_high = (const float*)d_in[8];   // [768, 242]
    float* out = (float*)d_out;                    // [4, 4096, 768]

    float* z   = nullptr; cudaGetSymbolAddress((void**)&z,   g_z);
    float* T1t = nullptr; cudaGetSymbolAddress((void**)&T1t, g_T1t);
    float* WcT = nullptr; cudaGetSymbolAddress((void**)&WcT, g_WcT);
    uint32_t* vlh = nullptr; cudaGetSymbolAddress((void**)&vlh, g_vlh);
    uint32_t* wch = nullptr; cudaGetSymbolAddress((void**)&wch, g_wch);
    uint32_t* z2f = nullptr; cudaGetSymbolAddress((void**)&z2f, g_z2f);

    cudaFuncSetAttribute(mma_gemm_abt, cudaFuncAttributeMaxDynamicSharedMemorySize, SM_BYTES);
    cudaFuncSetAttribute(mma_gemm_fb,  cudaFuncAttributeMaxDynamicSharedMemorySize, SM2_BYTES);
    cudaFuncSetAttribute(wk1, cudaFuncAttributeMaxDynamicSharedMemorySize, WSM_BYTES);
    cudaFuncSetAttribute(wk2, cudaFuncAttributeMaxDynamicSharedMemorySize, WSM_BYTES);

    // weight chain (3 launches)
    wk1<<<403, 256, WSM_BYTES>>>(v_low, vlh, o_low, v_high, T1t);
    wk2<<<48, 256, WSM_BYTES>>>(o_high, T1t, WcT);
    wk3<<<384, 256>>>(WcT, wch);

    // gemm1: z = x @ v_low^T   [16384, 256]
    mma_gemm_abt<<<dim3(CP / 128, (BB * SS) / 128), 256, SM_BYTES>>>(
        x, HH, vlh, HH / 2, z, CP, HH);

    // banded softmax mix -> pair-interleaved fp16 z2
    mix_kernel<<<dim3(SS / 64, CP / 64, BB), 256>>>(z, z2f);

    // gemm2: out = z2 @ WcT^T  [16384, 768]
    mma_gemm_fb<<<dim3(HH / 128, (BB * SS) / 128), 256, SM2_BYTES>>>(
        z2f, CP / 2, wch, CP / 2, out, HH, CP);

    (void)in_sizes; (void)n_in; (void)out_size;
}

// round 11
// speedup vs baseline: 1.7281x; 1.0596x over previous
#include <cuda_runtime.h>
#include <cuda_fp16.h>
#include <cstdint>
#include <cstddef>

// Problem constants
#define BB 4
#define SS 4096
#define HH 768
#define RR 242
#define HK 256
#define CP 256
#define RWIN 16
#define NFREQ 384

// ---------------- device scratch ---------------------------------------------------------
__device__ float g_z [(size_t)BB * SS * CP];
__device__ float g_T1t[RR * RR];
__device__ float g_WcT[HH * CP];            // cols 242..255 never written -> stay zero
__device__ float g_e[RWIN + 1];
// pair-interleaved fp16x2 tensors, stored as u32 (one k-pair per word)
__device__ __align__(16) uint32_t g_vlh[CP * HH / 2];
__device__ __align__(16) uint32_t g_wch[HH * CP / 2];
__device__ __align__(16) uint32_t g_z2f[(size_t)BB * SS * CP / 2];

// ---------------- fp16 helpers -----------------------------------------------------------
__device__ __forceinline__ uint32_t pack_f16x2(float e0, float e1) {
    uint32_t r;                      // low half = e0, high half = e1
    asm("cvt.rn.f16x2.f32 %0, %1, %2;" : "=r"(r) : "f"(e1), "f"(e0));
    return r;
}
__device__ __forceinline__ void mma_f16(float* d, const uint32_t* a, uint32_t b0, uint32_t b1) {
    asm volatile(
        "mma.sync.aligned.m16n8k16.row.col.f32.f16.f16.f32 "
        "{%0,%1,%2,%3}, {%4,%5,%6,%7}, {%8,%9}, {%0,%1,%2,%3};"
        : "+f"(d[0]), "+f"(d[1]), "+f"(d[2]), "+f"(d[3])
        : "r"(a[0]), "r"(a[1]), "r"(a[2]), "r"(a[3]), "r"(b0), "r"(b1));
}
__device__ __forceinline__ uint32_t smem_u32(const void* p) {
    uint32_t a;
    asm("{ .reg .u64 t; cvta.to.shared.u64 t, %1; cvt.u32.u64 %0, t; }" : "=r"(a) : "l"(p));
    return a;
}
__device__ __forceinline__ void cp16(uint32_t dst, const void* src) {
    asm volatile("cp.async.cg.shared.global [%0], [%1], 16;" :: "r"(dst), "l"(src));
}
__device__ __forceinline__ void cp_commit() {
    asm volatile("cp.async.commit_group;" ::: "memory");
}
template<int N> __device__ __forceinline__ void cp_wait() {
    asm volatile("cp.async.wait_group %0;" :: "n"(N) : "memory");
}

// ---------------- pair-interleave conversion (hi only) -----------------------------------
// slot j within an 8-slot (16-k) group holds pair p = (j>>1) + (j&1)*4.
__device__ __forceinline__ void conv_hi_idx(int idx, const float* __restrict__ src,
                                            int rows_src, int cols,
                                            uint32_t* __restrict__ hi) {
    int cols2 = cols >> 1;
    int row = idx / cols2;
    int s   = idx - row * cols2;
    int grp = s >> 3, j = s & 7;
    int k = (grp << 4) + (((j >> 1) + ((j & 1) << 2)) << 1);
    float e0 = 0.f, e1 = 0.f;
    if (row < rows_src) {
        e0 = src[(size_t)row * cols + k];
        e1 = src[(size_t)row * cols + k + 1];
    }
    hi[idx] = pack_f16x2(e0, e1);
}

// ---------------- exclusive-tile 64x64 small gemm ----------------------------------------
#define WSM_BYTES (2 * 128 * 68 * 4)
__device__ void gemm64_body(float* smem,
                            const float* __restrict__ A, int lda,
                            const float* __restrict__ B, int ldb,
                            float* __restrict__ C, int ldc,
                            int M, int N, int K, int m_t, int n_t) {
    float* As = smem;             // [128][68]  As[k][m]
    float* Bs = smem + 128 * 68;  // [128][68]  Bs[k][n]
    const int tid = threadIdx.x;
    const int m0 = m_t * 64, n0 = n_t * 64;
    const int ty = tid >> 4, tx = tid & 15;
    float acc[4][4] = {};
    for (int k0 = 0; k0 < K; k0 += 128) {
        const int kl = min(128, K - k0);
        #pragma unroll
        for (int i = 0; i < 32; i++) {
            int idx = tid + i * 256;
            int m = idx >> 7, k = idx & 127;
            float v = 0.f;
            if (k < kl && m0 + m < M) v = A[(size_t)(m0 + m) * lda + k0 + k];
            As[k * 68 + m] = v;
        }
        #pragma unroll
        for (int i = 0; i < 32; i++) {
            int idx = tid + i * 256;
            int k = idx >> 6, n = idx & 63;
            float v = 0.f;
            if (k < kl && n0 + n < N) v = B[(size_t)(k0 + k) * ldb + n0 + n];
            Bs[k * 68 + n] = v;
        }
        __syncthreads();
        for (int k = 0; k < kl; k++) {
            float4 a = *(const float4*)&As[k * 68 + ty * 4];
            float4 b = *(const float4*)&Bs[k * 68 + tx * 4];
            acc[0][0] += a.x * b.x; acc[0][1] += a.x * b.y; acc[0][2] += a.x * b.z; acc[0][3] += a.x * b.w;
            acc[1][0] += a.y * b.x; acc[1][1] += a.y * b.y; acc[1][2] += a.y * b.z; acc[1][3] += a.y * b.w;
            acc[2][0] += a.z * b.x; acc[2][1] += a.z * b.y; acc[2][2] += a.z * b.z; acc[2][3] += a.z * b.w;
            acc[3][0] += a.w * b.x; acc[3][1] += a.w * b.y; acc[3][2] += a.w * b.z; acc[3][3] += a.w * b.w;
        }
        __syncthreads();
    }
    #pragma unroll
    for (int i = 0; i < 4; i++) {
        int m = m0 + ty * 4 + i;
        if (m >= M) continue;
        #pragma unroll
        for (int j = 0; j < 4; j++) {
            int n = n0 + tx * 4 + j;
            if (n < N) C[(size_t)m * ldc + n] = acc[i][j];
        }
    }
}

// ---------------- W1: conv(v_low) + band-weight prep + T1t gemm --------------------------
__global__ void __launch_bounds__(256)
wk1(const float* __restrict__ v_low, uint32_t* __restrict__ vlh,
    const float* __restrict__ o_low, const float* __restrict__ v_high,
    float* __restrict__ T1t) {
    extern __shared__ float wsm[];
    const int bid = blockIdx.x, tid = threadIdx.x;
    if (bid < 384) {
        conv_hi_idx(bid * 256 + tid, v_low, RR, HH, vlh);
    } else if (bid < 387) {
        int w = (bid - 384) * 8 + (tid >> 5);
        int lane = tid & 31;
        if (w > RWIN) return;
        float d = (float)w, s = 0.f;
        for (int j = lane; j < NFREQ; j += 32) {
            float f = expf(-(float)j * (9.210340371976184f / (float)NFREQ));
            s += cosf(d * f);
        }
        #pragma unroll
        for (int o = 16; o > 0; o >>= 1) s += __shfl_down_sync(0xffffffffu, s, o);
        if (lane == 0) g_e[w] = expf(s - (float)NFREQ);
    } else {
        int tb = bid - 387;
        gemm64_body(wsm, o_low, HK, v_high, RR, T1t, RR, RR, RR, HK, tb >> 2, tb & 3);
    }
}

// ---------------- W2: WcT gemm ------------------------------------------------------------
__global__ void __launch_bounds__(256)
wk2(const float* __restrict__ o_high, const float* __restrict__ T1t,
    float* __restrict__ WcT) {
    extern __shared__ float wsm[];
    const int cb = blockIdx.x;
    gemm64_body(wsm, o_high, RR, T1t, RR, WcT, CP, HH, RR, RR, cb >> 2, cb & 3);
}

// ---------------- W3: conv(WcT) -----------------------------------------------------------
__global__ void __launch_bounds__(256)
wk3(const float* __restrict__ WcT, uint32_t* __restrict__ wch) {
    conv_hi_idx(blockIdx.x * 256 + threadIdx.x, WcT, HH, CP, wch);
}

// ---------------- gemm1: C = round_f16(A_f32) @ B_f16^T, BK=64 ---------------------------
// BM=BN=128; 8 warps (4M x 2N), warp tile 32x64.
#define A_PITCH 72                      // floats; 72 mod 32 = 8 -> conflict-free frag loads
#define B_PITCH 40                      // u32;    40 mod 32 = 8
#define A_U32 (128 * A_PITCH)           // 9216 u32 = 36864 B
#define B_U32 (128 * B_PITCH)           // 5120 u32 = 20480 B
#define STAGE_U32 (A_U32 + B_U32)       // 14336 u32 = 57344 B
#define SM_BYTES (2 * STAGE_U32 * 4)    // 114688 B

__global__ void __launch_bounds__(256, 2)
mma_gemm_abt(const float* __restrict__ A, int lda,
             const uint32_t* __restrict__ Bh, int ldbu,
             float* __restrict__ C, int ldc, int K) {
    extern __shared__ uint32_t sm4[];
    const uint32_t sb = smem_u32(sm4);
    const int tid  = threadIdx.x;
    const int wid  = tid >> 5;
    const int lane = tid & 31;
    const int m0 = blockIdx.y * 128;
    const int n0 = blockIdx.x * 128;
    const int mbw = (wid & 3) * 32;
    const int nbw = (wid >> 2) * 64;
    const int lr = lane >> 2;
    const int lc = lane & 3;

    const int ar = tid >> 4, ac = tid & 15;   // A: rows ar+16i (i<8), 16B chunk ac
    const int br = tid >> 3, bc = tid & 7;    // B: rows br+32i (i<4), 16B chunk bc

    const float*    aSrc  = A  + (size_t)(m0 + ar) * lda + ac * 4;
    const uint32_t* bhSrc = Bh + (size_t)(n0 + br) * ldbu + bc * 4;
    const uint32_t aDst  = sb + (ar * A_PITCH + ac * 4) * 4;
    const uint32_t bhDst = sb + (A_U32 + br * B_PITCH + bc * 4) * 4;

    float acc[2][8][4] = {};
    const int nchunks = K >> 6;

    #define ISSUE(ch) do {                                                          \
        const uint32_t so_ = ((ch) & 1) * (STAGE_U32 * 4);                          \
        const int kf_ = (ch) << 6;                                                  \
        const int ku_ = (ch) << 5;                                                  \
        _Pragma("unroll")                                                           \
        for (int i_ = 0; i_ < 8; i_++)                                              \
            cp16(aDst + so_ + i_ * 16 * A_PITCH * 4,                                \
                 aSrc + kf_ + (size_t)i_ * 16 * lda);                               \
        _Pragma("unroll")                                                           \
        for (int i_ = 0; i_ < 4; i_++)                                              \
            cp16(bhDst + so_ + i_ * 32 * B_PITCH * 4,                               \
                 bhSrc + ku_ + (size_t)i_ * 32 * ldbu);                             \
        cp_commit();                                                                \
    } while (0)

    ISSUE(0);
    for (int ch = 0; ch < nchunks; ch++) {
        cp_wait<0>();
        __syncthreads();
        if (ch + 1 < nchunks) ISSUE(ch + 1);

        const uint32_t stg = (ch & 1) * STAGE_U32;
        const float* As = (const float*)(sm4 + stg);
        const uint32_t* BHs = sm4 + stg + A_U32;

        #pragma unroll
        for (int ks = 0; ks < 4; ks++) {
            uint32_t ah[2][4];
            #pragma unroll
            for (int t = 0; t < 2; t++) {
                const float* ap = As + (mbw + t * 16 + lr) * A_PITCH + ks * 16 + 2 * lc;
                float2 f0 = *(const float2*)(ap);
                float2 f1 = *(const float2*)(ap + 8 * A_PITCH);
                float2 f2 = *(const float2*)(ap + 8);
                float2 f3 = *(const float2*)(ap + 8 * A_PITCH + 8);
                ah[t][0] = pack_f16x2(f0.x, f0.y);
                ah[t][1] = pack_f16x2(f1.x, f1.y);
                ah[t][2] = pack_f16x2(f2.x, f2.y);
                ah[t][3] = pack_f16x2(f3.x, f3.y);
            }
            #pragma unroll
            for (int u = 0; u < 8; u++) {
                int rb = (nbw + u * 8 + lr) * B_PITCH + ks * 8 + 2 * lc;
                uint2 bh = *(const uint2*)(BHs + rb);
                #pragma unroll
                for (int t = 0; t < 2; t++)
                    mma_f16(acc[t][u], ah[t], bh.x, bh.y);
            }
        }
    }

    #pragma unroll
    for (int t = 0; t < 2; t++) {
        int row = m0 + mbw + t * 16 + lr;
        #pragma unroll
        for (int u = 0; u < 8; u++) {
            int col = n0 + nbw + u * 8 + lc * 2;
            *(float2*)(C + (size_t)row * ldc + col) = make_float2(acc[t][u][0], acc[t][u][1]);
            *(float2*)(C + (size_t)(row + 8) * ldc + col) = make_float2(acc[t][u][2], acc[t][u][3]);
        }
    }
}

// ---------------- gemm2: C = A_f16 @ B_f16^T, BK=64 --------------------------------------
#define P2 40                             // u32 pitch; 40 mod 32 = 8
#define T2_U32 (128 * P2)                 // 5120 u32 = 20480 B
#define STAGE2_U32 (2 * T2_U32)           // AF, BH = 40960 B
#define SM2_BYTES (2 * STAGE2_U32 * 4)    // 81920 B

__global__ void __launch_bounds__(256, 2)
mma_gemm_fb(const uint32_t* __restrict__ Af, int ldau,
            const uint32_t* __restrict__ Bh, int ldbu,
            float* __restrict__ C, int ldc, int K) {
    extern __shared__ uint32_t sm4[];
    const uint32_t sb = smem_u32(sm4);
    const int tid  = threadIdx.x;
    const int wid  = tid >> 5;
    const int lane = tid & 31;
    const int m0 = blockIdx.y * 128;
    const int n0 = blockIdx.x * 128;
    const int mbw = (wid & 3) * 32;
    const int nbw = (wid >> 2) * 64;
    const int lr = lane >> 2;
    const int lc = lane & 3;

    const int fr = tid >> 3, fc = tid & 7;   // rows fr+32i (i<4), 16B chunk fc

    const uint32_t* aSrc = Af + (size_t)(m0 + fr) * ldau + fc * 4;
    const uint32_t* bSrc = Bh + (size_t)(n0 + fr) * ldbu + fc * 4;
    const uint32_t aDst = sb + (fr * P2 + fc * 4) * 4;
    const uint32_t bDst = sb + (T2_U32 + fr * P2 + fc * 4) * 4;

    float acc[2][8][4] = {};
    const int nchunks = K >> 6;

    #define ISSUE2(ch) do {                                                         \
        const uint32_t so_ = ((ch) & 1) * (STAGE2_U32 * 4);                         \
        const int ku_ = (ch) << 5;                                                  \
        _Pragma("unroll")                                                           \
        for (int i_ = 0; i_ < 4; i_++) {                                            \
            cp16(aDst + so_ + i_ * 32 * P2 * 4,                                     \
                 aSrc + ku_ + (size_t)i_ * 32 * ldau);                              \
            cp16(bDst + so_ + i_ * 32 * P2 * 4,                                     \
                 bSrc + ku_ + (size_t)i_ * 32 * ldbu);                              \
        }                                                                           \
        cp_commit();                                                                \
    } while (0)

    ISSUE2(0);
    for (int ch = 0; ch < nchunks; ch++) {
        cp_wait<0>();
        __syncthreads();
        if (ch + 1 < nchunks) ISSUE2(ch + 1);

        const uint32_t stg = (ch & 1) * STAGE2_U32;
        const uint32_t* AFs = sm4 + stg;
        const uint32_t* BHs = sm4 + stg + T2_U32;

        #pragma unroll
        for (int ks = 0; ks < 4; ks++) {
            uint32_t ah[2][4];
            #pragma unroll
            for (int t = 0; t < 2; t++) {
                int ba = (mbw + t * 16 + lr) * P2 + ks * 8 + 2 * lc;
                uint2 h0 = *(const uint2*)(AFs + ba);
                uint2 h8 = *(const uint2*)(AFs + ba + 8 * P2);
                ah[t][0] = h0.x; ah[t][1] = h8.x; ah[t][2] = h0.y; ah[t][3] = h8.y;
            }
            #pragma unroll
            for (int u = 0; u < 8; u++) {
                int rb = (nbw + u * 8 + lr) * P2 + ks * 8 + 2 * lc;
                uint2 bh = *(const uint2*)(BHs + rb);
                #pragma unroll
                for (int t = 0; t < 2; t++)
                    mma_f16(acc[t][u], ah[t], bh.x, bh.y);
            }
        }
    }

    #pragma unroll
    for (int t = 0; t < 2; t++) {
        int row = m0 + mbw + t * 16 + lr;
        #pragma unroll
        for (int u = 0; u < 8; u++) {
            int col = n0 + nbw + u * 8 + lc * 2;
            *(float2*)(C + (size_t)row * ldc + col) = make_float2(acc[t][u][0], acc[t][u][1]);
            *(float2*)(C + (size_t)(row + 8) * ldc + col) = make_float2(acc[t][u][2], acc[t][u][3]);
        }
    }
}

// ---------------- banded softmax mix -> pair-interleaved fp16 ----------------------------
__global__ void __launch_bounds__(256)
mix_kernel(const float* __restrict__ z, uint32_t* __restrict__ z2f) {
    __shared__ float zs[96][64];
    __shared__ float ws[2 * RWIN + 1];
    const int s0 = blockIdx.x * 64;
    const int c0 = blockIdx.y * 64;
    const int b  = blockIdx.z;
    const int tid = threadIdx.x;

    if (tid < 2 * RWIN + 1) ws[tid] = g_e[tid < RWIN ? RWIN - tid : tid - RWIN];

    #pragma unroll
    for (int i = 0; i < 24; i++) {
        int idx = tid + i * 256;
        int r = idx >> 6, c = idx & 63;
        int gs = s0 - 16 + r;
        float v = 0.f;
        if ((unsigned)gs < (unsigned)SS)
            v = z[((size_t)b * SS + gs) * CP + c0 + c];
        zs[r][c] = v;
    }
    __syncthreads();

    const int pr = tid & 31;
    const int sw = tid >> 5;
    const int P = (c0 >> 1) + pr;
    const int slot = (P & 0x78) + 2 * (P & 3) + ((P >> 2) & 1);

    #pragma unroll 2
    for (int it = 0; it < 8; it++) {
        int sl = sw + it * 8;
        int s = s0 + sl;
        float Z = 0.f, a0 = 0.f, a1 = 0.f;
        #pragma unroll
        for (int d = -RWIN; d <= RWIN; ++d) {
            int t = s - d;
            if ((unsigned)t < (unsigned)SS) {
                float w = ws[d + RWIN];
                Z += w;
                float2 v = *(const float2*)&zs[sl + 16 - d][2 * pr];
                a0 += w * v.x;
                a1 += w * v.y;
            }
        }
        float inv = 1.f / Z;
        size_t row = (size_t)b * SS + s;
        z2f[row * 128 + slot] = pack_f16x2(a0 * inv, a1 * inv);
    }
}

// ---------------- launch ------------------------------------------------------------------
extern "C" void kernel_launch(void* const* d_in, const int* in_sizes, int n_in,
                              void* d_out, int out_size) {
    const float* x      = (const float*)d_in[0];
    const float* v_low  = (const float*)d_in[5];   // [242, 768]
    const float* v_high = (const float*)d_in[6];   // [256, 242]
    const float* o_low  = (const float*)d_in[7];   // [242, 256]
    const float* o_high = (const float*)d_in[8];   // [768, 242]
    float* out = (float*)d_out;                    // [4, 4096, 768]

    float* z   = nullptr; cudaGetSymbolAddress((void**)&z,   g_z);
    float* T1t = nullptr; cudaGetSymbolAddress((void**)&T1t, g_T1t);
    float* WcT = nullptr; cudaGetSymbolAddress((void**)&WcT, g_WcT);
    uint32_t* vlh = nullptr; cudaGetSymbolAddress((void**)&vlh, g_vlh);
    uint32_t* wch = nullptr; cudaGetSymbolAddress((void**)&wch, g_wch);
    uint32_t* z2f = nullptr; cudaGetSymbolAddress((void**)&z2f, g_z2f);

    cudaFuncSetAttribute(mma_gemm_abt, cudaFuncAttributeMaxDynamicSharedMemorySize, SM_BYTES);
    cudaFuncSetAttribute(mma_gemm_fb,  cudaFuncAttributeMaxDynamicSharedMemorySize, SM2_BYTES);
    cudaFuncSetAttribute(wk1, cudaFuncAttributeMaxDynamicSharedMemorySize, WSM_BYTES);
    cudaFuncSetAttribute(wk2, cudaFuncAttributeMaxDynamicSharedMemorySize, WSM_BYTES);

    // weight chain (3 launches)
    wk1<<<403, 256, WSM_BYTES>>>(v_low, vlh, o_low, v_high, T1t);
    wk2<<<48, 256, WSM_BYTES>>>(o_high, T1t, WcT);
    wk3<<<384, 256>>>(WcT, wch);

    // gemm1: z = x @ v_low^T   [16384, 256]
    mma_gemm_abt<<<dim3(CP / 128, (BB * SS) / 128), 256, SM_BYTES>>>(
        x, HH, vlh, HH / 2, z, CP, HH);

    // banded softmax mix -> pair-interleaved fp16 z2
    mix_kernel<<<dim3(SS / 64, CP / 64, BB), 256>>>(z, z2f);

    // gemm2: out = z2 @ WcT^T  [16384, 768]
    mma_gemm_fb<<<dim3(HH / 128, (BB * SS) / 128), 256, SM2_BYTES>>>(
        z2f, CP / 2, wch, CP / 2, out, HH, CP);

    (void)in_sizes; (void)n_in; (void)out_size;
}

// round 12
// speedup vs baseline: 1.7392x; 1.0064x over previous
#include <cuda_runtime.h>
#include <cuda_fp16.h>
#include <cstdint>
#include <cstddef>

// Problem constants
#define BB 4
#define SS 4096
#define HH 768
#define RR 242
#define HK 256
#define CP 256
#define RWIN 16
#define NFREQ 384

// ---------------- device scratch ---------------------------------------------------------
__device__ float g_T1t[RR * RR];
__device__ float g_e[RWIN + 1];
// pair-interleaved fp16x2 tensors, stored as u32 (one k/channel-pair per word)
__device__ __align__(16) uint32_t g_vlh[CP * HH / 2];
__device__ __align__(16) uint32_t g_wch[HH * CP / 2];
__device__ __align__(16) uint32_t g_zf [(size_t)BB * SS * CP / 2];   // gemm1 out (slot space)
__device__ __align__(16) uint32_t g_z2f[(size_t)BB * SS * CP / 2];   // mixed (slot space)

// ---------------- fp16 helpers -----------------------------------------------------------
__device__ __forceinline__ uint32_t pack_f16x2(float e0, float e1) {
    uint32_t r;                      // low half = e0, high half = e1
    asm("cvt.rn.f16x2.f32 %0, %1, %2;" : "=r"(r) : "f"(e1), "f"(e0));
    return r;
}
__device__ __forceinline__ void mma_f16(float* d, const uint32_t* a, uint32_t b0, uint32_t b1) {
    asm volatile(
        "mma.sync.aligned.m16n8k16.row.col.f32.f16.f16.f32 "
        "{%0,%1,%2,%3}, {%4,%5,%6,%7}, {%8,%9}, {%0,%1,%2,%3};"
        : "+f"(d[0]), "+f"(d[1]), "+f"(d[2]), "+f"(d[3])
        : "r"(a[0]), "r"(a[1]), "r"(a[2]), "r"(a[3]), "r"(b0), "r"(b1));
}
__device__ __forceinline__ uint32_t smem_u32(const void* p) {
    uint32_t a;
    asm("{ .reg .u64 t; cvta.to.shared.u64 t, %1; cvt.u32.u64 %0, t; }" : "=r"(a) : "l"(p));
    return a;
}
__device__ __forceinline__ void cp16(uint32_t dst, const void* src) {
    asm volatile("cp.async.cg.shared.global [%0], [%1], 16;" :: "r"(dst), "l"(src));
}
__device__ __forceinline__ void cp_commit() {
    asm volatile("cp.async.commit_group;" ::: "memory");
}
template<int N> __device__ __forceinline__ void cp_wait() {
    asm volatile("cp.async.wait_group %0;" :: "n"(N) : "memory");
}
// slot of channel/k pair P within its 128-slot row (matches mma b/a-frag k pattern)
__device__ __forceinline__ int pair_slot(int P) {
    return (P & 0x78) + 2 * (P & 3) + ((P >> 2) & 1);
}

// ---------------- pair-interleave conversion (hi only) -----------------------------------
__device__ __forceinline__ void conv_hi_idx(int idx, const float* __restrict__ src,
                                            int rows_src, int cols,
                                            uint32_t* __restrict__ hi) {
    int cols2 = cols >> 1;
    int row = idx / cols2;
    int s   = idx - row * cols2;
    int grp = s >> 3, j = s & 7;
    int k = (grp << 4) + (((j >> 1) + ((j & 1) << 2)) << 1);
    float e0 = 0.f, e1 = 0.f;
    if (row < rows_src) {
        e0 = src[(size_t)row * cols + k];
        e1 = src[(size_t)row * cols + k + 1];
    }
    hi[idx] = pack_f16x2(e0, e1);
}

// ---------------- 64x64 small gemm core (K loop in smem) ---------------------------------
// PACKED=false: writes C fp32 [M x N] (bounds-checked).
// PACKED=true : writes Cpk as pair-interleaved fp16 u32, full 64-col tile (acc is 0 beyond N).
#define WSM_BYTES (2 * 128 * 68 * 4)
template<bool PACKED>
__device__ void gemm64_body(float* smem,
                            const float* __restrict__ A, int lda,
                            const float* __restrict__ B, int ldb,
                            float* __restrict__ C, uint32_t* __restrict__ Cpk, int ldc,
                            int M, int N, int K, int m_t, int n_t) {
    float* As = smem;             // [128][68]  As[k][m]
    float* Bs = smem + 128 * 68;  // [128][68]  Bs[k][n]
    const int tid = threadIdx.x;
    const int m0 = m_t * 64, n0 = n_t * 64;
    const int ty = tid >> 4, tx = tid & 15;
    float acc[4][4] = {};
    for (int k0 = 0; k0 < K; k0 += 128) {
        const int kl = min(128, K - k0);
        #pragma unroll
        for (int i = 0; i < 32; i++) {
            int idx = tid + i * 256;
            int m = idx >> 7, k = idx & 127;
            float v = 0.f;
            if (k < kl && m0 + m < M) v = A[(size_t)(m0 + m) * lda + k0 + k];
            As[k * 68 + m] = v;
        }
        #pragma unroll
        for (int i = 0; i < 32; i++) {
            int idx = tid + i * 256;
            int k = idx >> 6, n = idx & 63;
            float v = 0.f;
            if (k < kl && n0 + n < N) v = B[(size_t)(k0 + k) * ldb + n0 + n];
            Bs[k * 68 + n] = v;
        }
        __syncthreads();
        for (int k = 0; k < kl; k++) {
            float4 a = *(const float4*)&As[k * 68 + ty * 4];
            float4 b = *(const float4*)&Bs[k * 68 + tx * 4];
            acc[0][0] += a.x * b.x; acc[0][1] += a.x * b.y; acc[0][2] += a.x * b.z; acc[0][3] += a.x * b.w;
            acc[1][0] += a.y * b.x; acc[1][1] += a.y * b.y; acc[1][2] += a.y * b.z; acc[1][3] += a.y * b.w;
            acc[2][0] += a.z * b.x; acc[2][1] += a.z * b.y; acc[2][2] += a.z * b.z; acc[2][3] += a.z * b.w;
            acc[3][0] += a.w * b.x; acc[3][1] += a.w * b.y; acc[3][2] += a.w * b.z; acc[3][3] += a.w * b.w;
        }
        __syncthreads();
    }
    #pragma unroll
    for (int i = 0; i < 4; i++) {
        int m = m0 + ty * 4 + i;
        if (m >= M) continue;
        if (PACKED) {
            #pragma unroll
            for (int j = 0; j < 4; j += 2) {
                int n = n0 + tx * 4 + j;              // even
                int slot = pair_slot(n >> 1);
                Cpk[(size_t)m * (ldc >> 1) + slot] = pack_f16x2(acc[i][j], acc[i][j + 1]);
            }
        } else {
            #pragma unroll
            for (int j = 0; j < 4; j++) {
                int n = n0 + tx * 4 + j;
                if (n < N) C[(size_t)m * ldc + n] = acc[i][j];
            }
        }
    }
}

// ---------------- W1: conv(v_low) + band-weight prep + T1t gemm --------------------------
__global__ void __launch_bounds__(256)
wk1(const float* __restrict__ v_low, uint32_t* __restrict__ vlh,
    const float* __restrict__ o_low, const float* __restrict__ v_high,
    float* __restrict__ T1t) {
    extern __shared__ float wsm[];
    const int bid = blockIdx.x, tid = threadIdx.x;
    if (bid < 384) {
        conv_hi_idx(bid * 256 + tid, v_low, RR, HH, vlh);
    } else if (bid < 387) {
        int w = (bid - 384) * 8 + (tid >> 5);
        int lane = tid & 31;
        if (w > RWIN) return;
        float d = (float)w, s = 0.f;
        for (int j = lane; j < NFREQ; j += 32) {
            float f = expf(-(float)j * (9.210340371976184f / (float)NFREQ));
            s += cosf(d * f);
        }
        #pragma unroll
        for (int o = 16; o > 0; o >>= 1) s += __shfl_down_sync(0xffffffffu, s, o);
        if (lane == 0) g_e[w] = expf(s - (float)NFREQ);
    } else {
        int tb = bid - 387;
        gemm64_body<false>(wsm, o_low, HK, v_high, RR, T1t, nullptr, RR,
                           RR, RR, HK, tb >> 2, tb & 3);
    }
}

// ---------------- W2: WcT gemm, fused fp16 pair-interleave (wk3 eliminated) --------------
__global__ void __launch_bounds__(256)
wk2(const float* __restrict__ o_high, const float* __restrict__ T1t,
    uint32_t* __restrict__ wch) {
    extern __shared__ float wsm[];
    const int cb = blockIdx.x;               // 48 blocks: 12m x 4n
    gemm64_body<true>(wsm, o_high, RR, T1t, RR, nullptr, wch, CP,
                      HH, RR, RR, cb >> 2, cb & 3);
}

// ---------------- gemm1: zf = round_f16(x @ v_low^T), slot-interleaved out ---------------
// BM=BN=128, BK=64; 8 warps (4M x 2N), warp tile 32x64.
#define A_PITCH 72
#define B_PITCH 40
#define A_U32 (128 * A_PITCH)
#define B_U32 (128 * B_PITCH)
#define STAGE_U32 (A_U32 + B_U32)
#define SM_BYTES (2 * STAGE_U32 * 4)    // 114688 B

__global__ void __launch_bounds__(256, 2)
mma_gemm_abt(const float* __restrict__ A, int lda,
             const uint32_t* __restrict__ Bh, int ldbu,
             uint32_t* __restrict__ Cpk, int K) {
    extern __shared__ uint32_t sm4[];
    const uint32_t sb = smem_u32(sm4);
    const int tid  = threadIdx.x;
    const int wid  = tid >> 5;
    const int lane = tid & 31;
    const int m0 = blockIdx.y * 128;
    const int n0 = blockIdx.x * 128;
    const int mbw = (wid & 3) * 32;
    const int nbw = (wid >> 2) * 64;
    const int lr = lane >> 2;
    const int lc = lane & 3;

    const int ar = tid >> 4, ac = tid & 15;
    const int br = tid >> 3, bc = tid & 7;

    const float*    aSrc  = A  + (size_t)(m0 + ar) * lda + ac * 4;
    const uint32_t* bhSrc = Bh + (size_t)(n0 + br) * ldbu + bc * 4;
    const uint32_t aDst  = sb + (ar * A_PITCH + ac * 4) * 4;
    const uint32_t bhDst = sb + (A_U32 + br * B_PITCH + bc * 4) * 4;

    float acc[2][8][4] = {};
    const int nchunks = K >> 6;

    #define ISSUE(ch) do {                                                          \
        const uint32_t so_ = ((ch) & 1) * (STAGE_U32 * 4);                          \
        const int kf_ = (ch) << 6;                                                  \
        const int ku_ = (ch) << 5;                                                  \
        _Pragma("unroll")                                                           \
        for (int i_ = 0; i_ < 8; i_++)                                              \
            cp16(aDst + so_ + i_ * 16 * A_PITCH * 4,                                \
                 aSrc + kf_ + (size_t)i_ * 16 * lda);                               \
        _Pragma("unroll")                                                           \
        for (int i_ = 0; i_ < 4; i_++)                                              \
            cp16(bhDst + so_ + i_ * 32 * B_PITCH * 4,                               \
                 bhSrc + ku_ + (size_t)i_ * 32 * ldbu);                             \
        cp_commit();                                                                \
    } while (0)

    ISSUE(0);
    for (int ch = 0; ch < nchunks; ch++) {
        cp_wait<0>();
        __syncthreads();
        if (ch + 1 < nchunks) ISSUE(ch + 1);

        const uint32_t stg = (ch & 1) * STAGE_U32;
        const float* As = (const float*)(sm4 + stg);
        const uint32_t* BHs = sm4 + stg + A_U32;

        #pragma unroll
        for (int ks = 0; ks < 4; ks++) {
            uint32_t ah[2][4];
            #pragma unroll
            for (int t = 0; t < 2; t++) {
                const float* ap = As + (mbw + t * 16 + lr) * A_PITCH + ks * 16 + 2 * lc;
                float2 f0 = *(const float2*)(ap);
                float2 f1 = *(const float2*)(ap + 8 * A_PITCH);
                float2 f2 = *(const float2*)(ap + 8);
                float2 f3 = *(const float2*)(ap + 8 * A_PITCH + 8);
                ah[t][0] = pack_f16x2(f0.x, f0.y);
                ah[t][1] = pack_f16x2(f1.x, f1.y);
                ah[t][2] = pack_f16x2(f2.x, f2.y);
                ah[t][3] = pack_f16x2(f3.x, f3.y);
            }
            #pragma unroll
            for (int u = 0; u < 8; u++) {
                int rb = (nbw + u * 8 + lr) * B_PITCH + ks * 8 + 2 * lc;
                uint2 bh = *(const uint2*)(BHs + rb);
                #pragma unroll
                for (int t = 0; t < 2; t++)
                    mma_f16(acc[t][u], ah[t], bh.x, bh.y);
            }
        }
    }

    // epilogue: pack channel pairs to fp16 and write in slot-interleaved layout
    #pragma unroll
    for (int t = 0; t < 2; t++) {
        int row = m0 + mbw + t * 16 + lr;
        #pragma unroll
        for (int u = 0; u < 8; u++) {
            int col = n0 + nbw + u * 8 + lc * 2;       // even
            int slot = pair_slot(col >> 1);
            Cpk[(size_t)row * 128 + slot]       = pack_f16x2(acc[t][u][0], acc[t][u][1]);
            Cpk[(size_t)(row + 8) * 128 + slot] = pack_f16x2(acc[t][u][2], acc[t][u][3]);
        }
    }
}

// ---------------- gemm2: out = z2_f16 @ Wc_f16^T (fp32 out), BK=64 -----------------------
#define P2 40
#define T2_U32 (128 * P2)
#define STAGE2_U32 (2 * T2_U32)
#define SM2_BYTES (2 * STAGE2_U32 * 4)    // 81920 B

__global__ void __launch_bounds__(256, 2)
mma_gemm_fb(const uint32_t* __restrict__ Af, int ldau,
            const uint32_t* __restrict__ Bh, int ldbu,
            float* __restrict__ C, int ldc, int K) {
    extern __shared__ uint32_t sm4[];
    const uint32_t sb = smem_u32(sm4);
    const int tid  = threadIdx.x;
    const int wid  = tid >> 5;
    const int lane = tid & 31;
    const int m0 = blockIdx.y * 128;
    const int n0 = blockIdx.x * 128;
    const int mbw = (wid & 3) * 32;
    const int nbw = (wid >> 2) * 64;
    const int lr = lane >> 2;
    const int lc = lane & 3;

    const int fr = tid >> 3, fc = tid & 7;

    const uint32_t* aSrc = Af + (size_t)(m0 + fr) * ldau + fc * 4;
    const uint32_t* bSrc = Bh + (size_t)(n0 + fr) * ldbu + fc * 4;
    const uint32_t aDst = sb + (fr * P2 + fc * 4) * 4;
    const uint32_t bDst = sb + (T2_U32 + fr * P2 + fc * 4) * 4;

    float acc[2][8][4] = {};
    const int nchunks = K >> 6;

    #define ISSUE2(ch) do {                                                         \
        const uint32_t so_ = ((ch) & 1) * (STAGE2_U32 * 4);                         \
        const int ku_ = (ch) << 5;                                                  \
        _Pragma("unroll")                                                           \
        for (int i_ = 0; i_ < 4; i_++) {                                            \
            cp16(aDst + so_ + i_ * 32 * P2 * 4,                                     \
                 aSrc + ku_ + (size_t)i_ * 32 * ldau);                              \
            cp16(bDst + so_ + i_ * 32 * P2 * 4,                                     \
                 bSrc + ku_ + (size_t)i_ * 32 * ldbu);                              \
        }                                                                           \
        cp_commit();                                                                \
    } while (0)

    ISSUE2(0);
    for (int ch = 0; ch < nchunks; ch++) {
        cp_wait<0>();
        __syncthreads();
        if (ch + 1 < nchunks) ISSUE2(ch + 1);

        const uint32_t stg = (ch & 1) * STAGE2_U32;
        const uint32_t* AFs = sm4 + stg;
        const uint32_t* BHs = sm4 + stg + T2_U32;

        #pragma unroll
        for (int ks = 0; ks < 4; ks++) {
            uint32_t ah[2][4];
            #pragma unroll
            for (int t = 0; t < 2; t++) {
                int ba = (mbw + t * 16 + lr) * P2 + ks * 8 + 2 * lc;
                uint2 h0 = *(const uint2*)(AFs + ba);
                uint2 h8 = *(const uint2*)(AFs + ba + 8 * P2);
                ah[t][0] = h0.x; ah[t][1] = h8.x; ah[t][2] = h0.y; ah[t][3] = h8.y;
            }
            #pragma unroll
            for (int u = 0; u < 8; u++) {
                int rb = (nbw + u * 8 + lr) * P2 + ks * 8 + 2 * lc;
                uint2 bh = *(const uint2*)(BHs + rb);
                #pragma unroll
                for (int t = 0; t < 2; t++)
                    mma_f16(acc[t][u], ah[t], bh.x, bh.y);
            }
        }
    }

    #pragma unroll
    for (int t = 0; t < 2; t++) {
        int row = m0 + mbw + t * 16 + lr;
        #pragma unroll
        for (int u = 0; u < 8; u++) {
            int col = n0 + nbw + u * 8 + lc * 2;
            *(float2*)(C + (size_t)row * ldc + col) = make_float2(acc[t][u][0], acc[t][u][1]);
            *(float2*)(C + (size_t)(row + 8) * ldc + col) = make_float2(acc[t][u][2], acc[t][u][3]);
        }
    }
}

// ---------------- banded softmax mix, fp16 slot-space in/out -----------------------------
// Block: 64 s-positions x 32 slots (= 64 channels). smem fp32 for exact inner loop.
__global__ void __launch_bounds__(256)
mix_kernel(const uint32_t* __restrict__ zf, uint32_t* __restrict__ z2f) {
    __shared__ float zs[96][64];
    __shared__ float ws[2 * RWIN + 1];
    const int s0 = blockIdx.x * 64;
    const int sl0 = blockIdx.y * 32;          // slot base
    const int b  = blockIdx.z;
    const int tid = threadIdx.x;

    if (tid < 2 * RWIN + 1) ws[tid] = g_e[tid < RWIN ? RWIN - tid : tid - RWIN];

    #pragma unroll
    for (int i = 0; i < 12; i++) {
        int idx = tid + i * 256;
        int r = idx >> 5, j = idx & 31;
        int gs = s0 - 16 + r;
        uint32_t v = 0;
        if ((unsigned)gs < (unsigned)SS)
            v = zf[((size_t)b * SS + gs) * 128 + sl0 + j];
        __half2 h = *reinterpret_cast<__half2*>(&v);
        float2 f = __half22float2(h);
        zs[r][2 * j]     = f.x;
        zs[r][2 * j + 1] = f.y;
    }
    __syncthreads();

    const int pr = tid & 31;          // slot within tile
    const int sw = tid >> 5;

    #pragma unroll 2
    for (int it = 0; it < 8; it++) {
        int sl = sw + it * 8;
        int s = s0 + sl;
        float Z = 0.f, a0 = 0.f, a1 = 0.f;
        #pragma unroll
        for (int d = -RWIN; d <= RWIN; ++d) {
            int t = s - d;
            if ((unsigned)t < (unsigned)SS) {
                float w = ws[d + RWIN];
                Z += w;
                float2 v = *(const float2*)&zs[sl + 16 - d][2 * pr];
                a0 += w * v.x;
                a1 += w * v.y;
            }
        }
        float inv = 1.f / Z;
        z2f[((size_t)b * SS + s) * 128 + sl0 + pr] = pack_f16x2(a0 * inv, a1 * inv);
    }
}

// ---------------- launch ------------------------------------------------------------------
extern "C" void kernel_launch(void* const* d_in, const int* in_sizes, int n_in,
                              void* d_out, int out_size) {
    const float* x      = (const float*)d_in[0];
    const float* v_low  = (const float*)d_in[5];   // [242, 768]
    const float* v_high = (const float*)d_in[6];   // [256, 242]
    const float* o_low  = (const float*)d_in[7];   // [242, 256]
    const float* o_high = (const float*)d_in[8];   // [768, 242]
    float* out = (float*)d_out;                    // [4, 4096, 768]

    float* T1t = nullptr; cudaGetSymbolAddress((void**)&T1t, g_T1t);
    uint32_t* vlh = nullptr; cudaGetSymbolAddress((void**)&vlh, g_vlh);
    uint32_t* wch = nullptr; cudaGetSymbolAddress((void**)&wch, g_wch);
    uint32_t* zf  = nullptr; cudaGetSymbolAddress((void**)&zf,  g_zf);
    uint32_t* z2f = nullptr; cudaGetSymbolAddress((void**)&z2f, g_z2f);

    cudaFuncSetAttribute(mma_gemm_abt, cudaFuncAttributeMaxDynamicSharedMemorySize, SM_BYTES);
    cudaFuncSetAttribute(mma_gemm_fb,  cudaFuncAttributeMaxDynamicSharedMemorySize, SM2_BYTES);
    cudaFuncSetAttribute(wk1, cudaFuncAttributeMaxDynamicSharedMemorySize, WSM_BYTES);
    cudaFuncSetAttribute(wk2, cudaFuncAttributeMaxDynamicSharedMemorySize, WSM_BYTES);

    // weight chain (2 launches; wch conversion fused into wk2)
    wk1<<<403, 256, WSM_BYTES>>>(v_low, vlh, o_low, v_high, T1t);
    wk2<<<48, 256, WSM_BYTES>>>(o_high, T1t, wch);

    // gemm1: zf = x @ v_low^T   [16384, 256] -> fp16 slot-interleaved
    mma_gemm_abt<<<dim3(CP / 128, (BB * SS) / 128), 256, SM_BYTES>>>(
        x, HH, vlh, HH / 2, zf, HH);

    // banded softmax mix (fp16 slot space)
    mix_kernel<<<dim3(SS / 64, 4, BB), 256>>>(zf, z2f);

    // gemm2: out = z2 @ WcT^T  [16384, 768]
    mma_gemm_fb<<<dim3(HH / 128, (BB * SS) / 128), 256, SM2_BYTES>>>(
        z2f, CP / 2, wch, CP / 2, out, HH, CP);

    (void)in_sizes; (void)n_in; (void)out_size;
}

// round 13
// speedup vs baseline: 1.8335x; 1.0542x over previous
#include <cuda_runtime.h>
#include <cuda_fp16.h>
#include <cstdint>
#include <cstddef>

// Problem constants
#define BB 4
#define SS 4096
#define HH 768
#define RR 242
#define HK 256
#define CP 256
#define RWIN 16
#define NFREQ 384

// ---------------- device scratch ---------------------------------------------------------
__device__ float g_T1t[RR * RR];
__device__ float g_e[RWIN + 1];
// pair-interleaved fp16x2 tensors, stored as u32 (one k/channel-pair per word)
__device__ __align__(16) uint32_t g_vlh[CP * HH / 2];
__device__ __align__(16) uint32_t g_wch[HH * CP / 2];
__device__ __align__(16) uint32_t g_zf [(size_t)BB * SS * CP / 2];   // gemm1 out (slot space)
__device__ __align__(16) uint32_t g_z2f[(size_t)BB * SS * CP / 2];   // mixed (slot space)

// ---------------- fp16 helpers -----------------------------------------------------------
__device__ __forceinline__ uint32_t pack_f16x2(float e0, float e1) {
    uint32_t r;                      // low half = e0, high half = e1
    asm("cvt.rn.f16x2.f32 %0, %1, %2;" : "=r"(r) : "f"(e1), "f"(e0));
    return r;
}
__device__ __forceinline__ void mma_f16(float* d, const uint32_t* a, uint32_t b0, uint32_t b1) {
    asm volatile(
        "mma.sync.aligned.m16n8k16.row.col.f32.f16.f16.f32 "
        "{%0,%1,%2,%3}, {%4,%5,%6,%7}, {%8,%9}, {%0,%1,%2,%3};"
        : "+f"(d[0]), "+f"(d[1]), "+f"(d[2]), "+f"(d[3])
        : "r"(a[0]), "r"(a[1]), "r"(a[2]), "r"(a[3]), "r"(b0), "r"(b1));
}
__device__ __forceinline__ uint32_t smem_u32(const void* p) {
    uint32_t a;
    asm("{ .reg .u64 t; cvta.to.shared.u64 t, %1; cvt.u32.u64 %0, t; }" : "=r"(a) : "l"(p));
    return a;
}
__device__ __forceinline__ void cp16(uint32_t dst, const void* src) {
    asm volatile("cp.async.cg.shared.global [%0], [%1], 16;" :: "r"(dst), "l"(src));
}
__device__ __forceinline__ void cp_commit() {
    asm volatile("cp.async.commit_group;" ::: "memory");
}
template<int N> __device__ __forceinline__ void cp_wait() {
    asm volatile("cp.async.wait_group %0;" :: "n"(N) : "memory");
}
// slot of channel/k pair P within its 128-slot row (matches mma b/a-frag k pattern)
__device__ __forceinline__ int pair_slot(int P) {
    return (P & 0x78) + 2 * (P & 3) + ((P >> 2) & 1);
}

// ---------------- pair-interleave conversion (hi only) -----------------------------------
__device__ __forceinline__ void conv_hi_idx(int idx, const float* __restrict__ src,
                                            int rows_src, int cols,
                                            uint32_t* __restrict__ hi) {
    int cols2 = cols >> 1;
    int row = idx / cols2;
    int s   = idx - row * cols2;
    int grp = s >> 3, j = s & 7;
    int k = (grp << 4) + (((j >> 1) + ((j & 1) << 2)) << 1);
    float e0 = 0.f, e1 = 0.f;
    if (row < rows_src) {
        e0 = src[(size_t)row * cols + k];
        e1 = src[(size_t)row * cols + k + 1];
    }
    hi[idx] = pack_f16x2(e0, e1);
}

// ---------------- 64x64 small gemm core (K loop in smem) ---------------------------------
#define WSM_BYTES (2 * 128 * 68 * 4)
template<bool PACKED>
__device__ void gemm64_body(float* smem,
                            const float* __restrict__ A, int lda,
                            const float* __restrict__ B, int ldb,
                            float* __restrict__ C, uint32_t* __restrict__ Cpk, int ldc,
                            int M, int N, int K, int m_t, int n_t) {
    float* As = smem;             // [128][68]  As[k][m]
    float* Bs = smem + 128 * 68;  // [128][68]  Bs[k][n]
    const int tid = threadIdx.x;
    const int m0 = m_t * 64, n0 = n_t * 64;
    const int ty = tid >> 4, tx = tid & 15;
    float acc[4][4] = {};
    for (int k0 = 0; k0 < K; k0 += 128) {
        const int kl = min(128, K - k0);
        #pragma unroll
        for (int i = 0; i < 32; i++) {
            int idx = tid + i * 256;
            int m = idx >> 7, k = idx & 127;
            float v = 0.f;
            if (k < kl && m0 + m < M) v = A[(size_t)(m0 + m) * lda + k0 + k];
            As[k * 68 + m] = v;
        }
        #pragma unroll
        for (int i = 0; i < 32; i++) {
            int idx = tid + i * 256;
            int k = idx >> 6, n = idx & 63;
            float v = 0.f;
            if (k < kl && n0 + n < N) v = B[(size_t)(k0 + k) * ldb + n0 + n];
            Bs[k * 68 + n] = v;
        }
        __syncthreads();
        for (int k = 0; k < kl; k++) {
            float4 a = *(const float4*)&As[k * 68 + ty * 4];
            float4 b = *(const float4*)&Bs[k * 68 + tx * 4];
            acc[0][0] += a.x * b.x; acc[0][1] += a.x * b.y; acc[0][2] += a.x * b.z; acc[0][3] += a.x * b.w;
            acc[1][0] += a.y * b.x; acc[1][1] += a.y * b.y; acc[1][2] += a.y * b.z; acc[1][3] += a.y * b.w;
            acc[2][0] += a.z * b.x; acc[2][1] += a.z * b.y; acc[2][2] += a.z * b.z; acc[2][3] += a.z * b.w;
            acc[3][0] += a.w * b.x; acc[3][1] += a.w * b.y; acc[3][2] += a.w * b.z; acc[3][3] += a.w * b.w;
        }
        __syncthreads();
    }
    #pragma unroll
    for (int i = 0; i < 4; i++) {
        int m = m0 + ty * 4 + i;
        if (m >= M) continue;
        if (PACKED) {
            #pragma unroll
            for (int j = 0; j < 4; j += 2) {
                int n = n0 + tx * 4 + j;              // even
                int slot = pair_slot(n >> 1);
                Cpk[(size_t)m * (ldc >> 1) + slot] = pack_f16x2(acc[i][j], acc[i][j + 1]);
            }
        } else {
            #pragma unroll
            for (int j = 0; j < 4; j++) {
                int n = n0 + tx * 4 + j;
                if (n < N) C[(size_t)m * ldc + n] = acc[i][j];
            }
        }
    }
}

// ---------------- W1: conv(v_low) + band-weight prep + T1t gemm --------------------------
__global__ void __launch_bounds__(256)
wk1(const float* __restrict__ v_low, uint32_t* __restrict__ vlh,
    const float* __restrict__ o_low, const float* __restrict__ v_high,
    float* __restrict__ T1t) {
    extern __shared__ float wsm[];
    const int bid = blockIdx.x, tid = threadIdx.x;
    if (bid < 384) {
        conv_hi_idx(bid * 256 + tid, v_low, RR, HH, vlh);
    } else if (bid < 387) {
        int w = (bid - 384) * 8 + (tid >> 5);
        int lane = tid & 31;
        if (w > RWIN) return;
        float d = (float)w, s = 0.f;
        for (int j = lane; j < NFREQ; j += 32) {
            float f = expf(-(float)j * (9.210340371976184f / (float)NFREQ));
            s += cosf(d * f);
        }
        #pragma unroll
        for (int o = 16; o > 0; o >>= 1) s += __shfl_down_sync(0xffffffffu, s, o);
        if (lane == 0) g_e[w] = expf(s - (float)NFREQ);
    } else {
        int tb = bid - 387;
        gemm64_body<false>(wsm, o_low, HK, v_high, RR, T1t, nullptr, RR,
                           RR, RR, HK, tb >> 2, tb & 3);
    }
}

// ---------------- W2: WcT gemm, fused fp16 pair-interleave -------------------------------
__global__ void __launch_bounds__(256)
wk2(const float* __restrict__ o_high, const float* __restrict__ T1t,
    uint32_t* __restrict__ wch) {
    extern __shared__ float wsm[];
    const int cb = blockIdx.x;               // 48 blocks: 12m x 4n
    gemm64_body<true>(wsm, o_high, RR, T1t, RR, nullptr, wch, CP,
                      HH, RR, RR, cb >> 2, cb & 3);
}

// ---------------- gemm1: zf = round_f16(x @ v_low^T), slot-interleaved out ---------------
#define A_PITCH 72
#define B_PITCH 40
#define A_U32 (128 * A_PITCH)
#define B_U32 (128 * B_PITCH)
#define STAGE_U32 (A_U32 + B_U32)
#define SM_BYTES (2 * STAGE_U32 * 4)    // 114688 B

__global__ void __launch_bounds__(256, 2)
mma_gemm_abt(const float* __restrict__ A, int lda,
             const uint32_t* __restrict__ Bh, int ldbu,
             uint32_t* __restrict__ Cpk, int K) {
    extern __shared__ uint32_t sm4[];
    const uint32_t sb = smem_u32(sm4);
    const int tid  = threadIdx.x;
    const int wid  = tid >> 5;
    const int lane = tid & 31;
    const int m0 = blockIdx.y * 128;
    const int n0 = blockIdx.x * 128;
    const int mbw = (wid & 3) * 32;
    const int nbw = (wid >> 2) * 64;
    const int lr = lane >> 2;
    const int lc = lane & 3;

    const int ar = tid >> 4, ac = tid & 15;
    const int br = tid >> 3, bc = tid & 7;

    const float*    aSrc  = A  + (size_t)(m0 + ar) * lda + ac * 4;
    const uint32_t* bhSrc = Bh + (size_t)(n0 + br) * ldbu + bc * 4;
    const uint32_t aDst  = sb + (ar * A_PITCH + ac * 4) * 4;
    const uint32_t bhDst = sb + (A_U32 + br * B_PITCH + bc * 4) * 4;

    float acc[2][8][4] = {};
    const int nchunks = K >> 6;

    #define ISSUE(ch) do {                                                          \
        const uint32_t so_ = ((ch) & 1) * (STAGE_U32 * 4);                          \
        const int kf_ = (ch) << 6;                                                  \
        const int ku_ = (ch) << 5;                                                  \
        _Pragma("unroll")                                                           \
        for (int i_ = 0; i_ < 8; i_++)                                              \
            cp16(aDst + so_ + i_ * 16 * A_PITCH * 4,                                \
                 aSrc + kf_ + (size_t)i_ * 16 * lda);                               \
        _Pragma("unroll")                                                           \
        for (int i_ = 0; i_ < 4; i_++)                                              \
            cp16(bhDst + so_ + i_ * 32 * B_PITCH * 4,                               \
                 bhSrc + ku_ + (size_t)i_ * 32 * ldbu);                             \
        cp_commit();                                                                \
    } while (0)

    ISSUE(0);
    for (int ch = 0; ch < nchunks; ch++) {
        cp_wait<0>();
        __syncthreads();
        if (ch + 1 < nchunks) ISSUE(ch + 1);

        const uint32_t stg = (ch & 1) * STAGE_U32;
        const float* As = (const float*)(sm4 + stg);
        const uint32_t* BHs = sm4 + stg + A_U32;

        #pragma unroll
        for (int ks = 0; ks < 4; ks++) {
            uint32_t ah[2][4];
            #pragma unroll
            for (int t = 0; t < 2; t++) {
                const float* ap = As + (mbw + t * 16 + lr) * A_PITCH + ks * 16 + 2 * lc;
                float2 f0 = *(const float2*)(ap);
                float2 f1 = *(const float2*)(ap + 8 * A_PITCH);
                float2 f2 = *(const float2*)(ap + 8);
                float2 f3 = *(const float2*)(ap + 8 * A_PITCH + 8);
                ah[t][0] = pack_f16x2(f0.x, f0.y);
                ah[t][1] = pack_f16x2(f1.x, f1.y);
                ah[t][2] = pack_f16x2(f2.x, f2.y);
                ah[t][3] = pack_f16x2(f3.x, f3.y);
            }
            #pragma unroll
            for (int u = 0; u < 8; u++) {
                int rb = (nbw + u * 8 + lr) * B_PITCH + ks * 8 + 2 * lc;
                uint2 bh = *(const uint2*)(BHs + rb);
                #pragma unroll
                for (int t = 0; t < 2; t++)
                    mma_f16(acc[t][u], ah[t], bh.x, bh.y);
            }
        }
    }

    #pragma unroll
    for (int t = 0; t < 2; t++) {
        int row = m0 + mbw + t * 16 + lr;
        #pragma unroll
        for (int u = 0; u < 8; u++) {
            int col = n0 + nbw + u * 8 + lc * 2;       // even
            int slot = pair_slot(col >> 1);
            Cpk[(size_t)row * 128 + slot]       = pack_f16x2(acc[t][u][0], acc[t][u][1]);
            Cpk[(size_t)(row + 8) * 128 + slot] = pack_f16x2(acc[t][u][2], acc[t][u][3]);
        }
    }
}

// ---------------- gemm2: out = z2_f16 @ Wc_f16^T (fp32 out), BK=64 -----------------------
#define P2 40
#define T2_U32 (128 * P2)
#define STAGE2_U32 (2 * T2_U32)
#define SM2_BYTES (2 * STAGE2_U32 * 4)    // 81920 B

__global__ void __launch_bounds__(256, 2)
mma_gemm_fb(const uint32_t* __restrict__ Af, int ldau,
            const uint32_t* __restrict__ Bh, int ldbu,
            float* __restrict__ C, int ldc, int K) {
    extern __shared__ uint32_t sm4[];
    const uint32_t sb = smem_u32(sm4);
    const int tid  = threadIdx.x;
    const int wid  = tid >> 5;
    const int lane = tid & 31;
    const int m0 = blockIdx.y * 128;
    const int n0 = blockIdx.x * 128;
    const int mbw = (wid & 3) * 32;
    const int nbw = (wid >> 2) * 64;
    const int lr = lane >> 2;
    const int lc = lane & 3;

    const int fr = tid >> 3, fc = tid & 7;

    const uint32_t* aSrc = Af + (size_t)(m0 + fr) * ldau + fc * 4;
    const uint32_t* bSrc = Bh + (size_t)(n0 + fr) * ldbu + fc * 4;
    const uint32_t aDst = sb + (fr * P2 + fc * 4) * 4;
    const uint32_t bDst = sb + (T2_U32 + fr * P2 + fc * 4) * 4;

    float acc[2][8][4] = {};
    const int nchunks = K >> 6;

    #define ISSUE2(ch) do {                                                         \
        const uint32_t so_ = ((ch) & 1) * (STAGE2_U32 * 4);                         \
        const int ku_ = (ch) << 5;                                                  \
        _Pragma("unroll")                                                           \
        for (int i_ = 0; i_ < 4; i_++) {                                            \
            cp16(aDst + so_ + i_ * 32 * P2 * 4,                                     \
                 aSrc + ku_ + (size_t)i_ * 32 * ldau);                              \
            cp16(bDst + so_ + i_ * 32 * P2 * 4,                                     \
                 bSrc + ku_ + (size_t)i_ * 32 * ldbu);                              \
        }                                                                           \
        cp_commit();                                                                \
    } while (0)

    ISSUE2(0);
    for (int ch = 0; ch < nchunks; ch++) {
        cp_wait<0>();
        __syncthreads();
        if (ch + 1 < nchunks) ISSUE2(ch + 1);

        const uint32_t stg = (ch & 1) * STAGE2_U32;
        const uint32_t* AFs = sm4 + stg;
        const uint32_t* BHs = sm4 + stg + T2_U32;

        #pragma unroll
        for (int ks = 0; ks < 4; ks++) {
            uint32_t ah[2][4];
            #pragma unroll
            for (int t = 0; t < 2; t++) {
                int ba = (mbw + t * 16 + lr) * P2 + ks * 8 + 2 * lc;
                uint2 h0 = *(const uint2*)(AFs + ba);
                uint2 h8 = *(const uint2*)(AFs + ba + 8 * P2);
                ah[t][0] = h0.x; ah[t][1] = h8.x; ah[t][2] = h0.y; ah[t][3] = h8.y;
            }
            #pragma unroll
            for (int u = 0; u < 8; u++) {
                int rb = (nbw + u * 8 + lr) * P2 + ks * 8 + 2 * lc;
                uint2 bh = *(const uint2*)(BHs + rb);
                #pragma unroll
                for (int t = 0; t < 2; t++)
                    mma_f16(acc[t][u], ah[t], bh.x, bh.y);
            }
        }
    }

    #pragma unroll
    for (int t = 0; t < 2; t++) {
        int row = m0 + mbw + t * 16 + lr;
        #pragma unroll
        for (int u = 0; u < 8; u++) {
            int col = n0 + nbw + u * 8 + lc * 2;
            *(float2*)(C + (size_t)row * ldc + col) = make_float2(acc[t][u][0], acc[t][u][1]);
            *(float2*)(C + (size_t)(row + 8) * ldc + col) = make_float2(acc[t][u][2], acc[t][u][3]);
        }
    }
}

// ---------------- banded softmax mix, fp16 slot-space, interior fast path ----------------
// Block: 64 s-positions x 32 slots. Interior blocks (all but bx=0,63): pre-normalized
// weights, no bounds checks, packed f32x2 FFMA. Boundary blocks: scalar path with Z.
__global__ void __launch_bounds__(256)
mix_kernel(const uint32_t* __restrict__ zf, uint32_t* __restrict__ z2f) {
    __shared__ float2 zs[96][32];
    __shared__ float ws[2 * RWIN + 1];
    __shared__ __align__(8) float2 wn2[2 * RWIN + 1];   // normalized, duplicated halves
    const int s0 = blockIdx.x * 64;
    const int sl0 = blockIdx.y * 32;
    const int b  = blockIdx.z;
    const int tid = threadIdx.x;

    if (tid < 2 * RWIN + 1) {
        float w = g_e[tid < RWIN ? RWIN - tid : tid - RWIN];
        ws[tid] = w;
        float Z = g_e[0];
        #pragma unroll
        for (int d = 1; d <= RWIN; d++) Z += 2.f * g_e[d];
        float wn = w / Z;
        wn2[tid] = make_float2(wn, wn);
    }

    #pragma unroll
    for (int i = 0; i < 12; i++) {
        int idx = tid + i * 256;
        int r = idx >> 5, j = idx & 31;
        int gs = s0 - 16 + r;
        uint32_t v = 0;
        if ((unsigned)gs < (unsigned)SS)
            v = zf[((size_t)b * SS + gs) * 128 + sl0 + j];
        __half2 h = *reinterpret_cast<__half2*>(&v);
        zs[r][j] = __half22float2(h);
    }
    __syncthreads();

    const int pr = tid & 31;
    const int sw = tid >> 5;
    const bool interior = (s0 >= RWIN) && (s0 + 64 + RWIN <= SS);

    if (interior) {
        for (int it = 0; it < 8; it++) {
            int sl = sw + it * 8;
            unsigned long long acc = 0ull;   // packed (0.f, 0.f)
            #pragma unroll
            for (int dd = 0; dd <= 2 * RWIN; dd++) {
                unsigned long long v = *(const unsigned long long*)&zs[sl + 32 - dd][pr];
                unsigned long long w = *(const unsigned long long*)&wn2[dd];
                asm("fma.rn.f32x2 %0, %1, %2, %0;" : "+l"(acc) : "l"(v), "l"(w));
            }
            float a0 = __uint_as_float((uint32_t)acc);
            float a1 = __uint_as_float((uint32_t)(acc >> 32));
            z2f[((size_t)b * SS + s0 + sl) * 128 + sl0 + pr] = pack_f16x2(a0, a1);
        }
    } else {
        for (int it = 0; it < 8; it++) {
            int sl = sw + it * 8;
            int s = s0 + sl;
            float Z = 0.f, a0 = 0.f, a1 = 0.f;
            #pragma unroll
            for (int d = -RWIN; d <= RWIN; ++d) {
                int t = s - d;
                if ((unsigned)t < (unsigned)SS) {
                    float w = ws[d + RWIN];
                    Z += w;
                    float2 v = zs[sl + 16 - d][pr];
                    a0 += w * v.x;
                    a1 += w * v.y;
                }
            }
            float inv = 1.f / Z;
            z2f[((size_t)b * SS + s) * 128 + sl0 + pr] = pack_f16x2(a0 * inv, a1 * inv);
        }
    }
}

// ---------------- launch ------------------------------------------------------------------
extern "C" void kernel_launch(void* const* d_in, const int* in_sizes, int n_in,
                              void* d_out, int out_size) {
    const float* x      = (const float*)d_in[0];
    const float* v_low  = (const float*)d_in[5];   // [242, 768]
    const float* v_high = (const float*)d_in[6];   // [256, 242]
    const float* o_low  = (const float*)d_in[7];   // [242, 256]
    const float* o_high = (const float*)d_in[8];   // [768, 242]
    float* out = (float*)d_out;                    // [4, 4096, 768]

    float* T1t = nullptr; cudaGetSymbolAddress((void**)&T1t, g_T1t);
    uint32_t* vlh = nullptr; cudaGetSymbolAddress((void**)&vlh, g_vlh);
    uint32_t* wch = nullptr; cudaGetSymbolAddress((void**)&wch, g_wch);
    uint32_t* zf  = nullptr; cudaGetSymbolAddress((void**)&zf,  g_zf);
    uint32_t* z2f = nullptr; cudaGetSymbolAddress((void**)&z2f, g_z2f);

    cudaFuncSetAttribute(mma_gemm_abt, cudaFuncAttributeMaxDynamicSharedMemorySize, SM_BYTES);
    cudaFuncSetAttribute(mma_gemm_fb,  cudaFuncAttributeMaxDynamicSharedMemorySize, SM2_BYTES);
    cudaFuncSetAttribute(wk1, cudaFuncAttributeMaxDynamicSharedMemorySize, WSM_BYTES);
    cudaFuncSetAttribute(wk2, cudaFuncAttributeMaxDynamicSharedMemorySize, WSM_BYTES);

    // weight chain (2 launches)
    wk1<<<403, 256, WSM_BYTES>>>(v_low, vlh, o_low, v_high, T1t);
    wk2<<<48, 256, WSM_BYTES>>>(o_high, T1t, wch);

    // gemm1: zf = x @ v_low^T   [16384, 256] -> fp16 slot-interleaved
    mma_gemm_abt<<<dim3(CP / 128, (BB * SS) / 128), 256, SM_BYTES>>>(
        x, HH, vlh, HH / 2, zf, HH);

    // banded softmax mix (fp16 slot space)
    mix_kernel<<<dim3(SS / 64, 4, BB), 256>>>(zf, z2f);

    // gemm2: out = z2 @ WcT^T  [16384, 768]
    mma_gemm_fb<<<dim3(HH / 128, (BB * SS) / 128), 256, SM2_BYTES>>>(
        z2f, CP / 2, wch, CP / 2, out, HH, CP);

    (void)in_sizes; (void)n_in; (void)out_size;
}

// round 14
// speedup vs baseline: 1.9757x; 1.0776x over previous
#include <cuda_runtime.h>
#include <cuda_fp16.h>
#include <cstdint>
#include <cstddef>

// Problem constants
#define BB 4
#define SS 4096
#define HH 768
#define RR 242
#define HK 256
#define CP 256
#define RWIN 16      // g_e table size (prep computes 0..16)
#define MIXW 8       // mix window half-width: e(d)=0 in fp32 for d>=8
#define NFREQ 384

// ---------------- device scratch ---------------------------------------------------------
__device__ float g_T1t[RR * RR];
__device__ float g_e[RWIN + 1];
// pair-interleaved fp16x2 tensors, stored as u32 (one k/channel-pair per word)
__device__ __align__(16) uint32_t g_vlh[CP * HH / 2];
__device__ __align__(16) uint32_t g_wch[HH * CP / 2];
__device__ __align__(16) uint32_t g_zf [(size_t)BB * SS * CP / 2];   // gemm1 out (slot space)
__device__ __align__(16) uint32_t g_z2f[(size_t)BB * SS * CP / 2];   // mixed (slot space)

// ---------------- fp16 helpers -----------------------------------------------------------
__device__ __forceinline__ uint32_t pack_f16x2(float e0, float e1) {
    uint32_t r;                      // low half = e0, high half = e1
    asm("cvt.rn.f16x2.f32 %0, %1, %2;" : "=r"(r) : "f"(e1), "f"(e0));
    return r;
}
__device__ __forceinline__ void mma_f16(float* d, const uint32_t* a, uint32_t b0, uint32_t b1) {
    asm volatile(
        "mma.sync.aligned.m16n8k16.row.col.f32.f16.f16.f32 "
        "{%0,%1,%2,%3}, {%4,%5,%6,%7}, {%8,%9}, {%0,%1,%2,%3};"
        : "+f"(d[0]), "+f"(d[1]), "+f"(d[2]), "+f"(d[3])
        : "r"(a[0]), "r"(a[1]), "r"(a[2]), "r"(a[3]), "r"(b0), "r"(b1));
}
__device__ __forceinline__ uint32_t smem_u32(const void* p) {
    uint32_t a;
    asm("{ .reg .u64 t; cvta.to.shared.u64 t, %1; cvt.u32.u64 %0, t; }" : "=r"(a) : "l"(p));
    return a;
}
__device__ __forceinline__ void cp16(uint32_t dst, const void* src) {
    asm volatile("cp.async.cg.shared.global [%0], [%1], 16;" :: "r"(dst), "l"(src));
}
__device__ __forceinline__ void cp_commit() {
    asm volatile("cp.async.commit_group;" ::: "memory");
}
template<int N> __device__ __forceinline__ void cp_wait() {
    asm volatile("cp.async.wait_group %0;" :: "n"(N) : "memory");
}
// slot of channel/k pair P within its 128-slot row (matches mma b/a-frag k pattern)
__device__ __forceinline__ int pair_slot(int P) {
    return (P & 0x78) + 2 * (P & 3) + ((P >> 2) & 1);
}

// ---------------- pair-interleave conversion (hi only) -----------------------------------
__device__ __forceinline__ void conv_hi_idx(int idx, const float* __restrict__ src,
                                            int rows_src, int cols,
                                            uint32_t* __restrict__ hi) {
    int cols2 = cols >> 1;
    int row = idx / cols2;
    int s   = idx - row * cols2;
    int grp = s >> 3, j = s & 7;
    int k = (grp << 4) + (((j >> 1) + ((j & 1) << 2)) << 1);
    float e0 = 0.f, e1 = 0.f;
    if (row < rows_src) {
        e0 = src[(size_t)row * cols + k];
        e1 = src[(size_t)row * cols + k + 1];
    }
    hi[idx] = pack_f16x2(e0, e1);
}

// ---------------- 64x64 small gemm core (K loop in smem) ---------------------------------
#define WSM_BYTES (2 * 128 * 68 * 4)
template<bool PACKED>
__device__ void gemm64_body(float* smem,
                            const float* __restrict__ A, int lda,
                            const float* __restrict__ B, int ldb,
                            float* __restrict__ C, uint32_t* __restrict__ Cpk, int ldc,
                            int M, int N, int K, int m_t, int n_t) {
    float* As = smem;             // [128][68]  As[k][m]
    float* Bs = smem + 128 * 68;  // [128][68]  Bs[k][n]
    const int tid = threadIdx.x;
    const int m0 = m_t * 64, n0 = n_t * 64;
    const int ty = tid >> 4, tx = tid & 15;
    float acc[4][4] = {};
    for (int k0 = 0; k0 < K; k0 += 128) {
        const int kl = min(128, K - k0);
        #pragma unroll
        for (int i = 0; i < 32; i++) {
            int idx = tid + i * 256;
            int m = idx >> 7, k = idx & 127;
            float v = 0.f;
            if (k < kl && m0 + m < M) v = A[(size_t)(m0 + m) * lda + k0 + k];
            As[k * 68 + m] = v;
        }
        #pragma unroll
        for (int i = 0; i < 32; i++) {
            int idx = tid + i * 256;
            int k = idx >> 6, n = idx & 63;
            float v = 0.f;
            if (k < kl && n0 + n < N) v = B[(size_t)(k0 + k) * ldb + n0 + n];
            Bs[k * 68 + n] = v;
        }
        __syncthreads();
        for (int k = 0; k < kl; k++) {
            float4 a = *(const float4*)&As[k * 68 + ty * 4];
            float4 b = *(const float4*)&Bs[k * 68 + tx * 4];
            acc[0][0] += a.x * b.x; acc[0][1] += a.x * b.y; acc[0][2] += a.x * b.z; acc[0][3] += a.x * b.w;
            acc[1][0] += a.y * b.x; acc[1][1] += a.y * b.y; acc[1][2] += a.y * b.z; acc[1][3] += a.y * b.w;
            acc[2][0] += a.z * b.x; acc[2][1] += a.z * b.y; acc[2][2] += a.z * b.z; acc[2][3] += a.z * b.w;
            acc[3][0] += a.w * b.x; acc[3][1] += a.w * b.y; acc[3][2] += a.w * b.z; acc[3][3] += a.w * b.w;
        }
        __syncthreads();
    }
    #pragma unroll
    for (int i = 0; i < 4; i++) {
        int m = m0 + ty * 4 + i;
        if (m >= M) continue;
        if (PACKED) {
            #pragma unroll
            for (int j = 0; j < 4; j += 2) {
                int n = n0 + tx * 4 + j;              // even
                int slot = pair_slot(n >> 1);
                Cpk[(size_t)m * (ldc >> 1) + slot] = pack_f16x2(acc[i][j], acc[i][j + 1]);
            }
        } else {
            #pragma unroll
            for (int j = 0; j < 4; j++) {
                int n = n0 + tx * 4 + j;
                if (n < N) C[(size_t)m * ldc + n] = acc[i][j];
            }
        }
    }
}

// ---------------- W1: conv(v_low) + band-weight prep + T1t gemm --------------------------
__global__ void __launch_bounds__(256)
wk1(const float* __restrict__ v_low, uint32_t* __restrict__ vlh,
    const float* __restrict__ o_low, const float* __restrict__ v_high,
    float* __restrict__ T1t) {
    extern __shared__ float wsm[];
    const int bid = blockIdx.x, tid = threadIdx.x;
    if (bid < 384) {
        conv_hi_idx(bid * 256 + tid, v_low, RR, HH, vlh);
    } else if (bid < 387) {
        int w = (bid - 384) * 8 + (tid >> 5);
        int lane = tid & 31;
        if (w > RWIN) return;
        float d = (float)w, s = 0.f;
        for (int j = lane; j < NFREQ; j += 32) {
            float f = expf(-(float)j * (9.210340371976184f / (float)NFREQ));
            s += cosf(d * f);
        }
        #pragma unroll
        for (int o = 16; o > 0; o >>= 1) s += __shfl_down_sync(0xffffffffu, s, o);
        if (lane == 0) g_e[w] = expf(s - (float)NFREQ);
    } else {
        int tb = bid - 387;
        gemm64_body<false>(wsm, o_low, HK, v_high, RR, T1t, nullptr, RR,
                           RR, RR, HK, tb >> 2, tb & 3);
    }
}

// ---------------- W2: WcT gemm, fused fp16 pair-interleave -------------------------------
__global__ void __launch_bounds__(256)
wk2(const float* __restrict__ o_high, const float* __restrict__ T1t,
    uint32_t* __restrict__ wch) {
    extern __shared__ float wsm[];
    const int cb = blockIdx.x;               // 48 blocks: 12m x 4n
    gemm64_body<true>(wsm, o_high, RR, T1t, RR, nullptr, wch, CP,
                      HH, RR, RR, cb >> 2, cb & 3);
}

// ---------------- gemm1: zf = round_f16(x @ v_low^T), slot-interleaved out ---------------
#define A_PITCH 72
#define B_PITCH 40
#define A_U32 (128 * A_PITCH)
#define B_U32 (128 * B_PITCH)
#define STAGE_U32 (A_U32 + B_U32)
#define SM_BYTES (2 * STAGE_U32 * 4)    // 114688 B

__global__ void __launch_bounds__(256, 2)
mma_gemm_abt(const float* __restrict__ A, int lda,
             const uint32_t* __restrict__ Bh, int ldbu,
             uint32_t* __restrict__ Cpk, int K) {
    extern __shared__ uint32_t sm4[];
    const uint32_t sb = smem_u32(sm4);
    const int tid  = threadIdx.x;
    const int wid  = tid >> 5;
    const int lane = tid & 31;
    const int m0 = blockIdx.y * 128;
    const int n0 = blockIdx.x * 128;
    const int mbw = (wid & 3) * 32;
    const int nbw = (wid >> 2) * 64;
    const int lr = lane >> 2;
    const int lc = lane & 3;

    const int ar = tid >> 4, ac = tid & 15;
    const int br = tid >> 3, bc = tid & 7;

    const float*    aSrc  = A  + (size_t)(m0 + ar) * lda + ac * 4;
    const uint32_t* bhSrc = Bh + (size_t)(n0 + br) * ldbu + bc * 4;
    const uint32_t aDst  = sb + (ar * A_PITCH + ac * 4) * 4;
    const uint32_t bhDst = sb + (A_U32 + br * B_PITCH + bc * 4) * 4;

    float acc[2][8][4] = {};
    const int nchunks = K >> 6;

    #define ISSUE(ch) do {                                                          \
        const uint32_t so_ = ((ch) & 1) * (STAGE_U32 * 4);                          \
        const int kf_ = (ch) << 6;                                                  \
        const int ku_ = (ch) << 5;                                                  \
        _Pragma("unroll")                                                           \
        for (int i_ = 0; i_ < 8; i_++)                                              \
            cp16(aDst + so_ + i_ * 16 * A_PITCH * 4,                                \
                 aSrc + kf_ + (size_t)i_ * 16 * lda);                               \
        _Pragma("unroll")                                                           \
        for (int i_ = 0; i_ < 4; i_++)                                              \
            cp16(bhDst + so_ + i_ * 32 * B_PITCH * 4,                               \
                 bhSrc + ku_ + (size_t)i_ * 32 * ldbu);                             \
        cp_commit();                                                                \
    } while (0)

    ISSUE(0);
    for (int ch = 0; ch < nchunks; ch++) {
        cp_wait<0>();
        __syncthreads();
        if (ch + 1 < nchunks) ISSUE(ch + 1);

        const uint32_t stg = (ch & 1) * STAGE_U32;
        const float* As = (const float*)(sm4 + stg);
        const uint32_t* BHs = sm4 + stg + A_U32;

        #pragma unroll
        for (int ks = 0; ks < 4; ks++) {
            uint32_t ah[2][4];
            #pragma unroll
            for (int t = 0; t < 2; t++) {
                const float* ap = As + (mbw + t * 16 + lr) * A_PITCH + ks * 16 + 2 * lc;
                float2 f0 = *(const float2*)(ap);
                float2 f1 = *(const float2*)(ap + 8 * A_PITCH);
                float2 f2 = *(const float2*)(ap + 8);
                float2 f3 = *(const float2*)(ap + 8 * A_PITCH + 8);
                ah[t][0] = pack_f16x2(f0.x, f0.y);
                ah[t][1] = pack_f16x2(f1.x, f1.y);
                ah[t][2] = pack_f16x2(f2.x, f2.y);
                ah[t][3] = pack_f16x2(f3.x, f3.y);
            }
            #pragma unroll
            for (int u = 0; u < 8; u++) {
                int rb = (nbw + u * 8 + lr) * B_PITCH + ks * 8 + 2 * lc;
                uint2 bh = *(const uint2*)(BHs + rb);
                #pragma unroll
                for (int t = 0; t < 2; t++)
                    mma_f16(acc[t][u], ah[t], bh.x, bh.y);
            }
        }
    }

    #pragma unroll
    for (int t = 0; t < 2; t++) {
        int row = m0 + mbw + t * 16 + lr;
        #pragma unroll
        for (int u = 0; u < 8; u++) {
            int col = n0 + nbw + u * 8 + lc * 2;       // even
            int slot = pair_slot(col >> 1);
            Cpk[(size_t)row * 128 + slot]       = pack_f16x2(acc[t][u][0], acc[t][u][1]);
            Cpk[(size_t)(row + 8) * 128 + slot] = pack_f16x2(acc[t][u][2], acc[t][u][3]);
        }
    }
}

// ---------------- gemm2: out = z2_f16 @ Wc_f16^T (fp32 out), BK=64 -----------------------
#define P2 40
#define T2_U32 (128 * P2)
#define STAGE2_U32 (2 * T2_U32)
#define SM2_BYTES (2 * STAGE2_U32 * 4)    // 81920 B

__global__ void __launch_bounds__(256, 2)
mma_gemm_fb(const uint32_t* __restrict__ Af, int ldau,
            const uint32_t* __restrict__ Bh, int ldbu,
            float* __restrict__ C, int ldc, int K) {
    extern __shared__ uint32_t sm4[];
    const uint32_t sb = smem_u32(sm4);
    const int tid  = threadIdx.x;
    const int wid  = tid >> 5;
    const int lane = tid & 31;
    const int m0 = blockIdx.y * 128;
    const int n0 = blockIdx.x * 128;
    const int mbw = (wid & 3) * 32;
    const int nbw = (wid >> 2) * 64;
    const int lr = lane >> 2;
    const int lc = lane & 3;

    const int fr = tid >> 3, fc = tid & 7;

    const uint32_t* aSrc = Af + (size_t)(m0 + fr) * ldau + fc * 4;
    const uint32_t* bSrc = Bh + (size_t)(n0 + fr) * ldbu + fc * 4;
    const uint32_t aDst = sb + (fr * P2 + fc * 4) * 4;
    const uint32_t bDst = sb + (T2_U32 + fr * P2 + fc * 4) * 4;

    float acc[2][8][4] = {};
    const int nchunks = K >> 6;

    #define ISSUE2(ch) do {                                                         \
        const uint32_t so_ = ((ch) & 1) * (STAGE2_U32 * 4);                         \
        const int ku_ = (ch) << 5;                                                  \
        _Pragma("unroll")                                                           \
        for (int i_ = 0; i_ < 4; i_++) {                                            \
            cp16(aDst + so_ + i_ * 32 * P2 * 4,                                     \
                 aSrc + ku_ + (size_t)i_ * 32 * ldau);                              \
            cp16(bDst + so_ + i_ * 32 * P2 * 4,                                     \
                 bSrc + ku_ + (size_t)i_ * 32 * ldbu);                              \
        }                                                                           \
        cp_commit();                                                                \
    } while (0)

    ISSUE2(0);
    for (int ch = 0; ch < nchunks; ch++) {
        cp_wait<0>();
        __syncthreads();
        if (ch + 1 < nchunks) ISSUE2(ch + 1);

        const uint32_t stg = (ch & 1) * STAGE2_U32;
        const uint32_t* AFs = sm4 + stg;
        const uint32_t* BHs = sm4 + stg + T2_U32;

        #pragma unroll
        for (int ks = 0; ks < 4; ks++) {
            uint32_t ah[2][4];
            #pragma unroll
            for (int t = 0; t < 2; t++) {
                int ba = (mbw + t * 16 + lr) * P2 + ks * 8 + 2 * lc;
                uint2 h0 = *(const uint2*)(AFs + ba);
                uint2 h8 = *(const uint2*)(AFs + ba + 8 * P2);
                ah[t][0] = h0.x; ah[t][1] = h8.x; ah[t][2] = h0.y; ah[t][3] = h8.y;
            }
            #pragma unroll
            for (int u = 0; u < 8; u++) {
                int rb = (nbw + u * 8 + lr) * P2 + ks * 8 + 2 * lc;
                uint2 bh = *(const uint2*)(BHs + rb);
                #pragma unroll
                for (int t = 0; t < 2; t++)
                    mma_f16(acc[t][u], ah[t], bh.x, bh.y);
            }
        }
    }

    #pragma unroll
    for (int t = 0; t < 2; t++) {
        int row = m0 + mbw + t * 16 + lr;
        #pragma unroll
        for (int u = 0; u < 8; u++) {
            int col = n0 + nbw + u * 8 + lc * 2;
            *(float2*)(C + (size_t)row * ldc + col) = make_float2(acc[t][u][0], acc[t][u][1]);
            *(float2*)(C + (size_t)(row + 8) * ldc + col) = make_float2(acc[t][u][2], acc[t][u][3]);
        }
    }
}

// ---------------- banded softmax mix: 17-tap, contiguous-output register accumulation ----
// Block: 64 s x 32 slots, halo MIXW=8 -> 80 rows smem. Each thread: 1 slot, 8 contiguous s.
__global__ void __launch_bounds__(256)
mix_kernel(const uint32_t* __restrict__ zf, uint32_t* __restrict__ z2f) {
    __shared__ float2 zs[80][32];
    __shared__ __align__(8) float2 wn2[2 * MIXW + 1];   // normalized, duplicated halves
    __shared__ float ws[2 * MIXW + 1];                  // raw weights (boundary path)
    const int s0 = blockIdx.x * 64;
    const int sl0 = blockIdx.y * 32;
    const int b  = blockIdx.z;
    const int tid = threadIdx.x;

    if (tid < 2 * MIXW + 1) {
        float w = g_e[tid < MIXW ? MIXW - tid : tid - MIXW];
        ws[tid] = w;
        float Z = g_e[0];
        #pragma unroll
        for (int d = 1; d <= MIXW; d++) Z += 2.f * g_e[d];
        float wn = w / Z;
        wn2[tid] = make_float2(wn, wn);
    }

    #pragma unroll
    for (int i = 0; i < 10; i++) {
        int idx = tid + i * 256;
        int r = idx >> 5, j = idx & 31;
        int gs = s0 - MIXW + r;
        uint32_t v = 0;
        if ((unsigned)gs < (unsigned)SS)
            v = zf[((size_t)b * SS + gs) * 128 + sl0 + j];
        __half2 h = *reinterpret_cast<__half2*>(&v);
        zs[r][j] = __half22float2(h);
    }
    __syncthreads();

    const int pr = tid & 31;          // slot
    const int sw = tid >> 5;          // s-group: outputs s0 + sw*8 .. +7
    const bool interior = (s0 >= MIXW) && (s0 + 64 + MIXW <= SS);

    if (interior) {
        // weights into registers once
        unsigned long long w2[2 * MIXW + 1];
        #pragma unroll
        for (int dd = 0; dd <= 2 * MIXW; dd++)
            w2[dd] = *(const unsigned long long*)&wn2[dd];

        unsigned long long acc[8] = {};
        // rows rr = 0..23 relative to sw*8; output i gets weight idx i + 16 - rr when in [0,16]
        #pragma unroll
        for (int rr = 0; rr < 8 + 2 * MIXW; rr++) {
            unsigned long long v = *(const unsigned long long*)&zs[sw * 8 + rr][pr];
            #pragma unroll
            for (int i = 0; i < 8; i++) {
                const int wi = i + 2 * MIXW - rr;
                if (wi >= 0 && wi <= 2 * MIXW)
                    asm("fma.rn.f32x2 %0, %1, %2, %0;" : "+l"(acc[i]) : "l"(v), "l"(w2[wi]));
            }
        }
        #pragma unroll
        for (int i = 0; i < 8; i++) {
            float a0 = __uint_as_float((uint32_t)acc[i]);
            float a1 = __uint_as_float((uint32_t)(acc[i] >> 32));
            z2f[((size_t)b * SS + s0 + sw * 8 + i) * 128 + sl0 + pr] = pack_f16x2(a0, a1);
        }
    } else {
        #pragma unroll
        for (int i = 0; i < 8; i++) {
            int sl = sw * 8 + i;
            int s = s0 + sl;
            float Z = 0.f, a0 = 0.f, a1 = 0.f;
            #pragma unroll
            for (int d = -MIXW; d <= MIXW; ++d) {
                int t = s - d;
                if ((unsigned)t < (unsigned)SS) {
                    float w = ws[d + MIXW];
                    Z += w;
                    float2 v = zs[sl + MIXW - d][pr];
                    a0 += w * v.x;
                    a1 += w * v.y;
                }
            }
            float inv = 1.f / Z;
            z2f[((size_t)b * SS + s) * 128 + sl0 + pr] = pack_f16x2(a0 * inv, a1 * inv);
        }
    }
}

// ---------------- launch ------------------------------------------------------------------
extern "C" void kernel_launch(void* const* d_in, const int* in_sizes, int n_in,
                              void* d_out, int out_size) {
    const float* x      = (const float*)d_in[0];
    const float* v_low  = (const float*)d_in[5];   // [242, 768]
    const float* v_high = (const float*)d_in[6];   // [256, 242]
    const float* o_low  = (const float*)d_in[7];   // [242, 256]
    const float* o_high = (const float*)d_in[8];   // [768, 242]
    float* out = (float*)d_out;                    // [4, 4096, 768]

    float* T1t = nullptr; cudaGetSymbolAddress((void**)&T1t, g_T1t);
    uint32_t* vlh = nullptr; cudaGetSymbolAddress((void**)&vlh, g_vlh);
    uint32_t* wch = nullptr; cudaGetSymbolAddress((void**)&wch, g_wch);
    uint32_t* zf  = nullptr; cudaGetSymbolAddress((void**)&zf,  g_zf);
    uint32_t* z2f = nullptr; cudaGetSymbolAddress((void**)&z2f, g_z2f);

    cudaFuncSetAttribute(mma_gemm_abt, cudaFuncAttributeMaxDynamicSharedMemorySize, SM_BYTES);
    cudaFuncSetAttribute(mma_gemm_fb,  cudaFuncAttributeMaxDynamicSharedMemorySize, SM2_BYTES);
    cudaFuncSetAttribute(wk1, cudaFuncAttributeMaxDynamicSharedMemorySize, WSM_BYTES);
    cudaFuncSetAttribute(wk2, cudaFuncAttributeMaxDynamicSharedMemorySize, WSM_BYTES);

    // weight chain (2 launches)
    wk1<<<403, 256, WSM_BYTES>>>(v_low, vlh, o_low, v_high, T1t);
    wk2<<<48, 256, WSM_BYTES>>>(o_high, T1t, wch);

    // gemm1: zf = x @ v_low^T   [16384, 256] -> fp16 slot-interleaved
    mma_gemm_abt<<<dim3(CP / 128, (BB * SS) / 128), 256, SM_BYTES>>>(
        x, HH, vlh, HH / 2, zf, HH);

    // banded softmax mix (fp16 slot space)
    mix_kernel<<<dim3(SS / 64, 4, BB), 256>>>(zf, z2f);

    // gemm2: out = z2 @ WcT^T  [16384, 768]
    mma_gemm_fb<<<dim3(HH / 128, (BB * SS) / 128), 256, SM2_BYTES>>>(
        z2f, CP / 2, wch, CP / 2, out, HH, CP);

    (void)in_sizes; (void)n_in; (void)out_size;
}

// round 15
// speedup vs baseline: 1.9908x; 1.0077x over previous
#include <cuda_runtime.h>
#include <cuda_fp16.h>
#include <cstdint>
#include <cstddef>

// Problem constants
#define BB 4
#define SS 4096
#define HH 768
#define RR 242
#define HK 256
#define CP 256
#define RWIN 16      // g_e table size (prep computes 0..16)
#define MIXW 2       // mix window half-width: normalized w(d) < 1e-15 for d>=2 (sub-ulp in fp32)
#define NFREQ 384

// ---------------- device scratch ---------------------------------------------------------
__device__ float g_T1t[RR * RR];
__device__ float g_e[RWIN + 1];
// pair-interleaved fp16x2 tensors, stored as u32 (one k/channel-pair per word)
__device__ __align__(16) uint32_t g_vlh[CP * HH / 2];
__device__ __align__(16) uint32_t g_wch[HH * CP / 2];
__device__ __align__(16) uint32_t g_zf [(size_t)BB * SS * CP / 2];   // gemm1 out (slot space)
__device__ __align__(16) uint32_t g_z2f[(size_t)BB * SS * CP / 2];   // mixed (slot space)

// ---------------- fp16 helpers -----------------------------------------------------------
__device__ __forceinline__ uint32_t pack_f16x2(float e0, float e1) {
    uint32_t r;                      // low half = e0, high half = e1
    asm("cvt.rn.f16x2.f32 %0, %1, %2;" : "=r"(r) : "f"(e1), "f"(e0));
    return r;
}
__device__ __forceinline__ void mma_f16(float* d, const uint32_t* a, uint32_t b0, uint32_t b1) {
    asm volatile(
        "mma.sync.aligned.m16n8k16.row.col.f32.f16.f16.f32 "
        "{%0,%1,%2,%3}, {%4,%5,%6,%7}, {%8,%9}, {%0,%1,%2,%3};"
        : "+f"(d[0]), "+f"(d[1]), "+f"(d[2]), "+f"(d[3])
        : "r"(a[0]), "r"(a[1]), "r"(a[2]), "r"(a[3]), "r"(b0), "r"(b1));
}
__device__ __forceinline__ uint32_t smem_u32(const void* p) {
    uint32_t a;
    asm("{ .reg .u64 t; cvta.to.shared.u64 t, %1; cvt.u32.u64 %0, t; }" : "=r"(a) : "l"(p));
    return a;
}
__device__ __forceinline__ void cp16(uint32_t dst, const void* src) {
    asm volatile("cp.async.cg.shared.global [%0], [%1], 16;" :: "r"(dst), "l"(src));
}
__device__ __forceinline__ void cp_commit() {
    asm volatile("cp.async.commit_group;" ::: "memory");
}
template<int N> __device__ __forceinline__ void cp_wait() {
    asm volatile("cp.async.wait_group %0;" :: "n"(N) : "memory");
}
// slot of channel/k pair P within its 128-slot row (matches mma b/a-frag k pattern)
__device__ __forceinline__ int pair_slot(int P) {
    return (P & 0x78) + 2 * (P & 3) + ((P >> 2) & 1);
}

// ---------------- pair-interleave conversion (hi only) -----------------------------------
__device__ __forceinline__ void conv_hi_idx(int idx, const float* __restrict__ src,
                                            int rows_src, int cols,
                                            uint32_t* __restrict__ hi) {
    int cols2 = cols >> 1;
    int row = idx / cols2;
    int s   = idx - row * cols2;
    int grp = s >> 3, j = s & 7;
    int k = (grp << 4) + (((j >> 1) + ((j & 1) << 2)) << 1);
    float e0 = 0.f, e1 = 0.f;
    if (row < rows_src) {
        e0 = src[(size_t)row * cols + k];
        e1 = src[(size_t)row * cols + k + 1];
    }
    hi[idx] = pack_f16x2(e0, e1);
}

// ---------------- 64x64 small gemm core (K loop in smem) ---------------------------------
#define WSM_BYTES (2 * 128 * 68 * 4)
template<bool PACKED>
__device__ void gemm64_body(float* smem,
                            const float* __restrict__ A, int lda,
                            const float* __restrict__ B, int ldb,
                            float* __restrict__ C, uint32_t* __restrict__ Cpk, int ldc,
                            int M, int N, int K, int m_t, int n_t) {
    float* As = smem;             // [128][68]  As[k][m]
    float* Bs = smem + 128 * 68;  // [128][68]  Bs[k][n]
    const int tid = threadIdx.x;
    const int m0 = m_t * 64, n0 = n_t * 64;
    const int ty = tid >> 4, tx = tid & 15;
    float acc[4][4] = {};
    for (int k0 = 0; k0 < K; k0 += 128) {
        const int kl = min(128, K - k0);
        #pragma unroll
        for (int i = 0; i < 32; i++) {
            int idx = tid + i * 256;
            int m = idx >> 7, k = idx & 127;
            float v = 0.f;
            if (k < kl && m0 + m < M) v = A[(size_t)(m0 + m) * lda + k0 + k];
            As[k * 68 + m] = v;
        }
        #pragma unroll
        for (int i = 0; i < 32; i++) {
            int idx = tid + i * 256;
            int k = idx >> 6, n = idx & 63;
            float v = 0.f;
            if (k < kl && n0 + n < N) v = B[(size_t)(k0 + k) * ldb + n0 + n];
            Bs[k * 68 + n] = v;
        }
        __syncthreads();
        for (int k = 0; k < kl; k++) {
            float4 a = *(const float4*)&As[k * 68 + ty * 4];
            float4 b = *(const float4*)&Bs[k * 68 + tx * 4];
            acc[0][0] += a.x * b.x; acc[0][1] += a.x * b.y; acc[0][2] += a.x * b.z; acc[0][3] += a.x * b.w;
            acc[1][0] += a.y * b.x; acc[1][1] += a.y * b.y; acc[1][2] += a.y * b.z; acc[1][3] += a.y * b.w;
            acc[2][0] += a.z * b.x; acc[2][1] += a.z * b.y; acc[2][2] += a.z * b.z; acc[2][3] += a.z * b.w;
            acc[3][0] += a.w * b.x; acc[3][1] += a.w * b.y; acc[3][2] += a.w * b.z; acc[3][3] += a.w * b.w;
        }
        __syncthreads();
    }
    #pragma unroll
    for (int i = 0; i < 4; i++) {
        int m = m0 + ty * 4 + i;
        if (m >= M) continue;
        if (PACKED) {
            #pragma unroll
            for (int j = 0; j < 4; j += 2) {
                int n = n0 + tx * 4 + j;              // even
                int slot = pair_slot(n >> 1);
                Cpk[(size_t)m * (ldc >> 1) + slot] = pack_f16x2(acc[i][j], acc[i][j + 1]);
            }
        } else {
            #pragma unroll
            for (int j = 0; j < 4; j++) {
                int n = n0 + tx * 4 + j;
                if (n < N) C[(size_t)m * ldc + n] = acc[i][j];
            }
        }
    }
}

// ---------------- W1: conv(v_low) + band-weight prep + T1t gemm --------------------------
__global__ void __launch_bounds__(256)
wk1(const float* __restrict__ v_low, uint32_t* __restrict__ vlh,
    const float* __restrict__ o_low, const float* __restrict__ v_high,
    float* __restrict__ T1t) {
    extern __shared__ float wsm[];
    const int bid = blockIdx.x, tid = threadIdx.x;
    if (bid < 384) {
        conv_hi_idx(bid * 256 + tid, v_low, RR, HH, vlh);
    } else if (bid < 387) {
        int w = (bid - 384) * 8 + (tid >> 5);
        int lane = tid & 31;
        if (w > RWIN) return;
        float d = (float)w, s = 0.f;
        for (int j = lane; j < NFREQ; j += 32) {
            float f = expf(-(float)j * (9.210340371976184f / (float)NFREQ));
            s += cosf(d * f);
        }
        #pragma unroll
        for (int o = 16; o > 0; o >>= 1) s += __shfl_down_sync(0xffffffffu, s, o);
        if (lane == 0) g_e[w] = expf(s - (float)NFREQ);
    } else {
        int tb = bid - 387;
        gemm64_body<false>(wsm, o_low, HK, v_high, RR, T1t, nullptr, RR,
                           RR, RR, HK, tb >> 2, tb & 3);
    }
}

// ---------------- W2: WcT gemm, fused fp16 pair-interleave -------------------------------
__global__ void __launch_bounds__(256)
wk2(const float* __restrict__ o_high, const float* __restrict__ T1t,
    uint32_t* __restrict__ wch) {
    extern __shared__ float wsm[];
    const int cb = blockIdx.x;               // 48 blocks: 12m x 4n
    gemm64_body<true>(wsm, o_high, RR, T1t, RR, nullptr, wch, CP,
                      HH, RR, RR, cb >> 2, cb & 3);
}

// ---------------- gemm1: zf = round_f16(x @ v_low^T), slot-interleaved out ---------------
#define A_PITCH 72
#define B_PITCH 40
#define A_U32 (128 * A_PITCH)
#define B_U32 (128 * B_PITCH)
#define STAGE_U32 (A_U32 + B_U32)
#define SM_BYTES (2 * STAGE_U32 * 4)    // 114688 B

__global__ void __launch_bounds__(256, 2)
mma_gemm_abt(const float* __restrict__ A, int lda,
             const uint32_t* __restrict__ Bh, int ldbu,
             uint32_t* __restrict__ Cpk, int K) {
    extern __shared__ uint32_t sm4[];
    const uint32_t sb = smem_u32(sm4);
    const int tid  = threadIdx.x;
    const int wid  = tid >> 5;
    const int lane = tid & 31;
    const int m0 = blockIdx.y * 128;
    const int n0 = blockIdx.x * 128;
    const int mbw = (wid & 3) * 32;
    const int nbw = (wid >> 2) * 64;
    const int lr = lane >> 2;
    const int lc = lane & 3;

    const int ar = tid >> 4, ac = tid & 15;
    const int br = tid >> 3, bc = tid & 7;

    const float*    aSrc  = A  + (size_t)(m0 + ar) * lda + ac * 4;
    const uint32_t* bhSrc = Bh + (size_t)(n0 + br) * ldbu + bc * 4;
    const uint32_t aDst  = sb + (ar * A_PITCH + ac * 4) * 4;
    const uint32_t bhDst = sb + (A_U32 + br * B_PITCH + bc * 4) * 4;

    float acc[2][8][4] = {};
    const int nchunks = K >> 6;

    #define ISSUE(ch) do {                                                          \
        const uint32_t so_ = ((ch) & 1) * (STAGE_U32 * 4);                          \
        const int kf_ = (ch) << 6;                                                  \
        const int ku_ = (ch) << 5;                                                  \
        _Pragma("unroll")                                                           \
        for (int i_ = 0; i_ < 8; i_++)                                              \
            cp16(aDst + so_ + i_ * 16 * A_PITCH * 4,                                \
                 aSrc + kf_ + (size_t)i_ * 16 * lda);                               \
        _Pragma("unroll")                                                           \
        for (int i_ = 0; i_ < 4; i_++)                                              \
            cp16(bhDst + so_ + i_ * 32 * B_PITCH * 4,                               \
                 bhSrc + ku_ + (size_t)i_ * 32 * ldbu);                             \
        cp_commit();                                                                \
    } while (0)

    ISSUE(0);
    for (int ch = 0; ch < nchunks; ch++) {
        cp_wait<0>();
        __syncthreads();
        if (ch + 1 < nchunks) ISSUE(ch + 1);

        const uint32_t stg = (ch & 1) * STAGE_U32;
        const float* As = (const float*)(sm4 + stg);
        const uint32_t* BHs = sm4 + stg + A_U32;

        #pragma unroll
        for (int ks = 0; ks < 4; ks++) {
            uint32_t ah[2][4];
            #pragma unroll
            for (int t = 0; t < 2; t++) {
                const float* ap = As + (mbw + t * 16 + lr) * A_PITCH + ks * 16 + 2 * lc;
                float2 f0 = *(const float2*)(ap);
                float2 f1 = *(const float2*)(ap + 8 * A_PITCH);
                float2 f2 = *(const float2*)(ap + 8);
                float2 f3 = *(const float2*)(ap + 8 * A_PITCH + 8);
                ah[t][0] = pack_f16x2(f0.x, f0.y);
                ah[t][1] = pack_f16x2(f1.x, f1.y);
                ah[t][2] = pack_f16x2(f2.x, f2.y);
                ah[t][3] = pack_f16x2(f3.x, f3.y);
            }
            #pragma unroll
            for (int u = 0; u < 8; u++) {
                int rb = (nbw + u * 8 + lr) * B_PITCH + ks * 8 + 2 * lc;
                uint2 bh = *(const uint2*)(BHs + rb);
                #pragma unroll
                for (int t = 0; t < 2; t++)
                    mma_f16(acc[t][u], ah[t], bh.x, bh.y);
            }
        }
    }

    #pragma unroll
    for (int t = 0; t < 2; t++) {
        int row = m0 + mbw + t * 16 + lr;
        #pragma unroll
        for (int u = 0; u < 8; u++) {
            int col = n0 + nbw + u * 8 + lc * 2;       // even
            int slot = pair_slot(col >> 1);
            Cpk[(size_t)row * 128 + slot]       = pack_f16x2(acc[t][u][0], acc[t][u][1]);
            Cpk[(size_t)(row + 8) * 128 + slot] = pack_f16x2(acc[t][u][2], acc[t][u][3]);
        }
    }
}

// ---------------- gemm2: out = z2_f16 @ Wc_f16^T (fp32 out), BK=64 -----------------------
#define P2 40
#define T2_U32 (128 * P2)
#define STAGE2_U32 (2 * T2_U32)
#define SM2_BYTES (2 * STAGE2_U32 * 4)    // 81920 B

__global__ void __launch_bounds__(256, 2)
mma_gemm_fb(const uint32_t* __restrict__ Af, int ldau,
            const uint32_t* __restrict__ Bh, int ldbu,
            float* __restrict__ C, int ldc, int K) {
    extern __shared__ uint32_t sm4[];
    const uint32_t sb = smem_u32(sm4);
    const int tid  = threadIdx.x;
    const int wid  = tid >> 5;
    const int lane = tid & 31;
    const int m0 = blockIdx.y * 128;
    const int n0 = blockIdx.x * 128;
    const int mbw = (wid & 3) * 32;
    const int nbw = (wid >> 2) * 64;
    const int lr = lane >> 2;
    const int lc = lane & 3;

    const int fr = tid >> 3, fc = tid & 7;

    const uint32_t* aSrc = Af + (size_t)(m0 + fr) * ldau + fc * 4;
    const uint32_t* bSrc = Bh + (size_t)(n0 + fr) * ldbu + fc * 4;
    const uint32_t aDst = sb + (fr * P2 + fc * 4) * 4;
    const uint32_t bDst = sb + (T2_U32 + fr * P2 + fc * 4) * 4;

    float acc[2][8][4] = {};
    const int nchunks = K >> 6;

    #define ISSUE2(ch) do {                                                         \
        const uint32_t so_ = ((ch) & 1) * (STAGE2_U32 * 4);                         \
        const int ku_ = (ch) << 5;                                                  \
        _Pragma("unroll")                                                           \
        for (int i_ = 0; i_ < 4; i_++) {                                            \
            cp16(aDst + so_ + i_ * 32 * P2 * 4,                                     \
                 aSrc + ku_ + (size_t)i_ * 32 * ldau);                              \
            cp16(bDst + so_ + i_ * 32 * P2 * 4,                                     \
                 bSrc + ku_ + (size_t)i_ * 32 * ldbu);                              \
        }                                                                           \
        cp_commit();                                                                \
    } while (0)

    ISSUE2(0);
    for (int ch = 0; ch < nchunks; ch++) {
        cp_wait<0>();
        __syncthreads();
        if (ch + 1 < nchunks) ISSUE2(ch + 1);

        const uint32_t stg = (ch & 1) * STAGE2_U32;
        const uint32_t* AFs = sm4 + stg;
        const uint32_t* BHs = sm4 + stg + T2_U32;

        #pragma unroll
        for (int ks = 0; ks < 4; ks++) {
            uint32_t ah[2][4];
            #pragma unroll
            for (int t = 0; t < 2; t++) {
                int ba = (mbw + t * 16 + lr) * P2 + ks * 8 + 2 * lc;
                uint2 h0 = *(const uint2*)(AFs + ba);
                uint2 h8 = *(const uint2*)(AFs + ba + 8 * P2);
                ah[t][0] = h0.x; ah[t][1] = h8.x; ah[t][2] = h0.y; ah[t][3] = h8.y;
            }
            #pragma unroll
            for (int u = 0; u < 8; u++) {
                int rb = (nbw + u * 8 + lr) * P2 + ks * 8 + 2 * lc;
                uint2 bh = *(const uint2*)(BHs + rb);
                #pragma unroll
                for (int t = 0; t < 2; t++)
                    mma_f16(acc[t][u], ah[t], bh.x, bh.y);
            }
        }
    }

    #pragma unroll
    for (int t = 0; t < 2; t++) {
        int row = m0 + mbw + t * 16 + lr;
        #pragma unroll
        for (int u = 0; u < 8; u++) {
            int col = n0 + nbw + u * 8 + lc * 2;
            *(float2*)(C + (size_t)row * ldc + col) = make_float2(acc[t][u][0], acc[t][u][1]);
            *(float2*)(C + (size_t)(row + 8) * ldc + col) = make_float2(acc[t][u][2], acc[t][u][3]);
        }
    }
}

// ---------------- banded softmax mix: 5-tap, contiguous-output register accumulation -----
// Block: 64 s x 32 slots, halo MIXW=2 -> 68 rows smem. Each thread: 1 slot, 8 contiguous s.
__global__ void __launch_bounds__(256)
mix_kernel(const uint32_t* __restrict__ zf, uint32_t* __restrict__ z2f) {
    __shared__ float2 zs[64 + 2 * MIXW][32];
    __shared__ __align__(8) float2 wn2[2 * MIXW + 1];   // normalized, duplicated halves
    __shared__ float ws[2 * MIXW + 1];                  // raw weights (boundary path)
    const int s0 = blockIdx.x * 64;
    const int sl0 = blockIdx.y * 32;
    const int b  = blockIdx.z;
    const int tid = threadIdx.x;

    if (tid < 2 * MIXW + 1) {
        float w = g_e[tid < MIXW ? MIXW - tid : tid - MIXW];
        ws[tid] = w;
        float Z = g_e[0];
        #pragma unroll
        for (int d = 1; d <= MIXW; d++) Z += 2.f * g_e[d];
        float wn = w / Z;
        wn2[tid] = make_float2(wn, wn);
    }

    const int NROWS = 64 + 2 * MIXW;     // 68
    #pragma unroll
    for (int i = 0; i < 9; i++) {
        int idx = tid + i * 256;
        if (idx < NROWS * 32) {
            int r = idx >> 5, j = idx & 31;
            int gs = s0 - MIXW + r;
            uint32_t v = 0;
            if ((unsigned)gs < (unsigned)SS)
                v = zf[((size_t)b * SS + gs) * 128 + sl0 + j];
            __half2 h = *reinterpret_cast<__half2*>(&v);
            zs[r][j] = __half22float2(h);
        }
    }
    __syncthreads();

    const int pr = tid & 31;          // slot
    const int sw = tid >> 5;          // s-group: outputs s0 + sw*8 .. +7
    const bool interior = (s0 >= MIXW) && (s0 + 64 + MIXW <= SS);

    if (interior) {
        unsigned long long w2[2 * MIXW + 1];
        #pragma unroll
        for (int dd = 0; dd <= 2 * MIXW; dd++)
            w2[dd] = *(const unsigned long long*)&wn2[dd];

        unsigned long long acc[8] = {};
        // rows rr = 0..(8+2*MIXW-1) relative to sw*8; output i uses weight wi = i+2*MIXW-rr
        #pragma unroll
        for (int rr = 0; rr < 8 + 2 * MIXW; rr++) {
            unsigned long long v = *(const unsigned long long*)&zs[sw * 8 + rr][pr];
            #pragma unroll
            for (int i = 0; i < 8; i++) {
                const int wi = i + 2 * MIXW - rr;
                if (wi >= 0 && wi <= 2 * MIXW)
                    asm("fma.rn.f32x2 %0, %1, %2, %0;" : "+l"(acc[i]) : "l"(v), "l"(w2[wi]));
            }
        }
        #pragma unroll
        for (int i = 0; i < 8; i++) {
            float a0 = __uint_as_float((uint32_t)acc[i]);
            float a1 = __uint_as_float((uint32_t)(acc[i] >> 32));
            z2f[((size_t)b * SS + s0 + sw * 8 + i) * 128 + sl0 + pr] = pack_f16x2(a0, a1);
        }
    } else {
        #pragma unroll
        for (int i = 0; i < 8; i++) {
            int sl = sw * 8 + i;
            int s = s0 + sl;
            float Z = 0.f, a0 = 0.f, a1 = 0.f;
            #pragma unroll
            for (int d = -MIXW; d <= MIXW; ++d) {
                int t = s - d;
                if ((unsigned)t < (unsigned)SS) {
                    float w = ws[d + MIXW];
                    Z += w;
                    float2 v = zs[sl + MIXW - d][pr];
                    a0 += w * v.x;
                    a1 += w * v.y;
                }
            }
            float inv = 1.f / Z;
            z2f[((size_t)b * SS + s) * 128 + sl0 + pr] = pack_f16x2(a0 * inv, a1 * inv);
        }
    }
}

// ---------------- launch ------------------------------------------------------------------
extern "C" void kernel_launch(void* const* d_in, const int* in_sizes, int n_in,
                              void* d_out, int out_size) {
    const float* x      = (const float*)d_in[0];
    const float* v_low  = (const float*)d_in[5];   // [242, 768]
    const float* v_high = (const float*)d_in[6];   // [256, 242]
    const float* o_low  = (const float*)d_in[7];   // [242, 256]
    const float* o_high = (const float*)d_in[8];   // [768, 242]
    float* out = (float*)d_out;                    // [4, 4096, 768]

    float* T1t = nullptr; cudaGetSymbolAddress((void**)&T1t, g_T1t);
    uint32_t* vlh = nullptr; cudaGetSymbolAddress((void**)&vlh, g_vlh);
    uint32_t* wch = nullptr; cudaGetSymbolAddress((void**)&wch, g_wch);
    uint32_t* zf  = nullptr; cudaGetSymbolAddress((void**)&zf,  g_zf);
    uint32_t* z2f = nullptr; cudaGetSymbolAddress((void**)&z2f, g_z2f);

    cudaFuncSetAttribute(mma_gemm_abt, cudaFuncAttributeMaxDynamicSharedMemorySize, SM_BYTES);
    cudaFuncSetAttribute(mma_gemm_fb,  cudaFuncAttributeMaxDynamicSharedMemorySize, SM2_BYTES);
    cudaFuncSetAttribute(wk1, cudaFuncAttributeMaxDynamicSharedMemorySize, WSM_BYTES);
    cudaFuncSetAttribute(wk2, cudaFuncAttributeMaxDynamicSharedMemorySize, WSM_BYTES);

    // weight chain (2 launches)
    wk1<<<403, 256, WSM_BYTES>>>(v_low, vlh, o_low, v_high, T1t);
    wk2<<<48, 256, WSM_BYTES>>>(o_high, T1t, wch);

    // gemm1: zf = x @ v_low^T   [16384, 256] -> fp16 slot-interleaved
    mma_gemm_abt<<<dim3(CP / 128, (BB * SS) / 128), 256, SM_BYTES>>>(
        x, HH, vlh, HH / 2, zf, HH);

    // banded softmax mix (fp16 slot space, 5 taps)
    mix_kernel<<<dim3(SS / 64, 4, BB), 256>>>(zf, z2f);

    // gemm2: out = z2 @ WcT^T  [16384, 768]
    mma_gemm_fb<<<dim3(HH / 128, (BB * SS) / 128), 256, SM2_BYTES>>>(
        z2f, CP / 2, wch, CP / 2, out, HH, CP);

    (void)in_sizes; (void)n_in; (void)out_size;
}

// round 16
// speedup vs baseline: 2.6977x; 1.3551x over previous
#include <cuda_runtime.h>
#include <cuda_fp16.h>
#include <cstdint>
#include <cstddef>

// Problem constants
#define BB 4
#define SS 4096
#define HH 768
#define RR 242
#define HK 256
#define CP 256
#define RWIN 16      // g_e table size (prep computes 0..16)
#define MIXW 2       // mix window half-width: normalized w(d) < 1e-15 for d>=2 (sub-ulp in fp32)
#define NFREQ 384

// ---------------- device scratch ---------------------------------------------------------
__device__ float g_T1t[RR * RR];
__device__ float g_e[RWIN + 1];
// pair-interleaved fp16x2 tensors, stored as u32 (one k/channel-pair per word)
__device__ __align__(16) uint32_t g_vlh[CP * HH / 2];
__device__ __align__(16) uint32_t g_wch[HH * CP / 2];
__device__ __align__(16) uint32_t g_zf [(size_t)BB * SS * CP / 2];   // gemm1 out (slot space)
__device__ __align__(16) uint32_t g_z2f[(size_t)BB * SS * CP / 2];   // mixed (slot space)

// ---------------- fp16 helpers -----------------------------------------------------------
__device__ __forceinline__ uint32_t pack_f16x2(float e0, float e1) {
    uint32_t r;                      // low half = e0, high half = e1
    asm("cvt.rn.f16x2.f32 %0, %1, %2;" : "=r"(r) : "f"(e1), "f"(e0));
    return r;
}
__device__ __forceinline__ void mma_f16(float* d, const uint32_t* a, uint32_t b0, uint32_t b1) {
    asm volatile(
        "mma.sync.aligned.m16n8k16.row.col.f32.f16.f16.f32 "
        "{%0,%1,%2,%3}, {%4,%5,%6,%7}, {%8,%9}, {%0,%1,%2,%3};"
        : "+f"(d[0]), "+f"(d[1]), "+f"(d[2]), "+f"(d[3])
        : "r"(a[0]), "r"(a[1]), "r"(a[2]), "r"(a[3]), "r"(b0), "r"(b1));
}
__device__ __forceinline__ uint32_t smem_u32(const void* p) {
    uint32_t a;
    asm("{ .reg .u64 t; cvta.to.shared.u64 t, %1; cvt.u32.u64 %0, t; }" : "=r"(a) : "l"(p));
    return a;
}
__device__ __forceinline__ void cp16(uint32_t dst, const void* src) {
    asm volatile("cp.async.cg.shared.global [%0], [%1], 16;" :: "r"(dst), "l"(src));
}
__device__ __forceinline__ void cp_commit() {
    asm volatile("cp.async.commit_group;" ::: "memory");
}
template<int N> __device__ __forceinline__ void cp_wait() {
    asm volatile("cp.async.wait_group %0;" :: "n"(N) : "memory");
}
// slot of channel/k pair P within its 128-slot row (matches mma b/a-frag k pattern)
__device__ __forceinline__ int pair_slot(int P) {
    return (P & 0x78) + 2 * (P & 3) + ((P >> 2) & 1);
}

// ---------------- pair-interleave conversion (hi only) -----------------------------------
__device__ __forceinline__ void conv_hi_idx(int idx, const float* __restrict__ src,
                                            int rows_src, int cols,
                                            uint32_t* __restrict__ hi) {
    int cols2 = cols >> 1;
    int row = idx / cols2;
    int s   = idx - row * cols2;
    int grp = s >> 3, j = s & 7;
    int k = (grp << 4) + (((j >> 1) + ((j & 1) << 2)) << 1);
    float e0 = 0.f, e1 = 0.f;
    if (row < rows_src) {
        e0 = src[(size_t)row * cols + k];
        e1 = src[(size_t)row * cols + k + 1];
    }
    hi[idx] = pack_f16x2(e0, e1);
}

// ---------------- 64x64 small gemm core (K loop in smem) ---------------------------------
#define WSM_BYTES (2 * 128 * 68 * 4)
template<bool PACKED>
__device__ void gemm64_body(float* smem,
                            const float* __restrict__ A, int lda,
                            const float* __restrict__ B, int ldb,
                            float* __restrict__ C, uint32_t* __restrict__ Cpk, int ldc,
                            int M, int N, int K, int m_t, int n_t) {
    float* As = smem;             // [128][68]  As[k][m]
    float* Bs = smem + 128 * 68;  // [128][68]  Bs[k][n]
    const int tid = threadIdx.x;
    const int m0 = m_t * 64, n0 = n_t * 64;
    const int ty = tid >> 4, tx = tid & 15;
    float acc[4][4] = {};
    for (int k0 = 0; k0 < K; k0 += 128) {
        const int kl = min(128, K - k0);
        #pragma unroll
        for (int i = 0; i < 32; i++) {
            int idx = tid + i * 256;
            int m = idx >> 7, k = idx & 127;
            float v = 0.f;
            if (k < kl && m0 + m < M) v = A[(size_t)(m0 + m) * lda + k0 + k];
            As[k * 68 + m] = v;
        }
        #pragma unroll
        for (int i = 0; i < 32; i++) {
            int idx = tid + i * 256;
            int k = idx >> 6, n = idx & 63;
            float v = 0.f;
            if (k < kl && n0 + n < N) v = B[(size_t)(k0 + k) * ldb + n0 + n];
            Bs[k * 68 + n] = v;
        }
        __syncthreads();
        for (int k = 0; k < kl; k++) {
            float4 a = *(const float4*)&As[k * 68 + ty * 4];
            float4 b = *(const float4*)&Bs[k * 68 + tx * 4];
            acc[0][0] += a.x * b.x; acc[0][1] += a.x * b.y; acc[0][2] += a.x * b.z; acc[0][3] += a.x * b.w;
            acc[1][0] += a.y * b.x; acc[1][1] += a.y * b.y; acc[1][2] += a.y * b.z; acc[1][3] += a.y * b.w;
            acc[2][0] += a.z * b.x; acc[2][1] += a.z * b.y; acc[2][2] += a.z * b.z; acc[2][3] += a.z * b.w;
            acc[3][0] += a.w * b.x; acc[3][1] += a.w * b.y; acc[3][2] += a.w * b.z; acc[3][3] += a.w * b.w;
        }
        __syncthreads();
    }
    #pragma unroll
    for (int i = 0; i < 4; i++) {
        int m = m0 + ty * 4 + i;
        if (m >= M) continue;
        if (PACKED) {
            #pragma unroll
            for (int j = 0; j < 4; j += 2) {
                int n = n0 + tx * 4 + j;              // even
                int slot = pair_slot(n >> 1);
                Cpk[(size_t)m * (ldc >> 1) + slot] = pack_f16x2(acc[i][j], acc[i][j + 1]);
            }
        } else {
            #pragma unroll
            for (int j = 0; j < 4; j++) {
                int n = n0 + tx * 4 + j;
                if (n < N) C[(size_t)m * ldc + n] = acc[i][j];
            }
        }
    }
}

// ---------------- W1a: conv(v_low) + band-weight prep (no smem) --------------------------
__global__ void __launch_bounds__(256)
wk1a(const float* __restrict__ v_low, uint32_t* __restrict__ vlh) {
    const int bid = blockIdx.x, tid = threadIdx.x;
    if (bid < 384) {
        conv_hi_idx(bid * 256 + tid, v_low, RR, HH, vlh);
    } else {
        int w = (bid - 384) * 8 + (tid >> 5);
        int lane = tid & 31;
        if (w > RWIN) return;
        float d = (float)w, s = 0.f;
        for (int j = lane; j < NFREQ; j += 32) {
            float f = expf(-(float)j * (9.210340371976184f / (float)NFREQ));
            s += cosf(d * f);
        }
        #pragma unroll
        for (int o = 16; o > 0; o >>= 1) s += __shfl_down_sync(0xffffffffu, s, o);
        if (lane == 0) g_e[w] = expf(s - (float)NFREQ);
    }
}

// ---------------- W1b: T1t gemm (side stream) --------------------------------------------
__global__ void __launch_bounds__(256)
wk1b(const float* __restrict__ o_low, const float* __restrict__ v_high,
     float* __restrict__ T1t) {
    extern __shared__ float wsm[];
    const int tb = blockIdx.x;               // 16 blocks: 4m x 4n
    gemm64_body<false>(wsm, o_low, HK, v_high, RR, T1t, nullptr, RR,
                       RR, RR, HK, tb >> 2, tb & 3);
}

// ---------------- W2: WcT gemm, fused fp16 pair-interleave (side stream) -----------------
__global__ void __launch_bounds__(256)
wk2(const float* __restrict__ o_high, const float* __restrict__ T1t,
    uint32_t* __restrict__ wch) {
    extern __shared__ float wsm[];
    const int cb = blockIdx.x;               // 48 blocks: 12m x 4n
    gemm64_body<true>(wsm, o_high, RR, T1t, RR, nullptr, wch, CP,
                      HH, RR, RR, cb >> 2, cb & 3);
}

// ---------------- gemm1: zf = round_f16(x @ v_low^T), slot-interleaved out ---------------
#define A_PITCH 72
#define B_PITCH 40
#define A_U32 (128 * A_PITCH)
#define B_U32 (128 * B_PITCH)
#define STAGE_U32 (A_U32 + B_U32)
#define SM_BYTES (2 * STAGE_U32 * 4)    // 114688 B

__global__ void __launch_bounds__(256, 2)
mma_gemm_abt(const float* __restrict__ A, int lda,
             const uint32_t* __restrict__ Bh, int ldbu,
             uint32_t* __restrict__ Cpk, int K) {
    extern __shared__ uint32_t sm4[];
    const uint32_t sb = smem_u32(sm4);
    const int tid  = threadIdx.x;
    const int wid  = tid >> 5;
    const int lane = tid & 31;
    const int m0 = blockIdx.y * 128;
    const int n0 = blockIdx.x * 128;
    const int mbw = (wid & 3) * 32;
    const int nbw = (wid >> 2) * 64;
    const int lr = lane >> 2;
    const int lc = lane & 3;

    const int ar = tid >> 4, ac = tid & 15;
    const int br = tid >> 3, bc = tid & 7;

    const float*    aSrc  = A  + (size_t)(m0 + ar) * lda + ac * 4;
    const uint32_t* bhSrc = Bh + (size_t)(n0 + br) * ldbu + bc * 4;
    const uint32_t aDst  = sb + (ar * A_PITCH + ac * 4) * 4;
    const uint32_t bhDst = sb + (A_U32 + br * B_PITCH + bc * 4) * 4;

    float acc[2][8][4] = {};
    const int nchunks = K >> 6;

    #define ISSUE(ch) do {                                                          \
        const uint32_t so_ = ((ch) & 1) * (STAGE_U32 * 4);                          \
        const int kf_ = (ch) << 6;                                                  \
        const int ku_ = (ch) << 5;                                                  \
        _Pragma("unroll")                                                           \
        for (int i_ = 0; i_ < 8; i_++)                                              \
            cp16(aDst + so_ + i_ * 16 * A_PITCH * 4,                                \
                 aSrc + kf_ + (size_t)i_ * 16 * lda);                               \
        _Pragma("unroll")                                                           \
        for (int i_ = 0; i_ < 4; i_++)                                              \
            cp16(bhDst + so_ + i_ * 32 * B_PITCH * 4,                               \
                 bhSrc + ku_ + (size_t)i_ * 32 * ldbu);                             \
        cp_commit();                                                                \
    } while (0)

    ISSUE(0);
    for (int ch = 0; ch < nchunks; ch++) {
        cp_wait<0>();
        __syncthreads();
        if (ch + 1 < nchunks) ISSUE(ch + 1);

        const uint32_t stg = (ch & 1) * STAGE_U32;
        const float* As = (const float*)(sm4 + stg);
        const uint32_t* BHs = sm4 + stg + A_U32;

        #pragma unroll
        for (int ks = 0; ks < 4; ks++) {
            uint32_t ah[2][4];
            #pragma unroll
            for (int t = 0; t < 2; t++) {
                const float* ap = As + (mbw + t * 16 + lr) * A_PITCH + ks * 16 + 2 * lc;
                float2 f0 = *(const float2*)(ap);
                float2 f1 = *(const float2*)(ap + 8 * A_PITCH);
                float2 f2 = *(const float2*)(ap + 8);
                float2 f3 = *(const float2*)(ap + 8 * A_PITCH + 8);
                ah[t][0] = pack_f16x2(f0.x, f0.y);
                ah[t][1] = pack_f16x2(f1.x, f1.y);
                ah[t][2] = pack_f16x2(f2.x, f2.y);
                ah[t][3] = pack_f16x2(f3.x, f3.y);
            }
            #pragma unroll
            for (int u = 0; u < 8; u++) {
                int rb = (nbw + u * 8 + lr) * B_PITCH + ks * 8 + 2 * lc;
                uint2 bh = *(const uint2*)(BHs + rb);
                #pragma unroll
                for (int t = 0; t < 2; t++)
                    mma_f16(acc[t][u], ah[t], bh.x, bh.y);
            }
        }
    }

    #pragma unroll
    for (int t = 0; t < 2; t++) {
        int row = m0 + mbw + t * 16 + lr;
        #pragma unroll
        for (int u = 0; u < 8; u++) {
            int col = n0 + nbw + u * 8 + lc * 2;       // even
            int slot = pair_slot(col >> 1);
            Cpk[(size_t)row * 128 + slot]       = pack_f16x2(acc[t][u][0], acc[t][u][1]);
            Cpk[(size_t)(row + 8) * 128 + slot] = pack_f16x2(acc[t][u][2], acc[t][u][3]);
        }
    }
}

// ---------------- gemm2: out = z2_f16 @ Wc_f16^T (fp32 out), BK=64 -----------------------
#define P2 40
#define T2_U32 (128 * P2)
#define STAGE2_U32 (2 * T2_U32)
#define SM2_BYTES (2 * STAGE2_U32 * 4)    // 81920 B

__global__ void __launch_bounds__(256, 2)
mma_gemm_fb(const uint32_t* __restrict__ Af, int ldau,
            const uint32_t* __restrict__ Bh, int ldbu,
            float* __restrict__ C, int ldc, int K) {
    extern __shared__ uint32_t sm4[];
    const uint32_t sb = smem_u32(sm4);
    const int tid  = threadIdx.x;
    const int wid  = tid >> 5;
    const int lane = tid & 31;
    const int m0 = blockIdx.y * 128;
    const int n0 = blockIdx.x * 128;
    const int mbw = (wid & 3) * 32;
    const int nbw = (wid >> 2) * 64;
    const int lr = lane >> 2;
    const int lc = lane & 3;

    const int fr = tid >> 3, fc = tid & 7;

    const uint32_t* aSrc = Af + (size_t)(m0 + fr) * ldau + fc * 4;
    const uint32_t* bSrc = Bh + (size_t)(n0 + fr) * ldbu + fc * 4;
    const uint32_t aDst = sb + (fr * P2 + fc * 4) * 4;
    const uint32_t bDst = sb + (T2_U32 + fr * P2 + fc * 4) * 4;

    float acc[2][8][4] = {};
    const int nchunks = K >> 6;

    #define ISSUE2(ch) do {                                                         \
        const uint32_t so_ = ((ch) & 1) * (STAGE2_U32 * 4);                         \
        const int ku_ = (ch) << 5;                                                  \
        _Pragma("unroll")                                                           \
        for (int i_ = 0; i_ < 4; i_++) {                                            \
            cp16(aDst + so_ + i_ * 32 * P2 * 4,                                     \
                 aSrc + ku_ + (size_t)i_ * 32 * ldau);                              \
            cp16(bDst + so_ + i_ * 32 * P2 * 4,                                     \
                 bSrc + ku_ + (size_t)i_ * 32 * ldbu);                              \
        }                                                                           \
        cp_commit();                                                                \
    } while (0)

    ISSUE2(0);
    for (int ch = 0; ch < nchunks; ch++) {
        cp_wait<0>();
        __syncthreads();
        if (ch + 1 < nchunks) ISSUE2(ch + 1);

        const uint32_t stg = (ch & 1) * STAGE2_U32;
        const uint32_t* AFs = sm4 + stg;
        const uint32_t* BHs = sm4 + stg + T2_U32;

        #pragma unroll
        for (int ks = 0; ks < 4; ks++) {
            uint32_t ah[2][4];
            #pragma unroll
            for (int t = 0; t < 2; t++) {
                int ba = (mbw + t * 16 + lr) * P2 + ks * 8 + 2 * lc;
                uint2 h0 = *(const uint2*)(AFs + ba);
                uint2 h8 = *(const uint2*)(AFs + ba + 8 * P2);
                ah[t][0] = h0.x; ah[t][1] = h8.x; ah[t][2] = h0.y; ah[t][3] = h8.y;
            }
            #pragma unroll
            for (int u = 0; u < 8; u++) {
                int rb = (nbw + u * 8 + lr) * P2 + ks * 8 + 2 * lc;
                uint2 bh = *(const uint2*)(BHs + rb);
                #pragma unroll
                for (int t = 0; t < 2; t++)
                    mma_f16(acc[t][u], ah[t], bh.x, bh.y);
            }
        }
    }

    #pragma unroll
    for (int t = 0; t < 2; t++) {
        int row = m0 + mbw + t * 16 + lr;
        #pragma unroll
        for (int u = 0; u < 8; u++) {
            int col = n0 + nbw + u * 8 + lc * 2;
            *(float2*)(C + (size_t)row * ldc + col) = make_float2(acc[t][u][0], acc[t][u][1]);
            *(float2*)(C + (size_t)(row + 8) * ldc + col) = make_float2(acc[t][u][2], acc[t][u][3]);
        }
    }
}

// ---------------- banded softmax mix: 5-tap, contiguous-output register accumulation -----
__global__ void __launch_bounds__(256)
mix_kernel(const uint32_t* __restrict__ zf, uint32_t* __restrict__ z2f) {
    __shared__ float2 zs[64 + 2 * MIXW][32];
    __shared__ __align__(8) float2 wn2[2 * MIXW + 1];   // normalized, duplicated halves
    __shared__ float ws[2 * MIXW + 1];                  // raw weights (boundary path)
    const int s0 = blockIdx.x * 64;
    const int sl0 = blockIdx.y * 32;
    const int b  = blockIdx.z;
    const int tid = threadIdx.x;

    if (tid < 2 * MIXW + 1) {
        float w = g_e[tid < MIXW ? MIXW - tid : tid - MIXW];
        ws[tid] = w;
        float Z = g_e[0];
        #pragma unroll
        for (int d = 1; d <= MIXW; d++) Z += 2.f * g_e[d];
        float wn = w / Z;
        wn2[tid] = make_float2(wn, wn);
    }

    const int NROWS = 64 + 2 * MIXW;     // 68
    #pragma unroll
    for (int i = 0; i < 9; i++) {
        int idx = tid + i * 256;
        if (idx < NROWS * 32) {
            int r = idx >> 5, j = idx & 31;
            int gs = s0 - MIXW + r;
            uint32_t v = 0;
            if ((unsigned)gs < (unsigned)SS)
                v = zf[((size_t)b * SS + gs) * 128 + sl0 + j];
            __half2 h = *reinterpret_cast<__half2*>(&v);
            zs[r][j] = __half22float2(h);
        }
    }
    __syncthreads();

    const int pr = tid & 31;          // slot
    const int sw = tid >> 5;          // s-group: outputs s0 + sw*8 .. +7
    const bool interior = (s0 >= MIXW) && (s0 + 64 + MIXW <= SS);

    if (interior) {
        unsigned long long w2[2 * MIXW + 1];
        #pragma unroll
        for (int dd = 0; dd <= 2 * MIXW; dd++)
            w2[dd] = *(const unsigned long long*)&wn2[dd];

        unsigned long long acc[8] = {};
        #pragma unroll
        for (int rr = 0; rr < 8 + 2 * MIXW; rr++) {
            unsigned long long v = *(const unsigned long long*)&zs[sw * 8 + rr][pr];
            #pragma unroll
            for (int i = 0; i < 8; i++) {
                const int wi = i + 2 * MIXW - rr;
                if (wi >= 0 && wi <= 2 * MIXW)
                    asm("fma.rn.f32x2 %0, %1, %2, %0;" : "+l"(acc[i]) : "l"(v), "l"(w2[wi]));
            }
        }
        #pragma unroll
        for (int i = 0; i < 8; i++) {
            float a0 = __uint_as_float((uint32_t)acc[i]);
            float a1 = __uint_as_float((uint32_t)(acc[i] >> 32));
            z2f[((size_t)b * SS + s0 + sw * 8 + i) * 128 + sl0 + pr] = pack_f16x2(a0, a1);
        }
    } else {
        #pragma unroll
        for (int i = 0; i < 8; i++) {
            int sl = sw * 8 + i;
            int s = s0 + sl;
            float Z = 0.f, a0 = 0.f, a1 = 0.f;
            #pragma unroll
            for (int d = -MIXW; d <= MIXW; ++d) {
                int t = s - d;
                if ((unsigned)t < (unsigned)SS) {
                    float w = ws[d + MIXW];
                    Z += w;
                    float2 v = zs[sl + MIXW - d][pr];
                    a0 += w * v.x;
                    a1 += w * v.y;
                }
            }
            float inv = 1.f / Z;
            z2f[((size_t)b * SS + s) * 128 + sl0 + pr] = pack_f16x2(a0 * inv, a1 * inv);
        }
    }
}

// ---------------- launch ------------------------------------------------------------------
extern "C" void kernel_launch(void* const* d_in, const int* in_sizes, int n_in,
                              void* d_out, int out_size) {
    const float* x      = (const float*)d_in[0];
    const float* v_low  = (const float*)d_in[5];   // [242, 768]
    const float* v_high = (const float*)d_in[6];   // [256, 242]
    const float* o_low  = (const float*)d_in[7];   // [242, 256]
    const float* o_high = (const float*)d_in[8];   // [768, 242]
    float* out = (float*)d_out;                    // [4, 4096, 768]

    float* T1t = nullptr; cudaGetSymbolAddress((void**)&T1t, g_T1t);
    uint32_t* vlh = nullptr; cudaGetSymbolAddress((void**)&vlh, g_vlh);
    uint32_t* wch = nullptr; cudaGetSymbolAddress((void**)&wch, g_wch);
    uint32_t* zf  = nullptr; cudaGetSymbolAddress((void**)&zf,  g_zf);
    uint32_t* z2f = nullptr; cudaGetSymbolAddress((void**)&z2f, g_z2f);

    cudaFuncSetAttribute(mma_gemm_abt, cudaFuncAttributeMaxDynamicSharedMemorySize, SM_BYTES);
    cudaFuncSetAttribute(mma_gemm_fb,  cudaFuncAttributeMaxDynamicSharedMemorySize, SM2_BYTES);
    cudaFuncSetAttribute(wk1b, cudaFuncAttributeMaxDynamicSharedMemorySize, WSM_BYTES);
    cudaFuncSetAttribute(wk2,  cudaFuncAttributeMaxDynamicSharedMemorySize, WSM_BYTES);

    // one-time stream/event setup (resource creation only; no device allocation)
    static cudaStream_t s2 = nullptr;
    static cudaEvent_t ev_fork = nullptr, ev_join = nullptr;
    if (s2 == nullptr) {
        cudaStreamCreateWithFlags(&s2, cudaStreamNonBlocking);
        cudaEventCreateWithFlags(&ev_fork, cudaEventDisableTiming);
        cudaEventCreateWithFlags(&ev_join, cudaEventDisableTiming);
    }

    // fork: weight branch (T1t gemm -> WcT gemm) on side stream
    cudaEventRecord(ev_fork, 0);
    cudaStreamWaitEvent(s2, ev_fork, 0);
    wk1b<<<16, 256, WSM_BYTES, s2>>>(o_low, v_high, T1t);
    wk2 <<<48, 256, WSM_BYTES, s2>>>(o_high, T1t, wch);
    cudaEventRecord(ev_join, s2);

    // main branch: conv(v_low)+prep -> gemm1 -> mix
    wk1a<<<387, 256>>>(v_low, vlh);
    mma_gemm_abt<<<dim3(CP / 128, (BB * SS) / 128), 256, SM_BYTES>>>(
        x, HH, vlh, HH / 2, zf, HH);
    mix_kernel<<<dim3(SS / 64, 4, BB), 256>>>(zf, z2f);

    // join: gemm2 needs wch from the weight branch
    cudaStreamWaitEvent(0, ev_join, 0);
    mma_gemm_fb<<<dim3(HH / 128, (BB * SS) / 128), 256, SM2_BYTES>>>(
        z2f, CP / 2, wch, CP / 2, out, HH, CP);

    (void)in_sizes; (void)n_in; (void)out_size;
}